// round 1
// baseline (speedup 1.0000x reference)
#include <cuda_runtime.h>
#include <cstdint>

#define NP 100000
#define NA 100000
#define NF 50000
#define FIN 128
#define HID 64
#define OUTF 349

// ---------------- scratch (device globals; no runtime allocation) ----------------
// transformed source features (per edge type)
static __device__ __align__(256) float g_hs_wr[NA * HID];   // author @ wl1_wr
static __device__ __align__(256) float g_hs_rw[NP * HID];   // paper  @ wl1_rw
static __device__ __align__(256) float g_hs_ci[NP * HID];   // paper  @ wl1_ci
static __device__ __align__(256) float g_hs_ht[NP * HID];   // paper  @ wl1_ht
static __device__ __align__(256) float g_hs_rh[NF * HID];   // field  @ wl1_rh
// layer-1 aggregation buffers
static __device__ __align__(256) float g_ag_wr[NP * HID];
static __device__ __align__(256) float g_ag_rw[NA * HID];
static __device__ __align__(256) float g_ag_ci[NP * HID];
static __device__ __align__(256) float g_ag_ht[NF * HID];
static __device__ __align__(256) float g_ag_rh[NP * HID];
// self terms
static __device__ __align__(256) float g_selfP[NP * HID];
static __device__ __align__(256) float g_selfA[NA * HID];
static __device__ __align__(256) float g_selfF[NF * HID];
// layer-1 outputs
static __device__ __align__(256) float g_p1[NP * HID];
static __device__ __align__(256) float g_a1[NA * HID];
static __device__ __align__(256) float g_f1[NF * HID];
// layer-2 aggregation buffers
static __device__ __align__(256) float g_ag2_wr[NP * HID];
static __device__ __align__(256) float g_ag2_ci[NP * HID];
static __device__ __align__(256) float g_ag2_rh[NP * HID];
// degree counts
static __device__ __align__(256) int g_cnt_wr[NP];
static __device__ __align__(256) int g_cnt_rw[NA];
static __device__ __align__(256) int g_cnt_ci[NP];
static __device__ __align__(256) int g_cnt_ht[NF];
static __device__ __align__(256) int g_cnt_rh[NP];
// summed weights / biases
static __device__ __align__(256) float g_wsumP[FIN * HID];
static __device__ __align__(256) float g_w2sum[HID * OUTF];
static __device__ __align__(256) float g_bsum1[HID];
static __device__ __align__(256) float g_bsum2[OUTF];

// ---------------- weight/bias prep ----------------
__global__ void prep_weights(const float* __restrict__ wr1a, const float* __restrict__ wr1b,
                             const float* __restrict__ wr1c,
                             const float* __restrict__ wr2a, const float* __restrict__ wr2b,
                             const float* __restrict__ wr2c,
                             const float* __restrict__ b1a, const float* __restrict__ b1b,
                             const float* __restrict__ b1c,
                             const float* __restrict__ b2a, const float* __restrict__ b2b,
                             const float* __restrict__ b2c) {
    int i = blockIdx.x * blockDim.x + threadIdx.x;
    if (i < FIN * HID) g_wsumP[i] = wr1a[i] + wr1b[i] + wr1c[i];
    if (i < HID * OUTF) g_w2sum[i] = wr2a[i] + wr2b[i] + wr2c[i];
    if (i < HID) g_bsum1[i] = b1a[i] + b1b[i] + b1c[i];
    if (i < OUTF) g_bsum2[i] = b2a[i] + b2b[i] + b2c[i];
}

// ---------------- GEMM: C[M,64] = A[M,128] @ B[128,64] ----------------
// 64x64 tile, 256 threads, 4x4 per-thread micro-tile.
__global__ void gemm_f128(const float* __restrict__ A, const float* __restrict__ B,
                          float* __restrict__ C, int M) {
    __shared__ float As[64 * 65];
    __shared__ float Bs[64 * 64];
    const int t = threadIdx.x;
    const int ty = t >> 4, tx = t & 15;
    const int rowBase = blockIdx.x * 64;

    float acc[4][4] = {};

    for (int kb = 0; kb < 2; ++kb) {
#pragma unroll
        for (int j = 0; j < 4; ++j) {
            int v = t + j * 256;          // float4 slot 0..1023
            int r = v >> 4, c4 = v & 15;
            int gr = rowBase + r;
            if (gr >= M) gr = M - 1;
            float4 av = *(const float4*)(A + (size_t)gr * FIN + kb * 64 + c4 * 4);
            As[r * 65 + c4 * 4 + 0] = av.x;
            As[r * 65 + c4 * 4 + 1] = av.y;
            As[r * 65 + c4 * 4 + 2] = av.z;
            As[r * 65 + c4 * 4 + 3] = av.w;
            float4 bv = *(const float4*)(B + (size_t)(kb * 64 + r) * 64 + c4 * 4);
            *(float4*)&Bs[r * 64 + c4 * 4] = bv;
        }
        __syncthreads();
#pragma unroll 8
        for (int kk = 0; kk < 64; ++kk) {
            float4 b = *(const float4*)&Bs[kk * 64 + tx * 4];
            float a0 = As[(ty * 4 + 0) * 65 + kk];
            float a1 = As[(ty * 4 + 1) * 65 + kk];
            float a2 = As[(ty * 4 + 2) * 65 + kk];
            float a3 = As[(ty * 4 + 3) * 65 + kk];
            acc[0][0] += a0 * b.x; acc[0][1] += a0 * b.y; acc[0][2] += a0 * b.z; acc[0][3] += a0 * b.w;
            acc[1][0] += a1 * b.x; acc[1][1] += a1 * b.y; acc[1][2] += a1 * b.z; acc[1][3] += a1 * b.w;
            acc[2][0] += a2 * b.x; acc[2][1] += a2 * b.y; acc[2][2] += a2 * b.z; acc[2][3] += a2 * b.w;
            acc[3][0] += a3 * b.x; acc[3][1] += a3 * b.y; acc[3][2] += a3 * b.z; acc[3][3] += a3 * b.w;
        }
        __syncthreads();
    }

#pragma unroll
    for (int r = 0; r < 4; ++r) {
        int gr = rowBase + ty * 4 + r;
        if (gr < M) {
            float4 o = make_float4(acc[r][0], acc[r][1], acc[r][2], acc[r][3]);
            *(float4*)(C + (size_t)gr * 64 + tx * 4) = o;
        }
    }
}

// ---------------- edge scatter: 16 threads per edge, vector red ----------------
__global__ void scatter16(const float* __restrict__ feat, const int* __restrict__ ei, int E,
                          float* __restrict__ agg, int* __restrict__ cnt) {
    int gid = blockIdx.x * blockDim.x + threadIdx.x;
    int e = gid >> 4;
    int lane = gid & 15;
    if (e >= E) return;
    int s = __ldg(ei + e);
    int d = __ldg(ei + E + e);
    float4 v = *(const float4*)(feat + (size_t)s * 64 + lane * 4);
    float* p = agg + (size_t)d * 64 + lane * 4;
    asm volatile("red.global.add.v4.f32 [%0], {%1,%2,%3,%4};"
                 :: "l"(p), "f"(v.x), "f"(v.y), "f"(v.z), "f"(v.w) : "memory");
    if (cnt != nullptr && lane == 0) atomicAdd(cnt + d, 1);
}

// ---------------- layer-1 finalize ----------------
__global__ void finalize_p1_k() {
    int t = blockIdx.x * blockDim.x + threadIdx.x;
    if (t >= NP * 16) return;
    int node = t >> 4, l = t & 15;
    float iw = 1.f / fmaxf((float)g_cnt_wr[node], 1.f);
    float ic = 1.f / fmaxf((float)g_cnt_ci[node], 1.f);
    float ir = 1.f / fmaxf((float)g_cnt_rh[node], 1.f);
    float4 s = ((const float4*)g_selfP)[t];
    float4 aw = ((const float4*)g_ag_wr)[t];
    float4 ac = ((const float4*)g_ag_ci)[t];
    float4 ar = ((const float4*)g_ag_rh)[t];
    float4 b = ((const float4*)g_bsum1)[l];
    float4 o;
    o.x = fmaxf(s.x + b.x + aw.x * iw + ac.x * ic + ar.x * ir, 0.f);
    o.y = fmaxf(s.y + b.y + aw.y * iw + ac.y * ic + ar.y * ir, 0.f);
    o.z = fmaxf(s.z + b.z + aw.z * iw + ac.z * ic + ar.z * ir, 0.f);
    o.w = fmaxf(s.w + b.w + aw.w * iw + ac.w * ic + ar.w * ir, 0.f);
    ((float4*)g_p1)[t] = o;
}

__global__ void finalize_af_k(const float* __restrict__ selfX, const float* __restrict__ ag,
                              const int* __restrict__ cnt, const float* __restrict__ bias,
                              float* __restrict__ out, int n) {
    int t = blockIdx.x * blockDim.x + threadIdx.x;
    if (t >= n * 16) return;
    int node = t >> 4, l = t & 15;
    float inv = 1.f / fmaxf((float)cnt[node], 1.f);
    float4 s = ((const float4*)selfX)[t];
    float4 a = ((const float4*)ag)[t];
    float4 b = ((const float4*)bias)[l];
    float4 o;
    o.x = fmaxf(s.x + b.x + a.x * inv, 0.f);
    o.y = fmaxf(s.y + b.y + a.y * inv, 0.f);
    o.z = fmaxf(s.z + b.z + a.z * inv, 0.f);
    o.w = fmaxf(s.w + b.w + a.w * inv, 0.f);
    ((float4*)out)[t] = o;
}

// ---------------- normalize layer-2 agg (mean) ----------------
__global__ void normalize_k(float* __restrict__ a, const int* __restrict__ cnt, int n) {
    int t = blockIdx.x * blockDim.x + threadIdx.x;
    if (t >= n * 16) return;
    int node = t >> 4;
    float inv = 1.f / fmaxf((float)cnt[node], 1.f);
    float4 v = ((const float4*)a)[t];
    v.x *= inv; v.y *= inv; v.z *= inv; v.w *= inv;
    ((float4*)a)[t] = v;
}

// ---------------- output GEMM: C[M,349] = sum_b A_b[M,64] @ B_b[64,349] + bsum2 ----------------
__global__ void gemm_out(const float* __restrict__ A0, const float* __restrict__ A1,
                         const float* __restrict__ A2, const float* __restrict__ A3,
                         const float* __restrict__ B0, const float* __restrict__ B1,
                         const float* __restrict__ B2, const float* __restrict__ B3,
                         float* __restrict__ C, int M) {
    __shared__ float As[64 * 65];
    __shared__ float Bs[64 * 64];
    const int t = threadIdx.x;
    const int ty = t >> 4, tx = t & 15;
    const int rowBase = blockIdx.x * 64;
    const int colBase = blockIdx.y * 64;

    const float* Aps[4] = {A0, A1, A2, A3};
    const float* Bps[4] = {B0, B1, B2, B3};

    float acc[4][4] = {};

    for (int kb = 0; kb < 4; ++kb) {
        const float* Ap = Aps[kb];
        const float* Bp = Bps[kb];
#pragma unroll
        for (int j = 0; j < 4; ++j) {
            int v = t + j * 256;
            int r = v >> 4, c4 = v & 15;
            int gr = rowBase + r;
            if (gr >= M) gr = M - 1;
            float4 av = *(const float4*)(Ap + (size_t)gr * 64 + c4 * 4);
            As[r * 65 + c4 * 4 + 0] = av.x;
            As[r * 65 + c4 * 4 + 1] = av.y;
            As[r * 65 + c4 * 4 + 2] = av.z;
            As[r * 65 + c4 * 4 + 3] = av.w;
        }
#pragma unroll
        for (int j = 0; j < 16; ++j) {
            int idx = t + j * 256;          // 0..4095
            int r = idx >> 6, c = idx & 63; // k-row, n-col within tile
            int col = colBase + c;
            Bs[r * 64 + c] = (col < OUTF) ? Bp[(size_t)r * OUTF + col] : 0.f;
        }
        __syncthreads();
#pragma unroll 8
        for (int kk = 0; kk < 64; ++kk) {
            float4 b = *(const float4*)&Bs[kk * 64 + tx * 4];
            float a0 = As[(ty * 4 + 0) * 65 + kk];
            float a1 = As[(ty * 4 + 1) * 65 + kk];
            float a2 = As[(ty * 4 + 2) * 65 + kk];
            float a3 = As[(ty * 4 + 3) * 65 + kk];
            acc[0][0] += a0 * b.x; acc[0][1] += a0 * b.y; acc[0][2] += a0 * b.z; acc[0][3] += a0 * b.w;
            acc[1][0] += a1 * b.x; acc[1][1] += a1 * b.y; acc[1][2] += a1 * b.z; acc[1][3] += a1 * b.w;
            acc[2][0] += a2 * b.x; acc[2][1] += a2 * b.y; acc[2][2] += a2 * b.z; acc[2][3] += a2 * b.w;
            acc[3][0] += a3 * b.x; acc[3][1] += a3 * b.y; acc[3][2] += a3 * b.z; acc[3][3] += a3 * b.w;
        }
        __syncthreads();
    }

#pragma unroll
    for (int r = 0; r < 4; ++r) {
        int gr = rowBase + ty * 4 + r;
        if (gr >= M) continue;
#pragma unroll
        for (int c = 0; c < 4; ++c) {
            int col = colBase + tx * 4 + c;
            if (col < OUTF)
                C[(size_t)gr * OUTF + col] = acc[r][c] + g_bsum2[col];
        }
    }
}

// ---------------- host launcher ----------------
extern "C" void kernel_launch(void* const* d_in, const int* in_sizes, int n_in,
                              void* d_out, int out_size) {
    const float* x_paper  = (const float*)d_in[0];
    const float* x_author = (const float*)d_in[1];
    const float* x_field  = (const float*)d_in[2];
    const int* ei_wr = (const int*)d_in[3];
    const int* ei_rw = (const int*)d_in[4];
    const int* ei_ci = (const int*)d_in[5];
    const int* ei_ht = (const int*)d_in[6];
    const int* ei_rh = (const int*)d_in[7];
    const int E_wr = in_sizes[3] / 2;
    const int E_rw = in_sizes[4] / 2;
    const int E_ci = in_sizes[5] / 2;
    const int E_ht = in_sizes[6] / 2;
    const int E_rh = in_sizes[7] / 2;

    const float* wl1_wr = (const float*)d_in[8];
    const float* wr1_wr = (const float*)d_in[9];
    const float* wl1_rw = (const float*)d_in[11];
    const float* wr1_rw = (const float*)d_in[12];
    const float* b1_rw  = (const float*)d_in[13];
    const float* wl1_ci = (const float*)d_in[14];
    const float* wr1_ci = (const float*)d_in[15];
    const float* wl1_ht = (const float*)d_in[17];
    const float* wr1_ht = (const float*)d_in[18];
    const float* b1_ht  = (const float*)d_in[19];
    const float* wl1_rh = (const float*)d_in[20];
    const float* wr1_rh = (const float*)d_in[21];

    const float* wl2_wr = (const float*)d_in[23];
    const float* wr2_wr = (const float*)d_in[24];
    const float* wl2_ci = (const float*)d_in[26];
    const float* wr2_ci = (const float*)d_in[27];
    const float* wl2_rh = (const float*)d_in[29];
    const float* wr2_rh = (const float*)d_in[30];

    const float* b1_wr = (const float*)d_in[10];
    const float* b1_ci = (const float*)d_in[16];
    const float* b1_rh = (const float*)d_in[22];
    const float* b2_wr = (const float*)d_in[25];
    const float* b2_ci = (const float*)d_in[28];
    const float* b2_rh = (const float*)d_in[31];

    float* out = (float*)d_out;

    // resolve scratch addresses
    void *p_hs_wr, *p_hs_rw, *p_hs_ci, *p_hs_ht, *p_hs_rh;
    void *p_ag_wr, *p_ag_rw, *p_ag_ci, *p_ag_ht, *p_ag_rh;
    void *p_selfP, *p_selfA, *p_selfF, *p_p1, *p_a1, *p_f1;
    void *p_ag2_wr, *p_ag2_ci, *p_ag2_rh;
    void *p_cnt_wr, *p_cnt_rw, *p_cnt_ci, *p_cnt_ht, *p_cnt_rh;
    void *p_wsumP, *p_w2sum;
    cudaGetSymbolAddress(&p_hs_wr, g_hs_wr);
    cudaGetSymbolAddress(&p_hs_rw, g_hs_rw);
    cudaGetSymbolAddress(&p_hs_ci, g_hs_ci);
    cudaGetSymbolAddress(&p_hs_ht, g_hs_ht);
    cudaGetSymbolAddress(&p_hs_rh, g_hs_rh);
    cudaGetSymbolAddress(&p_ag_wr, g_ag_wr);
    cudaGetSymbolAddress(&p_ag_rw, g_ag_rw);
    cudaGetSymbolAddress(&p_ag_ci, g_ag_ci);
    cudaGetSymbolAddress(&p_ag_ht, g_ag_ht);
    cudaGetSymbolAddress(&p_ag_rh, g_ag_rh);
    cudaGetSymbolAddress(&p_selfP, g_selfP);
    cudaGetSymbolAddress(&p_selfA, g_selfA);
    cudaGetSymbolAddress(&p_selfF, g_selfF);
    cudaGetSymbolAddress(&p_p1, g_p1);
    cudaGetSymbolAddress(&p_a1, g_a1);
    cudaGetSymbolAddress(&p_f1, g_f1);
    cudaGetSymbolAddress(&p_ag2_wr, g_ag2_wr);
    cudaGetSymbolAddress(&p_ag2_ci, g_ag2_ci);
    cudaGetSymbolAddress(&p_ag2_rh, g_ag2_rh);
    cudaGetSymbolAddress(&p_cnt_wr, g_cnt_wr);
    cudaGetSymbolAddress(&p_cnt_rw, g_cnt_rw);
    cudaGetSymbolAddress(&p_cnt_ci, g_cnt_ci);
    cudaGetSymbolAddress(&p_cnt_ht, g_cnt_ht);
    cudaGetSymbolAddress(&p_cnt_rh, g_cnt_rh);
    cudaGetSymbolAddress(&p_wsumP, g_wsumP);
    cudaGetSymbolAddress(&p_w2sum, g_w2sum);

    // zero accumulation buffers + counts
    cudaMemsetAsync(p_ag_wr, 0, sizeof(float) * NP * HID, 0);
    cudaMemsetAsync(p_ag_rw, 0, sizeof(float) * NA * HID, 0);
    cudaMemsetAsync(p_ag_ci, 0, sizeof(float) * NP * HID, 0);
    cudaMemsetAsync(p_ag_ht, 0, sizeof(float) * NF * HID, 0);
    cudaMemsetAsync(p_ag_rh, 0, sizeof(float) * NP * HID, 0);
    cudaMemsetAsync(p_ag2_wr, 0, sizeof(float) * NP * HID, 0);
    cudaMemsetAsync(p_ag2_ci, 0, sizeof(float) * NP * HID, 0);
    cudaMemsetAsync(p_ag2_rh, 0, sizeof(float) * NP * HID, 0);
    cudaMemsetAsync(p_cnt_wr, 0, sizeof(int) * NP, 0);
    cudaMemsetAsync(p_cnt_rw, 0, sizeof(int) * NA, 0);
    cudaMemsetAsync(p_cnt_ci, 0, sizeof(int) * NP, 0);
    cudaMemsetAsync(p_cnt_ht, 0, sizeof(int) * NF, 0);
    cudaMemsetAsync(p_cnt_rh, 0, sizeof(int) * NP, 0);

    // summed weights / biases
    prep_weights<<<(HID * OUTF + 255) / 256, 256>>>(
        wr1_wr, wr1_ci, wr1_rh, wr2_wr, wr2_ci, wr2_rh,
        b1_wr, b1_ci, b1_rh, b2_wr, b2_ci, b2_rh);

    // layer-1 transforms (transform before aggregate: mean is linear)
    const int gP = (NP + 63) / 64, gA = (NA + 63) / 64, gF = (NF + 63) / 64;
    gemm_f128<<<gA, 256>>>(x_author, wl1_wr, (float*)p_hs_wr, NA);
    gemm_f128<<<gP, 256>>>(x_paper,  wl1_rw, (float*)p_hs_rw, NP);
    gemm_f128<<<gP, 256>>>(x_paper,  wl1_ci, (float*)p_hs_ci, NP);
    gemm_f128<<<gP, 256>>>(x_paper,  wl1_ht, (float*)p_hs_ht, NP);
    gemm_f128<<<gF, 256>>>(x_field,  wl1_rh, (float*)p_hs_rh, NF);
    gemm_f128<<<gP, 256>>>(x_paper,  (const float*)p_wsumP, (float*)p_selfP, NP);
    gemm_f128<<<gA, 256>>>(x_author, wr1_rw, (float*)p_selfA, NA);
    gemm_f128<<<gF, 256>>>(x_field,  wr1_ht, (float*)p_selfF, NF);

    // layer-1 scatter (mean numerators + degree counts)
    auto sgrid = [](int E) { return (E * 16 + 255) / 256; };
    scatter16<<<sgrid(E_wr), 256>>>((const float*)p_hs_wr, ei_wr, E_wr, (float*)p_ag_wr, (int*)p_cnt_wr);
    scatter16<<<sgrid(E_rw), 256>>>((const float*)p_hs_rw, ei_rw, E_rw, (float*)p_ag_rw, (int*)p_cnt_rw);
    scatter16<<<sgrid(E_ci), 256>>>((const float*)p_hs_ci, ei_ci, E_ci, (float*)p_ag_ci, (int*)p_cnt_ci);
    scatter16<<<sgrid(E_ht), 256>>>((const float*)p_hs_ht, ei_ht, E_ht, (float*)p_ag_ht, (int*)p_cnt_ht);
    scatter16<<<sgrid(E_rh), 256>>>((const float*)p_hs_rh, ei_rh, E_rh, (float*)p_ag_rh, (int*)p_cnt_rh);

    // layer-1 finalize (mean + self + bias + relu)
    finalize_p1_k<<<(NP * 16 + 255) / 256, 256>>>();
    finalize_af_k<<<(NA * 16 + 255) / 256, 256>>>((const float*)p_selfA, (const float*)p_ag_rw,
                                                  (const int*)p_cnt_rw, b1_rw, (float*)p_a1, NA);
    finalize_af_k<<<(NF * 16 + 255) / 256, 256>>>((const float*)p_selfF, (const float*)p_ag_ht,
                                                  (const int*)p_cnt_ht, b1_ht, (float*)p_f1, NF);

    // layer-2 scatter (same edge sets as layer-1 wr/ci/rh -> counts reused)
    scatter16<<<sgrid(E_wr), 256>>>((const float*)p_a1, ei_wr, E_wr, (float*)p_ag2_wr, nullptr);
    scatter16<<<sgrid(E_ci), 256>>>((const float*)p_p1, ei_ci, E_ci, (float*)p_ag2_ci, nullptr);
    scatter16<<<sgrid(E_rh), 256>>>((const float*)p_f1, ei_rh, E_rh, (float*)p_ag2_rh, nullptr);

    // normalize layer-2 means
    normalize_k<<<(NP * 16 + 255) / 256, 256>>>((float*)p_ag2_wr, (const int*)p_cnt_wr, NP);
    normalize_k<<<(NP * 16 + 255) / 256, 256>>>((float*)p_ag2_ci, (const int*)p_cnt_ci, NP);
    normalize_k<<<(NP * 16 + 255) / 256, 256>>>((float*)p_ag2_rh, (const int*)p_cnt_rh, NP);

    // output GEMM: 4 K-chunks (3 aggregated + self) into [100000, 349]
    dim3 g2(gP, (OUTF + 63) / 64);
    gemm_out<<<g2, 256>>>((const float*)p_ag2_wr, (const float*)p_ag2_ci,
                          (const float*)p_ag2_rh, (const float*)p_p1,
                          wl2_wr, wl2_ci, wl2_rh, (const float*)p_w2sum,
                          out, NP);
}

// round 2
// speedup vs baseline: 1.1811x; 1.1811x over previous
#include <cuda_runtime.h>
#include <cstdint>

#define NP 100000
#define NA 100000
#define NF 50000
#define FIN 128
#define HID 64
#define OUTF 349

#define E_WR 1000000
#define E_RW 1000000
#define E_CI 2000000
#define E_HT 1000000
#define E_RH 1000000

// ---------------- scratch (device globals; no runtime allocation) ----------------
// transformed source features (per edge type)
static __device__ __align__(256) float g_hs_wr[NA * HID];   // author @ wl1_wr
static __device__ __align__(256) float g_hs_rw[NP * HID];   // paper  @ wl1_rw
static __device__ __align__(256) float g_hs_ci[NP * HID];   // paper  @ wl1_ci
static __device__ __align__(256) float g_hs_ht[NP * HID];   // paper  @ wl1_ht
static __device__ __align__(256) float g_hs_rh[NF * HID];   // field  @ wl1_rh
// layer-1 mean buffers (pull output)
static __device__ __align__(256) float g_m_wr[NP * HID];
static __device__ __align__(256) float g_m_rw[NA * HID];
static __device__ __align__(256) float g_m_ci[NP * HID];
static __device__ __align__(256) float g_m_ht[NF * HID];
static __device__ __align__(256) float g_m_rh[NP * HID];
// self terms
static __device__ __align__(256) float g_selfP[NP * HID];
static __device__ __align__(256) float g_selfA[NA * HID];
static __device__ __align__(256) float g_selfF[NF * HID];
// layer-1 outputs
static __device__ __align__(256) float g_p1[NP * HID];
static __device__ __align__(256) float g_a1[NA * HID];
static __device__ __align__(256) float g_f1[NF * HID];
// layer-2 mean buffers
static __device__ __align__(256) float g_m2_wr[NP * HID];
static __device__ __align__(256) float g_m2_ci[NP * HID];
static __device__ __align__(256) float g_m2_rh[NP * HID];
// CSR per edge type
static __device__ int g_cnt_wr[NP], g_cnt_rw[NA], g_cnt_ci[NP], g_cnt_ht[NF], g_cnt_rh[NP];
static __device__ int g_rp_wr[NP + 1], g_rp_rw[NA + 1], g_rp_ci[NP + 1], g_rp_ht[NF + 1], g_rp_rh[NP + 1];
static __device__ int g_fl_wr[NP], g_fl_rw[NA], g_fl_ci[NP], g_fl_ht[NF], g_fl_rh[NP];
static __device__ int g_csr_wr[E_WR], g_csr_rw[E_RW], g_csr_ci[E_CI], g_csr_ht[E_HT], g_csr_rh[E_RH];
// scan temporaries (max blocks = ceil(100000/1024) = 98)
static __device__ int g_bsum[5][128];
// summed weights / biases
static __device__ __align__(256) float g_wsumP[FIN * HID];
static __device__ __align__(256) float g_w2sum[HID * OUTF];
static __device__ __align__(256) float g_bsum1[HID];
static __device__ __align__(256) float g_bsum2[OUTF];

// ---------------- weight/bias prep ----------------
__global__ void prep_weights(const float* __restrict__ wr1a, const float* __restrict__ wr1b,
                             const float* __restrict__ wr1c,
                             const float* __restrict__ wr2a, const float* __restrict__ wr2b,
                             const float* __restrict__ wr2c,
                             const float* __restrict__ b1a, const float* __restrict__ b1b,
                             const float* __restrict__ b1c,
                             const float* __restrict__ b2a, const float* __restrict__ b2b,
                             const float* __restrict__ b2c) {
    int i = blockIdx.x * blockDim.x + threadIdx.x;
    if (i < FIN * HID) g_wsumP[i] = wr1a[i] + wr1b[i] + wr1c[i];
    if (i < HID * OUTF) g_w2sum[i] = wr2a[i] + wr2b[i] + wr2c[i];
    if (i < HID) g_bsum1[i] = b1a[i] + b1b[i] + b1c[i];
    if (i < OUTF) g_bsum2[i] = b2a[i] + b2b[i] + b2c[i];
}

// ---------------- CSR build ----------------
__global__ void k_count(const int* __restrict__ ei, int E, int* __restrict__ cnt) {
    int e = blockIdx.x * blockDim.x + threadIdx.x;
    if (e >= E) return;
    atomicAdd(cnt + __ldg(ei + E + e), 1);
}

// block partial sums over 1024-element chunks
__global__ void k_blocksum(const int* __restrict__ c, int n, int* __restrict__ bsum) {
    __shared__ int s[256];
    int base = blockIdx.x * 1024;
    int t = threadIdx.x;
    int v = 0;
#pragma unroll
    for (int j = 0; j < 4; ++j) {
        int i = base + t * 4 + j;
        if (i < n) v += c[i];
    }
    s[t] = v;
    __syncthreads();
    for (int o = 128; o > 0; o >>= 1) {
        if (t < o) s[t] += s[t + o];
        __syncthreads();
    }
    if (t == 0) bsum[blockIdx.x] = s[0];
}

// single-block exclusive scan of block sums (nb <= 128); writes total to *rp_last
__global__ void k_scan_bsums(int* __restrict__ bsum, int nb, int* __restrict__ rp_last) {
    __shared__ int s[256];
    int t = threadIdx.x;
    int v = (t < nb) ? bsum[t] : 0;
    s[t] = v;
    __syncthreads();
    for (int o = 1; o < 256; o <<= 1) {
        int x = (t >= o) ? s[t - o] : 0;
        __syncthreads();
        s[t] += x;
        __syncthreads();
    }
    if (t < nb) bsum[t] = s[t] - v;   // exclusive prefix
    if (t == 0) *rp_last = s[255];    // grand total
}

// per-chunk exclusive scan + add block offset -> rowptr & fill
__global__ void k_scan_write(const int* __restrict__ c, int n, const int* __restrict__ bsum_ex,
                             int* __restrict__ rowptr, int* __restrict__ fill) {
    __shared__ int s[256];
    int base = blockIdx.x * 1024;
    int t = threadIdx.x;
    int loc[4];
    int v = 0;
#pragma unroll
    for (int j = 0; j < 4; ++j) {
        int i = base + t * 4 + j;
        loc[j] = v;
        v += (i < n) ? c[i] : 0;
    }
    s[t] = v;
    __syncthreads();
    int inc = v;
    for (int o = 1; o < 256; o <<= 1) {
        int x = (t >= o) ? s[t - o] : 0;
        __syncthreads();
        s[t] += x;
        __syncthreads();
    }
    inc = s[t];
    int ex = inc - v;
    int off = bsum_ex[blockIdx.x] + ex;
#pragma unroll
    for (int j = 0; j < 4; ++j) {
        int i = base + t * 4 + j;
        if (i < n) {
            int r = off + loc[j];
            rowptr[i] = r;
            fill[i] = r;
        }
    }
}

__global__ void k_fill(const int* __restrict__ ei, int E, int* __restrict__ fill,
                       int* __restrict__ csr) {
    int e = blockIdx.x * blockDim.x + threadIdx.x;
    if (e >= E) return;
    int s = __ldg(ei + e);
    int d = __ldg(ei + E + e);
    int pos = atomicAdd(fill + d, 1);
    csr[pos] = s;
}

// ---------------- pull aggregation (mean fused), 16 threads per dst ----------------
__global__ void k_pull(const float* __restrict__ feat, const int* __restrict__ rowptr,
                       const int* __restrict__ csr, float* __restrict__ out, int n) {
    int gid = blockIdx.x * blockDim.x + threadIdx.x;
    int g = gid >> 4, lane = gid & 15;
    if (g >= n) return;
    int beg = __ldg(rowptr + g), end = __ldg(rowptr + g + 1);
    float4 acc = make_float4(0.f, 0.f, 0.f, 0.f);
    int j = beg;
    for (; j + 1 < end; j += 2) {
        int s0 = __ldg(csr + j);
        int s1 = __ldg(csr + j + 1);
        float4 v0 = *(const float4*)(feat + (size_t)s0 * HID + lane * 4);
        float4 v1 = *(const float4*)(feat + (size_t)s1 * HID + lane * 4);
        acc.x += v0.x + v1.x;
        acc.y += v0.y + v1.y;
        acc.z += v0.z + v1.z;
        acc.w += v0.w + v1.w;
    }
    if (j < end) {
        int s0 = __ldg(csr + j);
        float4 v0 = *(const float4*)(feat + (size_t)s0 * HID + lane * 4);
        acc.x += v0.x; acc.y += v0.y; acc.z += v0.z; acc.w += v0.w;
    }
    float inv = 1.f / fmaxf((float)(end - beg), 1.f);
    acc.x *= inv; acc.y *= inv; acc.z *= inv; acc.w *= inv;
    *(float4*)(out + (size_t)g * HID + lane * 4) = acc;
}

// ---------------- GEMM: C[M,64] = A[M,128] @ B[128,64], batched over blockIdx.y ----------------
struct GemmBatch {
    const float* B[4];
    float* C[4];
};

__global__ void gemm_f128_multi(const float* __restrict__ A, GemmBatch p, int M) {
    __shared__ float As[64 * 65];
    __shared__ float Bs[64 * 64];
    const float* __restrict__ Bp = p.B[blockIdx.y];
    float* __restrict__ Cp = p.C[blockIdx.y];
    const int t = threadIdx.x;
    const int ty = t >> 4, tx = t & 15;
    const int rowBase = blockIdx.x * 64;

    float acc[4][4] = {};

    for (int kb = 0; kb < 2; ++kb) {
#pragma unroll
        for (int j = 0; j < 4; ++j) {
            int v = t + j * 256;
            int r = v >> 4, c4 = v & 15;
            int gr = rowBase + r;
            if (gr >= M) gr = M - 1;
            float4 av = *(const float4*)(A + (size_t)gr * FIN + kb * 64 + c4 * 4);
            As[r * 65 + c4 * 4 + 0] = av.x;
            As[r * 65 + c4 * 4 + 1] = av.y;
            As[r * 65 + c4 * 4 + 2] = av.z;
            As[r * 65 + c4 * 4 + 3] = av.w;
            float4 bv = *(const float4*)(Bp + (size_t)(kb * 64 + r) * 64 + c4 * 4);
            *(float4*)&Bs[r * 64 + c4 * 4] = bv;
        }
        __syncthreads();
#pragma unroll 8
        for (int kk = 0; kk < 64; ++kk) {
            float4 b = *(const float4*)&Bs[kk * 64 + tx * 4];
            float a0 = As[(ty * 4 + 0) * 65 + kk];
            float a1 = As[(ty * 4 + 1) * 65 + kk];
            float a2 = As[(ty * 4 + 2) * 65 + kk];
            float a3 = As[(ty * 4 + 3) * 65 + kk];
            acc[0][0] += a0 * b.x; acc[0][1] += a0 * b.y; acc[0][2] += a0 * b.z; acc[0][3] += a0 * b.w;
            acc[1][0] += a1 * b.x; acc[1][1] += a1 * b.y; acc[1][2] += a1 * b.z; acc[1][3] += a1 * b.w;
            acc[2][0] += a2 * b.x; acc[2][1] += a2 * b.y; acc[2][2] += a2 * b.z; acc[2][3] += a2 * b.w;
            acc[3][0] += a3 * b.x; acc[3][1] += a3 * b.y; acc[3][2] += a3 * b.z; acc[3][3] += a3 * b.w;
        }
        __syncthreads();
    }

#pragma unroll
    for (int r = 0; r < 4; ++r) {
        int gr = rowBase + ty * 4 + r;
        if (gr < M) {
            float4 o = make_float4(acc[r][0], acc[r][1], acc[r][2], acc[r][3]);
            *(float4*)(Cp + (size_t)gr * 64 + tx * 4) = o;
        }
    }
}

// ---------------- layer-1 finalize (means already computed) ----------------
__global__ void finalize_p1_k() {
    int t = blockIdx.x * blockDim.x + threadIdx.x;
    if (t >= NP * 16) return;
    int l = t & 15;
    float4 s = ((const float4*)g_selfP)[t];
    float4 aw = ((const float4*)g_m_wr)[t];
    float4 ac = ((const float4*)g_m_ci)[t];
    float4 ar = ((const float4*)g_m_rh)[t];
    float4 b = ((const float4*)g_bsum1)[l];
    float4 o;
    o.x = fmaxf(s.x + b.x + aw.x + ac.x + ar.x, 0.f);
    o.y = fmaxf(s.y + b.y + aw.y + ac.y + ar.y, 0.f);
    o.z = fmaxf(s.z + b.z + aw.z + ac.z + ar.z, 0.f);
    o.w = fmaxf(s.w + b.w + aw.w + ac.w + ar.w, 0.f);
    ((float4*)g_p1)[t] = o;
}

__global__ void finalize_af_k(const float* __restrict__ selfX, const float* __restrict__ mean,
                              const float* __restrict__ bias, float* __restrict__ out, int n) {
    int t = blockIdx.x * blockDim.x + threadIdx.x;
    if (t >= n * 16) return;
    int l = t & 15;
    float4 s = ((const float4*)selfX)[t];
    float4 a = ((const float4*)mean)[t];
    float4 b = ((const float4*)bias)[l];
    float4 o;
    o.x = fmaxf(s.x + b.x + a.x, 0.f);
    o.y = fmaxf(s.y + b.y + a.y, 0.f);
    o.z = fmaxf(s.z + b.z + a.z, 0.f);
    o.w = fmaxf(s.w + b.w + a.w, 0.f);
    ((float4*)out)[t] = o;
}

// ---------------- output GEMM: C[M,349] = sum_b A_b[M,64] @ B_b[64,349] + bsum2 ----------------
__global__ void gemm_out(const float* __restrict__ A0, const float* __restrict__ A1,
                         const float* __restrict__ A2, const float* __restrict__ A3,
                         const float* __restrict__ B0, const float* __restrict__ B1,
                         const float* __restrict__ B2, const float* __restrict__ B3,
                         float* __restrict__ C, int M) {
    __shared__ float As[64 * 65];
    __shared__ float Bs[64 * 64];
    const int t = threadIdx.x;
    const int ty = t >> 4, tx = t & 15;
    const int rowBase = blockIdx.x * 64;
    const int colBase = blockIdx.y * 64;

    const float* Aps[4] = {A0, A1, A2, A3};
    const float* Bps[4] = {B0, B1, B2, B3};

    float acc[4][4] = {};

    for (int kb = 0; kb < 4; ++kb) {
        const float* __restrict__ Ap = Aps[kb];
        const float* __restrict__ Bp = Bps[kb];
#pragma unroll
        for (int j = 0; j < 4; ++j) {
            int v = t + j * 256;
            int r = v >> 4, c4 = v & 15;
            int gr = rowBase + r;
            if (gr >= M) gr = M - 1;
            float4 av = *(const float4*)(Ap + (size_t)gr * 64 + c4 * 4);
            As[r * 65 + c4 * 4 + 0] = av.x;
            As[r * 65 + c4 * 4 + 1] = av.y;
            As[r * 65 + c4 * 4 + 2] = av.z;
            As[r * 65 + c4 * 4 + 3] = av.w;
        }
#pragma unroll
        for (int j = 0; j < 16; ++j) {
            int idx = t + j * 256;
            int r = idx >> 6, c = idx & 63;
            int col = colBase + c;
            Bs[r * 64 + c] = (col < OUTF) ? Bp[(size_t)r * OUTF + col] : 0.f;
        }
        __syncthreads();
#pragma unroll 8
        for (int kk = 0; kk < 64; ++kk) {
            float4 b = *(const float4*)&Bs[kk * 64 + tx * 4];
            float a0 = As[(ty * 4 + 0) * 65 + kk];
            float a1 = As[(ty * 4 + 1) * 65 + kk];
            float a2 = As[(ty * 4 + 2) * 65 + kk];
            float a3 = As[(ty * 4 + 3) * 65 + kk];
            acc[0][0] += a0 * b.x; acc[0][1] += a0 * b.y; acc[0][2] += a0 * b.z; acc[0][3] += a0 * b.w;
            acc[1][0] += a1 * b.x; acc[1][1] += a1 * b.y; acc[1][2] += a1 * b.z; acc[1][3] += a1 * b.w;
            acc[2][0] += a2 * b.x; acc[2][1] += a2 * b.y; acc[2][2] += a2 * b.z; acc[2][3] += a2 * b.w;
            acc[3][0] += a3 * b.x; acc[3][1] += a3 * b.y; acc[3][2] += a3 * b.z; acc[3][3] += a3 * b.w;
        }
        __syncthreads();
    }

#pragma unroll
    for (int r = 0; r < 4; ++r) {
        int gr = rowBase + ty * 4 + r;
        if (gr >= M) continue;
#pragma unroll
        for (int c = 0; c < 4; ++c) {
            int col = colBase + tx * 4 + c;
            if (col < OUTF)
                C[(size_t)gr * OUTF + col] = acc[r][c] + g_bsum2[col];
        }
    }
}

// ---------------- host launcher ----------------
static inline void* sym(const void* s) {
    void* p = nullptr;
    cudaGetSymbolAddress(&p, s);
    return p;
}

extern "C" void kernel_launch(void* const* d_in, const int* in_sizes, int n_in,
                              void* d_out, int out_size) {
    const float* x_paper  = (const float*)d_in[0];
    const float* x_author = (const float*)d_in[1];
    const float* x_field  = (const float*)d_in[2];
    const int* ei_wr = (const int*)d_in[3];
    const int* ei_rw = (const int*)d_in[4];
    const int* ei_ci = (const int*)d_in[5];
    const int* ei_ht = (const int*)d_in[6];
    const int* ei_rh = (const int*)d_in[7];
    const int nE_wr = in_sizes[3] / 2;
    const int nE_rw = in_sizes[4] / 2;
    const int nE_ci = in_sizes[5] / 2;
    const int nE_ht = in_sizes[6] / 2;
    const int nE_rh = in_sizes[7] / 2;

    const float* wl1_wr = (const float*)d_in[8];
    const float* wr1_wr = (const float*)d_in[9];
    const float* b1_wr  = (const float*)d_in[10];
    const float* wl1_rw = (const float*)d_in[11];
    const float* wr1_rw = (const float*)d_in[12];
    const float* b1_rw  = (const float*)d_in[13];
    const float* wl1_ci = (const float*)d_in[14];
    const float* wr1_ci = (const float*)d_in[15];
    const float* b1_ci  = (const float*)d_in[16];
    const float* wl1_ht = (const float*)d_in[17];
    const float* wr1_ht = (const float*)d_in[18];
    const float* b1_ht  = (const float*)d_in[19];
    const float* wl1_rh = (const float*)d_in[20];
    const float* wr1_rh = (const float*)d_in[21];
    const float* b1_rh  = (const float*)d_in[22];
    const float* wl2_wr = (const float*)d_in[23];
    const float* wr2_wr = (const float*)d_in[24];
    const float* b2_wr  = (const float*)d_in[25];
    const float* wl2_ci = (const float*)d_in[26];
    const float* wr2_ci = (const float*)d_in[27];
    const float* b2_ci  = (const float*)d_in[28];
    const float* wl2_rh = (const float*)d_in[29];
    const float* wr2_rh = (const float*)d_in[30];
    const float* b2_rh  = (const float*)d_in[31];

    float* out = (float*)d_out;

    // resolve scratch addresses
    float* hs_wr = (float*)sym(g_hs_wr);
    float* hs_rw = (float*)sym(g_hs_rw);
    float* hs_ci = (float*)sym(g_hs_ci);
    float* hs_ht = (float*)sym(g_hs_ht);
    float* hs_rh = (float*)sym(g_hs_rh);
    float* m_wr = (float*)sym(g_m_wr);
    float* m_rw = (float*)sym(g_m_rw);
    float* m_ci = (float*)sym(g_m_ci);
    float* m_ht = (float*)sym(g_m_ht);
    float* m_rh = (float*)sym(g_m_rh);
    float* selfP = (float*)sym(g_selfP);
    float* selfA = (float*)sym(g_selfA);
    float* selfF = (float*)sym(g_selfF);
    float* p1 = (float*)sym(g_p1);
    float* a1 = (float*)sym(g_a1);
    float* f1 = (float*)sym(g_f1);
    float* m2_wr = (float*)sym(g_m2_wr);
    float* m2_ci = (float*)sym(g_m2_ci);
    float* m2_rh = (float*)sym(g_m2_rh);
    int* cnt_wr = (int*)sym(g_cnt_wr);
    int* cnt_rw = (int*)sym(g_cnt_rw);
    int* cnt_ci = (int*)sym(g_cnt_ci);
    int* cnt_ht = (int*)sym(g_cnt_ht);
    int* cnt_rh = (int*)sym(g_cnt_rh);
    int* rp_wr = (int*)sym(g_rp_wr);
    int* rp_rw = (int*)sym(g_rp_rw);
    int* rp_ci = (int*)sym(g_rp_ci);
    int* rp_ht = (int*)sym(g_rp_ht);
    int* rp_rh = (int*)sym(g_rp_rh);
    int* fl_wr = (int*)sym(g_fl_wr);
    int* fl_rw = (int*)sym(g_fl_rw);
    int* fl_ci = (int*)sym(g_fl_ci);
    int* fl_ht = (int*)sym(g_fl_ht);
    int* fl_rh = (int*)sym(g_fl_rh);
    int* csr_wr = (int*)sym(g_csr_wr);
    int* csr_rw = (int*)sym(g_csr_rw);
    int* csr_ci = (int*)sym(g_csr_ci);
    int* csr_ht = (int*)sym(g_csr_ht);
    int* csr_rh = (int*)sym(g_csr_rh);
    int* bsum = (int*)sym(g_bsum);
    float* wsumP = (float*)sym(g_wsumP);
    float* w2sum = (float*)sym(g_w2sum);

    // ---- zero degree counters ----
    cudaMemsetAsync(cnt_wr, 0, sizeof(int) * NP, 0);
    cudaMemsetAsync(cnt_rw, 0, sizeof(int) * NA, 0);
    cudaMemsetAsync(cnt_ci, 0, sizeof(int) * NP, 0);
    cudaMemsetAsync(cnt_ht, 0, sizeof(int) * NF, 0);
    cudaMemsetAsync(cnt_rh, 0, sizeof(int) * NP, 0);

    // ---- summed weights / biases ----
    prep_weights<<<(HID * OUTF + 255) / 256, 256>>>(
        wr1_wr, wr1_ci, wr1_rh, wr2_wr, wr2_ci, wr2_rh,
        b1_wr, b1_ci, b1_rh, b2_wr, b2_ci, b2_rh);

    // ---- CSR build (count -> scan -> fill), per edge type ----
    struct CsrJob {
        const int* ei; int E; int* cnt; int* rp; int* fl; int* csr; int n; int* bs;
    } jobs[5] = {
        {ei_wr, nE_wr, cnt_wr, rp_wr, fl_wr, csr_wr, NP, bsum + 0 * 128},
        {ei_rw, nE_rw, cnt_rw, rp_rw, fl_rw, csr_rw, NA, bsum + 1 * 128},
        {ei_ci, nE_ci, cnt_ci, rp_ci, fl_ci, csr_ci, NP, bsum + 2 * 128},
        {ei_ht, nE_ht, cnt_ht, rp_ht, fl_ht, csr_ht, NF, bsum + 3 * 128},
        {ei_rh, nE_rh, cnt_rh, rp_rh, fl_rh, csr_rh, NP, bsum + 4 * 128},
    };
    for (int i = 0; i < 5; ++i)
        k_count<<<(jobs[i].E + 255) / 256, 256>>>(jobs[i].ei, jobs[i].E, jobs[i].cnt);
    for (int i = 0; i < 5; ++i) {
        int nb = (jobs[i].n + 1023) / 1024;
        k_blocksum<<<nb, 256>>>(jobs[i].cnt, jobs[i].n, jobs[i].bs);
        k_scan_bsums<<<1, 256>>>(jobs[i].bs, nb, jobs[i].rp + jobs[i].n);
        k_scan_write<<<nb, 256>>>(jobs[i].cnt, jobs[i].n, jobs[i].bs, jobs[i].rp, jobs[i].fl);
    }
    for (int i = 0; i < 5; ++i)
        k_fill<<<(jobs[i].E + 255) / 256, 256>>>(jobs[i].ei, jobs[i].E, jobs[i].fl, jobs[i].csr);

    // ---- layer-1 transforms (transform before aggregate: mean is linear) ----
    const int gP = (NP + 63) / 64, gA = (NA + 63) / 64, gF = (NF + 63) / 64;
    {
        GemmBatch bp;  // paper: 4 outputs
        bp.B[0] = wl1_rw; bp.C[0] = hs_rw;
        bp.B[1] = wl1_ci; bp.C[1] = hs_ci;
        bp.B[2] = wl1_ht; bp.C[2] = hs_ht;
        bp.B[3] = wsumP;  bp.C[3] = selfP;
        gemm_f128_multi<<<dim3(gP, 4), 256>>>(x_paper, bp, NP);
        GemmBatch ba;  // author: 2 outputs
        ba.B[0] = wl1_wr; ba.C[0] = hs_wr;
        ba.B[1] = wr1_rw; ba.C[1] = selfA;
        ba.B[2] = wl1_wr; ba.C[2] = hs_wr;
        ba.B[3] = wl1_wr; ba.C[3] = hs_wr;
        gemm_f128_multi<<<dim3(gA, 2), 256>>>(x_author, ba, NA);
        GemmBatch bf;  // field: 2 outputs
        bf.B[0] = wl1_rh; bf.C[0] = hs_rh;
        bf.B[1] = wr1_ht; bf.C[1] = selfF;
        bf.B[2] = wl1_rh; bf.C[2] = hs_rh;
        bf.B[3] = wl1_rh; bf.C[3] = hs_rh;
        gemm_f128_multi<<<dim3(gF, 2), 256>>>(x_field, bf, NF);
    }

    // ---- layer-1 pull (mean fused) ----
    auto pg = [](int n) { return (n * 16 + 255) / 256; };
    k_pull<<<pg(NP), 256>>>(hs_wr, rp_wr, csr_wr, m_wr, NP);
    k_pull<<<pg(NA), 256>>>(hs_rw, rp_rw, csr_rw, m_rw, NA);
    k_pull<<<pg(NP), 256>>>(hs_ci, rp_ci, csr_ci, m_ci, NP);
    k_pull<<<pg(NF), 256>>>(hs_ht, rp_ht, csr_ht, m_ht, NF);
    k_pull<<<pg(NP), 256>>>(hs_rh, rp_rh, csr_rh, m_rh, NP);

    // ---- layer-1 finalize (self + bias + means + relu) ----
    finalize_p1_k<<<(NP * 16 + 255) / 256, 256>>>();
    finalize_af_k<<<(NA * 16 + 255) / 256, 256>>>(selfA, m_rw, b1_rw, a1, NA);
    finalize_af_k<<<(NF * 16 + 255) / 256, 256>>>(selfF, m_ht, b1_ht, f1, NF);

    // ---- layer-2 pull (CSR reused) ----
    k_pull<<<pg(NP), 256>>>(a1, rp_wr, csr_wr, m2_wr, NP);
    k_pull<<<pg(NP), 256>>>(p1, rp_ci, csr_ci, m2_ci, NP);
    k_pull<<<pg(NP), 256>>>(f1, rp_rh, csr_rh, m2_rh, NP);

    // ---- output GEMM: 4 K-chunks (3 aggregated + self) into [100000, 349] ----
    dim3 g2(gP, (OUTF + 63) / 64);
    gemm_out<<<g2, 256>>>(m2_wr, m2_ci, m2_rh, p1,
                          wl2_wr, wl2_ci, wl2_rh, w2sum,
                          out, NP);
}

// round 3
// speedup vs baseline: 1.6679x; 1.4121x over previous
#include <cuda_runtime.h>
#include <cstdint>

#define NP 100000
#define NA 100000
#define NF 50000
#define FIN 128
#define HID 64
#define OUTF 349

#define E_WR 1000000
#define E_RW 1000000
#define E_CI 2000000
#define E_HT 1000000
#define E_RH 1000000

// ---------------- scratch (device globals; no runtime allocation) ----------------
static __device__ __align__(256) float g_hs_wr[NA * HID];
static __device__ __align__(256) float g_hs_rw[NP * HID];
static __device__ __align__(256) float g_hs_ci[NP * HID];
static __device__ __align__(256) float g_hs_ht[NP * HID];
static __device__ __align__(256) float g_hs_rh[NF * HID];
static __device__ __align__(256) float g_m_wr[NP * HID];
static __device__ __align__(256) float g_m_rw[NA * HID];
static __device__ __align__(256) float g_m_ci[NP * HID];
static __device__ __align__(256) float g_m_ht[NF * HID];
static __device__ __align__(256) float g_m_rh[NP * HID];
static __device__ __align__(256) float g_selfP[NP * HID];
static __device__ __align__(256) float g_selfA[NA * HID];
static __device__ __align__(256) float g_selfF[NF * HID];
static __device__ __align__(256) float g_p1[NP * HID];
static __device__ __align__(256) float g_a1[NA * HID];
static __device__ __align__(256) float g_f1[NF * HID];
static __device__ __align__(256) float g_m2_wr[NP * HID];
static __device__ __align__(256) float g_m2_ci[NP * HID];
static __device__ __align__(256) float g_m2_rh[NP * HID];
// CSR per edge type
static __device__ int g_cnt_wr[NP], g_cnt_rw[NA], g_cnt_ci[NP], g_cnt_ht[NF], g_cnt_rh[NP];
static __device__ int g_rp_wr[NP + 1], g_rp_rw[NA + 1], g_rp_ci[NP + 1], g_rp_ht[NF + 1], g_rp_rh[NP + 1];
static __device__ int g_fl_wr[NP], g_fl_rw[NA], g_fl_ci[NP], g_fl_ht[NF], g_fl_rh[NP];
static __device__ int g_csr_wr[E_WR], g_csr_rw[E_RW], g_csr_ci[E_CI], g_csr_ht[E_HT], g_csr_rh[E_RH];
static __device__ int g_bsum[5][128];
// summed weights / biases
static __device__ __align__(256) float g_wsumP[FIN * HID];
static __device__ __align__(256) float g_w2sum[HID * OUTF];
static __device__ __align__(256) float g_bsum1[HID];
static __device__ __align__(256) float g_bsum2[OUTF];

// ---------------- tf32 helpers ----------------
__device__ __forceinline__ uint32_t to_tf32(float x) {
    uint32_t r;
    asm("cvt.rna.tf32.f32 %0, %1;" : "=r"(r) : "f"(x));
    return r;
}

__device__ __forceinline__ void mma_tf32(float c[4], uint32_t a0, uint32_t a1,
                                         uint32_t a2, uint32_t a3,
                                         uint32_t b0, uint32_t b1) {
    asm volatile("mma.sync.aligned.m16n8k8.row.col.f32.tf32.tf32.f32 "
                 "{%0,%1,%2,%3}, {%4,%5,%6,%7}, {%8,%9}, {%0,%1,%2,%3};"
                 : "+f"(c[0]), "+f"(c[1]), "+f"(c[2]), "+f"(c[3])
                 : "r"(a0), "r"(a1), "r"(a2), "r"(a3), "r"(b0), "r"(b1));
}

// ---------------- weight/bias prep ----------------
__global__ void prep_weights(const float* __restrict__ wr1a, const float* __restrict__ wr1b,
                             const float* __restrict__ wr1c,
                             const float* __restrict__ wr2a, const float* __restrict__ wr2b,
                             const float* __restrict__ wr2c,
                             const float* __restrict__ b1a, const float* __restrict__ b1b,
                             const float* __restrict__ b1c,
                             const float* __restrict__ b2a, const float* __restrict__ b2b,
                             const float* __restrict__ b2c) {
    int i = blockIdx.x * blockDim.x + threadIdx.x;
    if (i < FIN * HID) g_wsumP[i] = wr1a[i] + wr1b[i] + wr1c[i];
    if (i < HID * OUTF) g_w2sum[i] = wr2a[i] + wr2b[i] + wr2c[i];
    if (i < HID) g_bsum1[i] = b1a[i] + b1b[i] + b1c[i];
    if (i < OUTF) g_bsum2[i] = b2a[i] + b2b[i] + b2c[i];
}

// ---------------- CSR build ----------------
__global__ void k_count(const int* __restrict__ ei, int E, int* __restrict__ cnt) {
    int e = blockIdx.x * blockDim.x + threadIdx.x;
    if (e >= E) return;
    atomicAdd(cnt + __ldg(ei + E + e), 1);
}

__global__ void k_blocksum(const int* __restrict__ c, int n, int* __restrict__ bsum) {
    __shared__ int s[256];
    int base = blockIdx.x * 1024;
    int t = threadIdx.x;
    int v = 0;
#pragma unroll
    for (int j = 0; j < 4; ++j) {
        int i = base + t * 4 + j;
        if (i < n) v += c[i];
    }
    s[t] = v;
    __syncthreads();
    for (int o = 128; o > 0; o >>= 1) {
        if (t < o) s[t] += s[t + o];
        __syncthreads();
    }
    if (t == 0) bsum[blockIdx.x] = s[0];
}

__global__ void k_scan_bsums(int* __restrict__ bsum, int nb, int* __restrict__ rp_last) {
    __shared__ int s[256];
    int t = threadIdx.x;
    int v = (t < nb) ? bsum[t] : 0;
    s[t] = v;
    __syncthreads();
    for (int o = 1; o < 256; o <<= 1) {
        int x = (t >= o) ? s[t - o] : 0;
        __syncthreads();
        s[t] += x;
        __syncthreads();
    }
    if (t < nb) bsum[t] = s[t] - v;
    if (t == 0) *rp_last = s[255];
}

__global__ void k_scan_write(const int* __restrict__ c, int n, const int* __restrict__ bsum_ex,
                             int* __restrict__ rowptr, int* __restrict__ fill) {
    __shared__ int s[256];
    int base = blockIdx.x * 1024;
    int t = threadIdx.x;
    int loc[4];
    int v = 0;
#pragma unroll
    for (int j = 0; j < 4; ++j) {
        int i = base + t * 4 + j;
        loc[j] = v;
        v += (i < n) ? c[i] : 0;
    }
    s[t] = v;
    __syncthreads();
    for (int o = 1; o < 256; o <<= 1) {
        int x = (t >= o) ? s[t - o] : 0;
        __syncthreads();
        s[t] += x;
        __syncthreads();
    }
    int ex = s[t] - v;
    int off = bsum_ex[blockIdx.x] + ex;
#pragma unroll
    for (int j = 0; j < 4; ++j) {
        int i = base + t * 4 + j;
        if (i < n) {
            int r = off + loc[j];
            rowptr[i] = r;
            fill[i] = r;
        }
    }
}

__global__ void k_fill(const int* __restrict__ ei, int E, int* __restrict__ fill,
                       int* __restrict__ csr) {
    int e = blockIdx.x * blockDim.x + threadIdx.x;
    if (e >= E) return;
    int s = __ldg(ei + e);
    int d = __ldg(ei + E + e);
    int pos = atomicAdd(fill + d, 1);
    csr[pos] = s;
}

// ---------------- pull aggregation (mean fused), 16 threads per dst ----------------
__global__ void k_pull(const float* __restrict__ feat, const int* __restrict__ rowptr,
                       const int* __restrict__ csr, float* __restrict__ out, int n) {
    int gid = blockIdx.x * blockDim.x + threadIdx.x;
    int g = gid >> 4, lane = gid & 15;
    if (g >= n) return;
    int beg = __ldg(rowptr + g), end = __ldg(rowptr + g + 1);
    float4 acc = make_float4(0.f, 0.f, 0.f, 0.f);
    int j = beg;
    for (; j + 1 < end; j += 2) {
        int s0 = __ldg(csr + j);
        int s1 = __ldg(csr + j + 1);
        float4 v0 = *(const float4*)(feat + (size_t)s0 * HID + lane * 4);
        float4 v1 = *(const float4*)(feat + (size_t)s1 * HID + lane * 4);
        acc.x += v0.x + v1.x;
        acc.y += v0.y + v1.y;
        acc.z += v0.z + v1.z;
        acc.w += v0.w + v1.w;
    }
    if (j < end) {
        int s0 = __ldg(csr + j);
        float4 v0 = *(const float4*)(feat + (size_t)s0 * HID + lane * 4);
        acc.x += v0.x; acc.y += v0.y; acc.z += v0.z; acc.w += v0.w;
    }
    float inv = 1.f / fmaxf((float)(end - beg), 1.f);
    acc.x *= inv; acc.y *= inv; acc.z *= inv; acc.w *= inv;
    *(float4*)(out + (size_t)g * HID + lane * 4) = acc;
}

// ---------------- tf32 GEMM: C[M,64] = A[M,128] @ B[128,64], batched ----------------
struct GemmBatch {
    const float* B[4];
    float* C[4];
};

__global__ void gemm_tf32_f128(const float* __restrict__ A, GemmBatch p, int M) {
    __shared__ uint32_t As[128 * 36];
    __shared__ uint32_t BsT[64 * 36];
    const float* __restrict__ Bp = p.B[blockIdx.y];
    float* __restrict__ Cp = p.C[blockIdx.y];
    const int t = threadIdx.x;
    const int wid = t >> 5, lane = t & 31;
    const int g = lane >> 2, tg = lane & 3;
    const int rowBase = blockIdx.x * 128;
    const int wrow = wid * 16;

    float c[8][4] = {};

    for (int kb = 0; kb < 4; ++kb) {
        // A chunk: 128 rows x 32 k
#pragma unroll
        for (int j = 0; j < 4; ++j) {
            int idx = t + j * 256;          // 0..1023
            int r = idx >> 3, c4 = idx & 7;
            int gr = rowBase + r;
            if (gr >= M) gr = M - 1;
            float4 av = *(const float4*)(A + (size_t)gr * FIN + kb * 32 + c4 * 4);
            uint32_t* d = &As[r * 36 + c4 * 4];
            d[0] = to_tf32(av.x); d[1] = to_tf32(av.y);
            d[2] = to_tf32(av.z); d[3] = to_tf32(av.w);
        }
        // B chunk: 32 k x 64 n -> BsT[n][k]
#pragma unroll
        for (int j = 0; j < 2; ++j) {
            int idx = t + j * 256;          // 0..511
            int r = idx >> 4, c4 = idx & 15;
            float4 bv = *(const float4*)(Bp + (size_t)(kb * 32 + r) * HID + c4 * 4);
            BsT[(c4 * 4 + 0) * 36 + r] = to_tf32(bv.x);
            BsT[(c4 * 4 + 1) * 36 + r] = to_tf32(bv.y);
            BsT[(c4 * 4 + 2) * 36 + r] = to_tf32(bv.z);
            BsT[(c4 * 4 + 3) * 36 + r] = to_tf32(bv.w);
        }
        __syncthreads();
#pragma unroll
        for (int ks = 0; ks < 4; ++ks) {
            int k0 = ks * 8;
            uint32_t a0 = As[(wrow + g) * 36 + k0 + tg];
            uint32_t a1 = As[(wrow + g + 8) * 36 + k0 + tg];
            uint32_t a2 = As[(wrow + g) * 36 + k0 + tg + 4];
            uint32_t a3 = As[(wrow + g + 8) * 36 + k0 + tg + 4];
#pragma unroll
            for (int nt = 0; nt < 8; ++nt) {
                uint32_t b0 = BsT[(nt * 8 + g) * 36 + k0 + tg];
                uint32_t b1 = BsT[(nt * 8 + g) * 36 + k0 + tg + 4];
                mma_tf32(c[nt], a0, a1, a2, a3, b0, b1);
            }
        }
        __syncthreads();
    }

    int r0 = rowBase + wrow + g, r1 = r0 + 8;
#pragma unroll
    for (int nt = 0; nt < 8; ++nt) {
        int col = nt * 8 + tg * 2;
        if (r0 < M) *(float2*)(Cp + (size_t)r0 * HID + col) = make_float2(c[nt][0], c[nt][1]);
        if (r1 < M) *(float2*)(Cp + (size_t)r1 * HID + col) = make_float2(c[nt][2], c[nt][3]);
    }
}

// ---------------- tf32 output GEMM: C[M,349] = sum_b A_b[M,64] @ B_b[64,349] + bsum2 ----------------
__global__ void gemm_out_tf32(const float* __restrict__ A0, const float* __restrict__ A1,
                              const float* __restrict__ A2, const float* __restrict__ A3,
                              const float* __restrict__ B0, const float* __restrict__ B1,
                              const float* __restrict__ B2, const float* __restrict__ B3,
                              float* __restrict__ C, int M) {
    __shared__ uint32_t As[128 * 36];
    __shared__ uint32_t BsT[64 * 36];
    const int t = threadIdx.x;
    const int wid = t >> 5, lane = t & 31;
    const int g = lane >> 2, tg = lane & 3;
    const int rowBase = blockIdx.x * 128;
    const int colBase = blockIdx.y * 64;
    const int wrow = wid * 16;

    const float* Aps[4] = {A0, A1, A2, A3};
    const float* Bps[4] = {B0, B1, B2, B3};

    float c[8][4] = {};

    for (int m = 0; m < 4; ++m) {
        const float* __restrict__ Ap = Aps[m];
        const float* __restrict__ Bp = Bps[m];
        for (int kb = 0; kb < 2; ++kb) {
            // A chunk: 128 x 32 (A row stride = 64)
#pragma unroll
            for (int j = 0; j < 4; ++j) {
                int idx = t + j * 256;
                int r = idx >> 3, c4 = idx & 7;
                int gr = rowBase + r;
                if (gr >= M) gr = M - 1;
                float4 av = *(const float4*)(Ap + (size_t)gr * HID + kb * 32 + c4 * 4);
                uint32_t* d = &As[r * 36 + c4 * 4];
                d[0] = to_tf32(av.x); d[1] = to_tf32(av.y);
                d[2] = to_tf32(av.z); d[3] = to_tf32(av.w);
            }
            // B chunk: 32 k x 64 n (row stride OUTF, col-guarded) -> BsT[n][k]
#pragma unroll
            for (int j = 0; j < 8; ++j) {
                int idx = t + j * 256;      // 0..2047
                int r = idx >> 6, cc = idx & 63;
                int col = colBase + cc;
                float v = (col < OUTF) ? Bp[(size_t)(kb * 32 + r) * OUTF + col] : 0.f;
                BsT[cc * 36 + r] = to_tf32(v);
            }
            __syncthreads();
#pragma unroll
            for (int ks = 0; ks < 4; ++ks) {
                int k0 = ks * 8;
                uint32_t a0 = As[(wrow + g) * 36 + k0 + tg];
                uint32_t a1 = As[(wrow + g + 8) * 36 + k0 + tg];
                uint32_t a2 = As[(wrow + g) * 36 + k0 + tg + 4];
                uint32_t a3 = As[(wrow + g + 8) * 36 + k0 + tg + 4];
#pragma unroll
                for (int nt = 0; nt < 8; ++nt) {
                    uint32_t b0 = BsT[(nt * 8 + g) * 36 + k0 + tg];
                    uint32_t b1 = BsT[(nt * 8 + g) * 36 + k0 + tg + 4];
                    mma_tf32(c[nt], a0, a1, a2, a3, b0, b1);
                }
            }
            __syncthreads();
        }
    }

    int r0 = rowBase + wrow + g, r1 = r0 + 8;
#pragma unroll
    for (int nt = 0; nt < 8; ++nt) {
        int col = colBase + nt * 8 + tg * 2;
        if (col < OUTF) {
            float bia = g_bsum2[col];
            if (r0 < M) C[(size_t)r0 * OUTF + col] = c[nt][0] + bia;
            if (r1 < M) C[(size_t)r1 * OUTF + col] = c[nt][2] + bia;
        }
        if (col + 1 < OUTF) {
            float bib = g_bsum2[col + 1];
            if (r0 < M) C[(size_t)r0 * OUTF + col + 1] = c[nt][1] + bib;
            if (r1 < M) C[(size_t)r1 * OUTF + col + 1] = c[nt][3] + bib;
        }
    }
}

// ---------------- layer-1 finalize ----------------
__global__ void finalize_p1_k() {
    int t = blockIdx.x * blockDim.x + threadIdx.x;
    if (t >= NP * 16) return;
    int l = t & 15;
    float4 s = ((const float4*)g_selfP)[t];
    float4 aw = ((const float4*)g_m_wr)[t];
    float4 ac = ((const float4*)g_m_ci)[t];
    float4 ar = ((const float4*)g_m_rh)[t];
    float4 b = ((const float4*)g_bsum1)[l];
    float4 o;
    o.x = fmaxf(s.x + b.x + aw.x + ac.x + ar.x, 0.f);
    o.y = fmaxf(s.y + b.y + aw.y + ac.y + ar.y, 0.f);
    o.z = fmaxf(s.z + b.z + aw.z + ac.z + ar.z, 0.f);
    o.w = fmaxf(s.w + b.w + aw.w + ac.w + ar.w, 0.f);
    ((float4*)g_p1)[t] = o;
}

__global__ void finalize_af_k(const float* __restrict__ selfX, const float* __restrict__ mean,
                              const float* __restrict__ bias, float* __restrict__ out, int n) {
    int t = blockIdx.x * blockDim.x + threadIdx.x;
    if (t >= n * 16) return;
    int l = t & 15;
    float4 s = ((const float4*)selfX)[t];
    float4 a = ((const float4*)mean)[t];
    float4 b = ((const float4*)bias)[l];
    float4 o;
    o.x = fmaxf(s.x + b.x + a.x, 0.f);
    o.y = fmaxf(s.y + b.y + a.y, 0.f);
    o.z = fmaxf(s.z + b.z + a.z, 0.f);
    o.w = fmaxf(s.w + b.w + a.w, 0.f);
    ((float4*)out)[t] = o;
}

// ---------------- host launcher ----------------
static inline void* sym(const void* s) {
    void* p = nullptr;
    cudaGetSymbolAddress(&p, s);
    return p;
}

extern "C" void kernel_launch(void* const* d_in, const int* in_sizes, int n_in,
                              void* d_out, int out_size) {
    const float* x_paper  = (const float*)d_in[0];
    const float* x_author = (const float*)d_in[1];
    const float* x_field  = (const float*)d_in[2];
    const int* ei_wr = (const int*)d_in[3];
    const int* ei_rw = (const int*)d_in[4];
    const int* ei_ci = (const int*)d_in[5];
    const int* ei_ht = (const int*)d_in[6];
    const int* ei_rh = (const int*)d_in[7];
    const int nE_wr = in_sizes[3] / 2;
    const int nE_rw = in_sizes[4] / 2;
    const int nE_ci = in_sizes[5] / 2;
    const int nE_ht = in_sizes[6] / 2;
    const int nE_rh = in_sizes[7] / 2;

    const float* wl1_wr = (const float*)d_in[8];
    const float* wr1_wr = (const float*)d_in[9];
    const float* b1_wr  = (const float*)d_in[10];
    const float* wl1_rw = (const float*)d_in[11];
    const float* wr1_rw = (const float*)d_in[12];
    const float* b1_rw  = (const float*)d_in[13];
    const float* wl1_ci = (const float*)d_in[14];
    const float* wr1_ci = (const float*)d_in[15];
    const float* b1_ci  = (const float*)d_in[16];
    const float* wl1_ht = (const float*)d_in[17];
    const float* wr1_ht = (const float*)d_in[18];
    const float* b1_ht  = (const float*)d_in[19];
    const float* wl1_rh = (const float*)d_in[20];
    const float* wr1_rh = (const float*)d_in[21];
    const float* b1_rh  = (const float*)d_in[22];
    const float* wl2_wr = (const float*)d_in[23];
    const float* wr2_wr = (const float*)d_in[24];
    const float* b2_wr  = (const float*)d_in[25];
    const float* wl2_ci = (const float*)d_in[26];
    const float* wr2_ci = (const float*)d_in[27];
    const float* b2_ci  = (const float*)d_in[28];
    const float* wl2_rh = (const float*)d_in[29];
    const float* wr2_rh = (const float*)d_in[30];
    const float* b2_rh  = (const float*)d_in[31];

    float* out = (float*)d_out;

    float* hs_wr = (float*)sym(g_hs_wr);
    float* hs_rw = (float*)sym(g_hs_rw);
    float* hs_ci = (float*)sym(g_hs_ci);
    float* hs_ht = (float*)sym(g_hs_ht);
    float* hs_rh = (float*)sym(g_hs_rh);
    float* m_wr = (float*)sym(g_m_wr);
    float* m_rw = (float*)sym(g_m_rw);
    float* m_ci = (float*)sym(g_m_ci);
    float* m_ht = (float*)sym(g_m_ht);
    float* m_rh = (float*)sym(g_m_rh);
    float* selfP = (float*)sym(g_selfP);
    float* selfA = (float*)sym(g_selfA);
    float* selfF = (float*)sym(g_selfF);
    float* p1 = (float*)sym(g_p1);
    float* a1 = (float*)sym(g_a1);
    float* f1 = (float*)sym(g_f1);
    float* m2_wr = (float*)sym(g_m2_wr);
    float* m2_ci = (float*)sym(g_m2_ci);
    float* m2_rh = (float*)sym(g_m2_rh);
    int* cnt_wr = (int*)sym(g_cnt_wr);
    int* cnt_rw = (int*)sym(g_cnt_rw);
    int* cnt_ci = (int*)sym(g_cnt_ci);
    int* cnt_ht = (int*)sym(g_cnt_ht);
    int* cnt_rh = (int*)sym(g_cnt_rh);
    int* rp_wr = (int*)sym(g_rp_wr);
    int* rp_rw = (int*)sym(g_rp_rw);
    int* rp_ci = (int*)sym(g_rp_ci);
    int* rp_ht = (int*)sym(g_rp_ht);
    int* rp_rh = (int*)sym(g_rp_rh);
    int* fl_wr = (int*)sym(g_fl_wr);
    int* fl_rw = (int*)sym(g_fl_rw);
    int* fl_ci = (int*)sym(g_fl_ci);
    int* fl_ht = (int*)sym(g_fl_ht);
    int* fl_rh = (int*)sym(g_fl_rh);
    int* csr_wr = (int*)sym(g_csr_wr);
    int* csr_rw = (int*)sym(g_csr_rw);
    int* csr_ci = (int*)sym(g_csr_ci);
    int* csr_ht = (int*)sym(g_csr_ht);
    int* csr_rh = (int*)sym(g_csr_rh);
    int* bsum = (int*)sym(g_bsum);
    float* wsumP = (float*)sym(g_wsumP);
    float* w2sum = (float*)sym(g_w2sum);

    // zero degree counters
    cudaMemsetAsync(cnt_wr, 0, sizeof(int) * NP, 0);
    cudaMemsetAsync(cnt_rw, 0, sizeof(int) * NA, 0);
    cudaMemsetAsync(cnt_ci, 0, sizeof(int) * NP, 0);
    cudaMemsetAsync(cnt_ht, 0, sizeof(int) * NF, 0);
    cudaMemsetAsync(cnt_rh, 0, sizeof(int) * NP, 0);

    prep_weights<<<(HID * OUTF + 255) / 256, 256>>>(
        wr1_wr, wr1_ci, wr1_rh, wr2_wr, wr2_ci, wr2_rh,
        b1_wr, b1_ci, b1_rh, b2_wr, b2_ci, b2_rh);

    // CSR build
    struct CsrJob {
        const int* ei; int E; int* cnt; int* rp; int* fl; int* csr; int n; int* bs;
    } jobs[5] = {
        {ei_wr, nE_wr, cnt_wr, rp_wr, fl_wr, csr_wr, NP, bsum + 0 * 128},
        {ei_rw, nE_rw, cnt_rw, rp_rw, fl_rw, csr_rw, NA, bsum + 1 * 128},
        {ei_ci, nE_ci, cnt_ci, rp_ci, fl_ci, csr_ci, NP, bsum + 2 * 128},
        {ei_ht, nE_ht, cnt_ht, rp_ht, fl_ht, csr_ht, NF, bsum + 3 * 128},
        {ei_rh, nE_rh, cnt_rh, rp_rh, fl_rh, csr_rh, NP, bsum + 4 * 128},
    };
    for (int i = 0; i < 5; ++i)
        k_count<<<(jobs[i].E + 255) / 256, 256>>>(jobs[i].ei, jobs[i].E, jobs[i].cnt);
    for (int i = 0; i < 5; ++i) {
        int nb = (jobs[i].n + 1023) / 1024;
        k_blocksum<<<nb, 256>>>(jobs[i].cnt, jobs[i].n, jobs[i].bs);
        k_scan_bsums<<<1, 256>>>(jobs[i].bs, nb, jobs[i].rp + jobs[i].n);
        k_scan_write<<<nb, 256>>>(jobs[i].cnt, jobs[i].n, jobs[i].bs, jobs[i].rp, jobs[i].fl);
    }
    for (int i = 0; i < 5; ++i)
        k_fill<<<(jobs[i].E + 255) / 256, 256>>>(jobs[i].ei, jobs[i].E, jobs[i].fl, jobs[i].csr);

    // layer-1 transforms (tf32 tensor cores; transform before aggregate)
    const int gP = (NP + 127) / 128, gA = (NA + 127) / 128, gF = (NF + 127) / 128;
    {
        GemmBatch bp;
        bp.B[0] = wl1_rw; bp.C[0] = hs_rw;
        bp.B[1] = wl1_ci; bp.C[1] = hs_ci;
        bp.B[2] = wl1_ht; bp.C[2] = hs_ht;
        bp.B[3] = wsumP;  bp.C[3] = selfP;
        gemm_tf32_f128<<<dim3(gP, 4), 256>>>(x_paper, bp, NP);
        GemmBatch ba;
        ba.B[0] = wl1_wr; ba.C[0] = hs_wr;
        ba.B[1] = wr1_rw; ba.C[1] = selfA;
        ba.B[2] = wl1_wr; ba.C[2] = hs_wr;
        ba.B[3] = wl1_wr; ba.C[3] = hs_wr;
        gemm_tf32_f128<<<dim3(gA, 2), 256>>>(x_author, ba, NA);
        GemmBatch bf;
        bf.B[0] = wl1_rh; bf.C[0] = hs_rh;
        bf.B[1] = wr1_ht; bf.C[1] = selfF;
        bf.B[2] = wl1_rh; bf.C[2] = hs_rh;
        bf.B[3] = wl1_rh; bf.C[3] = hs_rh;
        gemm_tf32_f128<<<dim3(gF, 2), 256>>>(x_field, bf, NF);
    }

    // layer-1 pull (mean fused)
    auto pg = [](int n) { return (n * 16 + 255) / 256; };
    k_pull<<<pg(NP), 256>>>(hs_wr, rp_wr, csr_wr, m_wr, NP);
    k_pull<<<pg(NA), 256>>>(hs_rw, rp_rw, csr_rw, m_rw, NA);
    k_pull<<<pg(NP), 256>>>(hs_ci, rp_ci, csr_ci, m_ci, NP);
    k_pull<<<pg(NF), 256>>>(hs_ht, rp_ht, csr_ht, m_ht, NF);
    k_pull<<<pg(NP), 256>>>(hs_rh, rp_rh, csr_rh, m_rh, NP);

    // layer-1 finalize
    finalize_p1_k<<<(NP * 16 + 255) / 256, 256>>>();
    finalize_af_k<<<(NA * 16 + 255) / 256, 256>>>(selfA, m_rw, b1_rw, a1, NA);
    finalize_af_k<<<(NF * 16 + 255) / 256, 256>>>(selfF, m_ht, b1_ht, f1, NF);

    // layer-2 pull (CSR reused)
    k_pull<<<pg(NP), 256>>>(a1, rp_wr, csr_wr, m2_wr, NP);
    k_pull<<<pg(NP), 256>>>(p1, rp_ci, csr_ci, m2_ci, NP);
    k_pull<<<pg(NP), 256>>>(f1, rp_rh, csr_rh, m2_rh, NP);

    // output GEMM (tf32): 4 K-chunks into [100000, 349]
    dim3 g2(gP, (OUTF + 63) / 64);
    gemm_out_tf32<<<g2, 256>>>(m2_wr, m2_ci, m2_rh, p1,
                               wl2_wr, wl2_ci, wl2_rh, w2sum,
                               out, NP);
}

// round 4
// speedup vs baseline: 1.7148x; 1.0281x over previous
#include <cuda_runtime.h>
#include <cstdint>

#define NP 100000
#define NA 100000
#define NF 50000
#define FIN 128
#define HID 64
#define OUTF 349

#define E_WR 1000000
#define E_RW 1000000
#define E_CI 2000000
#define E_HT 1000000
#define E_RH 1000000

#define CNT_TOT (NP + NA + NP + NF + NP)   // 450000

// ---------------- scratch (device globals; no runtime allocation) ----------------
static __device__ __align__(256) float g_hs_wr[NA * HID];
static __device__ __align__(256) float g_hs_rw[NP * HID];
static __device__ __align__(256) float g_hs_ci[NP * HID];
static __device__ __align__(256) float g_hs_ht[NP * HID];
static __device__ __align__(256) float g_hs_rh[NF * HID];
static __device__ __align__(256) float g_selfP[NP * HID];
static __device__ __align__(256) float g_selfA[NA * HID];
static __device__ __align__(256) float g_selfF[NF * HID];
static __device__ __align__(256) float g_p1[NP * HID];
static __device__ __align__(256) float g_a1[NA * HID];
static __device__ __align__(256) float g_f1[NF * HID];
static __device__ __align__(256) float g_m2_wr[NP * HID];
static __device__ __align__(256) float g_m2_ci[NP * HID];
static __device__ __align__(256) float g_m2_rh[NP * HID];
// CSR machinery (contiguous counters/fill for single memset)
static __device__ int g_cnt[CNT_TOT];
static __device__ int g_fl[CNT_TOT];
static __device__ int g_rp_wr[NP + 1], g_rp_rw[NA + 1], g_rp_ci[NP + 1], g_rp_ht[NF + 1], g_rp_rh[NP + 1];
static __device__ int g_csr_wr[E_WR], g_csr_rw[E_RW], g_csr_ci[E_CI], g_csr_ht[E_HT], g_csr_rh[E_RH];
static __device__ int g_bsumA[5][128];
// summed weights / biases
static __device__ __align__(256) float g_wsumP[FIN * HID];
static __device__ __align__(256) float g_w2sum[HID * OUTF];
static __device__ __align__(256) float g_bsum1[HID];
static __device__ __align__(256) float g_bsum2[OUTF];

__constant__ int c_n[5] = {NP, NA, NP, NF, NP};
__constant__ int c_off[5] = {0, NP, NP + NA, NP + NA + NP, NP + NA + NP + NF};

__device__ __forceinline__ int* rp_of(int ty) {
    switch (ty) {
        case 0: return g_rp_wr;
        case 1: return g_rp_rw;
        case 2: return g_rp_ci;
        case 3: return g_rp_ht;
        default: return g_rp_rh;
    }
}
__device__ __forceinline__ int* csr_of(int ty) {
    switch (ty) {
        case 0: return g_csr_wr;
        case 1: return g_csr_rw;
        case 2: return g_csr_ci;
        case 3: return g_csr_ht;
        default: return g_csr_rh;
    }
}

// ---------------- tf32 helpers ----------------
__device__ __forceinline__ uint32_t to_tf32(float x) {
    uint32_t r;
    asm("cvt.rna.tf32.f32 %0, %1;" : "=r"(r) : "f"(x));
    return r;
}

__device__ __forceinline__ void mma_tf32(float c[4], uint32_t a0, uint32_t a1,
                                         uint32_t a2, uint32_t a3,
                                         uint32_t b0, uint32_t b1) {
    asm volatile("mma.sync.aligned.m16n8k8.row.col.f32.tf32.tf32.f32 "
                 "{%0,%1,%2,%3}, {%4,%5,%6,%7}, {%8,%9}, {%0,%1,%2,%3};"
                 : "+f"(c[0]), "+f"(c[1]), "+f"(c[2]), "+f"(c[3])
                 : "r"(a0), "r"(a1), "r"(a2), "r"(a3), "r"(b0), "r"(b1));
}

// ---------------- weight/bias prep ----------------
__global__ void prep_weights(const float* __restrict__ wr1a, const float* __restrict__ wr1b,
                             const float* __restrict__ wr1c,
                             const float* __restrict__ wr2a, const float* __restrict__ wr2b,
                             const float* __restrict__ wr2c,
                             const float* __restrict__ b1a, const float* __restrict__ b1b,
                             const float* __restrict__ b1c,
                             const float* __restrict__ b2a, const float* __restrict__ b2b,
                             const float* __restrict__ b2c) {
    int i = blockIdx.x * blockDim.x + threadIdx.x;
    if (i < FIN * HID) g_wsumP[i] = wr1a[i] + wr1b[i] + wr1c[i];
    if (i < HID * OUTF) g_w2sum[i] = wr2a[i] + wr2b[i] + wr2c[i];
    if (i < HID) g_bsum1[i] = b1a[i] + b1b[i] + b1c[i];
    if (i < OUTF) g_bsum2[i] = b2a[i] + b2b[i] + b2c[i];
}

// ---------------- CSR build (batched over all 5 edge types) ----------------
struct EJobs {
    const int* ei[5];
    int E[5];
    int bs[6];   // block-range prefix per type
};

__global__ void k_count_all(EJobs ep) {
    int b = blockIdx.x;
    int ty = 0;
    while (b >= ep.bs[ty + 1]) ++ty;
    int e = (b - ep.bs[ty]) * 256 + threadIdx.x;
    if (e >= ep.E[ty]) return;
    int d = __ldg(ep.ei[ty] + ep.E[ty] + e);
    atomicAdd(g_cnt + c_off[ty] + d, 1);
}

__global__ void k_blocksum_all() {
    __shared__ int s[256];
    int ty = blockIdx.y;
    int n = c_n[ty];
    int base = blockIdx.x * 1024;
    if (base >= n) { if (threadIdx.x == 0) g_bsumA[ty][blockIdx.x] = 0; return; }
    const int* c = g_cnt + c_off[ty];
    int t = threadIdx.x;
    int v = 0;
#pragma unroll
    for (int j = 0; j < 4; ++j) {
        int i = base + t * 4 + j;
        if (i < n) v += c[i];
    }
    s[t] = v;
    __syncthreads();
    for (int o = 128; o > 0; o >>= 1) {
        if (t < o) s[t] += s[t + o];
        __syncthreads();
    }
    if (t == 0) g_bsumA[ty][blockIdx.x] = s[0];
}

__global__ void k_scan_bsums_all() {
    __shared__ int s[256];
    int ty = blockIdx.x;
    int n = c_n[ty];
    int nb = (n + 1023) / 1024;
    int t = threadIdx.x;
    int v = (t < nb) ? g_bsumA[ty][t] : 0;
    s[t] = v;
    __syncthreads();
    for (int o = 1; o < 256; o <<= 1) {
        int x = (t >= o) ? s[t - o] : 0;
        __syncthreads();
        s[t] += x;
        __syncthreads();
    }
    if (t < nb) g_bsumA[ty][t] = s[t] - v;
    if (t == 0) rp_of(ty)[n] = s[255];
}

__global__ void k_scan_write_all() {
    __shared__ int s[256];
    int ty = blockIdx.y;
    int n = c_n[ty];
    int base = blockIdx.x * 1024;
    if (base >= n) return;
    const int* c = g_cnt + c_off[ty];
    int* rowptr = rp_of(ty);
    int* fill = g_fl + c_off[ty];
    int t = threadIdx.x;
    int loc[4];
    int v = 0;
#pragma unroll
    for (int j = 0; j < 4; ++j) {
        int i = base + t * 4 + j;
        loc[j] = v;
        v += (i < n) ? c[i] : 0;
    }
    s[t] = v;
    __syncthreads();
    for (int o = 1; o < 256; o <<= 1) {
        int x = (t >= o) ? s[t - o] : 0;
        __syncthreads();
        s[t] += x;
        __syncthreads();
    }
    int ex = s[t] - v;
    int off = g_bsumA[ty][blockIdx.x] + ex;
#pragma unroll
    for (int j = 0; j < 4; ++j) {
        int i = base + t * 4 + j;
        if (i < n) {
            int r = off + loc[j];
            rowptr[i] = r;
            fill[i] = r;
        }
    }
}

__global__ void k_fill_all(EJobs ep) {
    int b = blockIdx.x;
    int ty = 0;
    while (b >= ep.bs[ty + 1]) ++ty;
    int e = (b - ep.bs[ty]) * 256 + threadIdx.x;
    if (e >= ep.E[ty]) return;
    int s = __ldg(ep.ei[ty] + e);
    int d = __ldg(ep.ei[ty] + ep.E[ty] + e);
    int pos = atomicAdd(g_fl + c_off[ty] + d, 1);
    csr_of(ty)[pos] = s;
}

// ---------------- pull primitives ----------------
__device__ __forceinline__ float4 pull_mean(const float* __restrict__ feat,
                                            const int* __restrict__ rowptr,
                                            const int* __restrict__ csr,
                                            int g, int lane) {
    int beg = __ldg(rowptr + g), end = __ldg(rowptr + g + 1);
    float4 acc = make_float4(0.f, 0.f, 0.f, 0.f);
    int j = beg;
    for (; j + 1 < end; j += 2) {
        int s0 = __ldg(csr + j);
        int s1 = __ldg(csr + j + 1);
        float4 v0 = *(const float4*)(feat + (size_t)s0 * HID + lane * 4);
        float4 v1 = *(const float4*)(feat + (size_t)s1 * HID + lane * 4);
        acc.x += v0.x + v1.x;
        acc.y += v0.y + v1.y;
        acc.z += v0.z + v1.z;
        acc.w += v0.w + v1.w;
    }
    if (j < end) {
        int s0 = __ldg(csr + j);
        float4 v0 = *(const float4*)(feat + (size_t)s0 * HID + lane * 4);
        acc.x += v0.x; acc.y += v0.y; acc.z += v0.z; acc.w += v0.w;
    }
    float inv = 1.f / fmaxf((float)(end - beg), 1.f);
    acc.x *= inv; acc.y *= inv; acc.z *= inv; acc.w *= inv;
    return acc;
}

// layer-1 paper: pull 3 edge types + self + bias + relu -> p1
__global__ void k_layer1_paper() {
    int t = blockIdx.x * blockDim.x + threadIdx.x;
    if (t >= NP * 16) return;
    int g = t >> 4, lane = t & 15;
    float4 aw = pull_mean(g_hs_wr, g_rp_wr, g_csr_wr, g, lane);
    float4 ac = pull_mean(g_hs_ci, g_rp_ci, g_csr_ci, g, lane);
    float4 ar = pull_mean(g_hs_rh, g_rp_rh, g_csr_rh, g, lane);
    float4 s = ((const float4*)g_selfP)[t];
    float4 b = ((const float4*)g_bsum1)[lane];
    float4 o;
    o.x = fmaxf(s.x + b.x + aw.x + ac.x + ar.x, 0.f);
    o.y = fmaxf(s.y + b.y + aw.y + ac.y + ar.y, 0.f);
    o.z = fmaxf(s.z + b.z + aw.z + ac.z + ar.z, 0.f);
    o.w = fmaxf(s.w + b.w + aw.w + ac.w + ar.w, 0.f);
    ((float4*)g_p1)[t] = o;
}

// layer-1 author/field: pull 1 edge type + self + bias + relu -> out
__global__ void k_layer1_af(const float* __restrict__ feat, const int* __restrict__ rowptr,
                            const int* __restrict__ csr, const float* __restrict__ selfX,
                            const float* __restrict__ bias, float* __restrict__ out, int n) {
    int t = blockIdx.x * blockDim.x + threadIdx.x;
    if (t >= n * 16) return;
    int g = t >> 4, lane = t & 15;
    float4 a = pull_mean(feat, rowptr, csr, g, lane);
    float4 s = ((const float4*)selfX)[t];
    float4 b = ((const float4*)bias)[lane];
    float4 o;
    o.x = fmaxf(s.x + b.x + a.x, 0.f);
    o.y = fmaxf(s.y + b.y + a.y, 0.f);
    o.z = fmaxf(s.z + b.z + a.z, 0.f);
    o.w = fmaxf(s.w + b.w + a.w, 0.f);
    ((float4*)out)[t] = o;
}

// layer-2: three pulls into m2 buffers in one kernel
__global__ void k_layer2_pulls() {
    int t = blockIdx.x * blockDim.x + threadIdx.x;
    if (t >= NP * 16) return;
    int g = t >> 4, lane = t & 15;
    ((float4*)g_m2_wr)[t] = pull_mean(g_a1, g_rp_wr, g_csr_wr, g, lane);
    ((float4*)g_m2_ci)[t] = pull_mean(g_p1, g_rp_ci, g_csr_ci, g, lane);
    ((float4*)g_m2_rh)[t] = pull_mean(g_f1, g_rp_rh, g_csr_rh, g, lane);
}

// ---------------- tf32 GEMM: C[M,64] = A[M,128] @ B[128,64], batched ----------------
struct GemmBatch {
    const float* B[4];
    float* C[4];
};

__global__ void gemm_tf32_f128(const float* __restrict__ A, GemmBatch p, int M) {
    __shared__ uint32_t As[128 * 36];
    __shared__ uint32_t BsT[64 * 36];
    const float* __restrict__ Bp = p.B[blockIdx.y];
    float* __restrict__ Cp = p.C[blockIdx.y];
    const int t = threadIdx.x;
    const int wid = t >> 5, lane = t & 31;
    const int g = lane >> 2, tg = lane & 3;
    const int rowBase = blockIdx.x * 128;
    const int wrow = wid * 16;

    float c[8][4] = {};

    for (int kb = 0; kb < 4; ++kb) {
#pragma unroll
        for (int j = 0; j < 4; ++j) {
            int idx = t + j * 256;
            int r = idx >> 3, c4 = idx & 7;
            int gr = rowBase + r;
            if (gr >= M) gr = M - 1;
            float4 av = *(const float4*)(A + (size_t)gr * FIN + kb * 32 + c4 * 4);
            uint32_t* d = &As[r * 36 + c4 * 4];
            d[0] = to_tf32(av.x); d[1] = to_tf32(av.y);
            d[2] = to_tf32(av.z); d[3] = to_tf32(av.w);
        }
#pragma unroll
        for (int j = 0; j < 2; ++j) {
            int idx = t + j * 256;
            int r = idx >> 4, c4 = idx & 15;
            float4 bv = *(const float4*)(Bp + (size_t)(kb * 32 + r) * HID + c4 * 4);
            BsT[(c4 * 4 + 0) * 36 + r] = to_tf32(bv.x);
            BsT[(c4 * 4 + 1) * 36 + r] = to_tf32(bv.y);
            BsT[(c4 * 4 + 2) * 36 + r] = to_tf32(bv.z);
            BsT[(c4 * 4 + 3) * 36 + r] = to_tf32(bv.w);
        }
        __syncthreads();
#pragma unroll
        for (int ks = 0; ks < 4; ++ks) {
            int k0 = ks * 8;
            uint32_t a0 = As[(wrow + g) * 36 + k0 + tg];
            uint32_t a1 = As[(wrow + g + 8) * 36 + k0 + tg];
            uint32_t a2 = As[(wrow + g) * 36 + k0 + tg + 4];
            uint32_t a3 = As[(wrow + g + 8) * 36 + k0 + tg + 4];
#pragma unroll
            for (int nt = 0; nt < 8; ++nt) {
                uint32_t b0 = BsT[(nt * 8 + g) * 36 + k0 + tg];
                uint32_t b1 = BsT[(nt * 8 + g) * 36 + k0 + tg + 4];
                mma_tf32(c[nt], a0, a1, a2, a3, b0, b1);
            }
        }
        __syncthreads();
    }

    int r0 = rowBase + wrow + g, r1 = r0 + 8;
#pragma unroll
    for (int nt = 0; nt < 8; ++nt) {
        int col = nt * 8 + tg * 2;
        if (r0 < M) *(float2*)(Cp + (size_t)r0 * HID + col) = make_float2(c[nt][0], c[nt][1]);
        if (r1 < M) *(float2*)(Cp + (size_t)r1 * HID + col) = make_float2(c[nt][2], c[nt][3]);
    }
}

// ---------------- tf32 output GEMM ----------------
__global__ void gemm_out_tf32(const float* __restrict__ A0, const float* __restrict__ A1,
                              const float* __restrict__ A2, const float* __restrict__ A3,
                              const float* __restrict__ B0, const float* __restrict__ B1,
                              const float* __restrict__ B2, const float* __restrict__ B3,
                              float* __restrict__ C, int M) {
    __shared__ uint32_t As[128 * 36];
    __shared__ uint32_t BsT[64 * 36];
    const int t = threadIdx.x;
    const int wid = t >> 5, lane = t & 31;
    const int g = lane >> 2, tg = lane & 3;
    const int rowBase = blockIdx.x * 128;
    const int colBase = blockIdx.y * 64;
    const int wrow = wid * 16;

    const float* Aps[4] = {A0, A1, A2, A3};
    const float* Bps[4] = {B0, B1, B2, B3};

    float c[8][4] = {};

    for (int m = 0; m < 4; ++m) {
        const float* __restrict__ Ap = Aps[m];
        const float* __restrict__ Bp = Bps[m];
        for (int kb = 0; kb < 2; ++kb) {
#pragma unroll
            for (int j = 0; j < 4; ++j) {
                int idx = t + j * 256;
                int r = idx >> 3, c4 = idx & 7;
                int gr = rowBase + r;
                if (gr >= M) gr = M - 1;
                float4 av = *(const float4*)(Ap + (size_t)gr * HID + kb * 32 + c4 * 4);
                uint32_t* d = &As[r * 36 + c4 * 4];
                d[0] = to_tf32(av.x); d[1] = to_tf32(av.y);
                d[2] = to_tf32(av.z); d[3] = to_tf32(av.w);
            }
#pragma unroll
            for (int j = 0; j < 8; ++j) {
                int idx = t + j * 256;
                int r = idx >> 6, cc = idx & 63;
                int col = colBase + cc;
                float v = (col < OUTF) ? Bp[(size_t)(kb * 32 + r) * OUTF + col] : 0.f;
                BsT[cc * 36 + r] = to_tf32(v);
            }
            __syncthreads();
#pragma unroll
            for (int ks = 0; ks < 4; ++ks) {
                int k0 = ks * 8;
                uint32_t a0 = As[(wrow + g) * 36 + k0 + tg];
                uint32_t a1 = As[(wrow + g + 8) * 36 + k0 + tg];
                uint32_t a2 = As[(wrow + g) * 36 + k0 + tg + 4];
                uint32_t a3 = As[(wrow + g + 8) * 36 + k0 + tg + 4];
#pragma unroll
                for (int nt = 0; nt < 8; ++nt) {
                    uint32_t b0 = BsT[(nt * 8 + g) * 36 + k0 + tg];
                    uint32_t b1 = BsT[(nt * 8 + g) * 36 + k0 + tg + 4];
                    mma_tf32(c[nt], a0, a1, a2, a3, b0, b1);
                }
            }
            __syncthreads();
        }
    }

    int r0 = rowBase + wrow + g, r1 = r0 + 8;
#pragma unroll
    for (int nt = 0; nt < 8; ++nt) {
        int col = colBase + nt * 8 + tg * 2;
        if (col < OUTF) {
            float bia = g_bsum2[col];
            if (r0 < M) C[(size_t)r0 * OUTF + col] = c[nt][0] + bia;
            if (r1 < M) C[(size_t)r1 * OUTF + col] = c[nt][2] + bia;
        }
        if (col + 1 < OUTF) {
            float bib = g_bsum2[col + 1];
            if (r0 < M) C[(size_t)r0 * OUTF + col + 1] = c[nt][1] + bib;
            if (r1 < M) C[(size_t)r1 * OUTF + col + 1] = c[nt][3] + bib;
        }
    }
}

// ---------------- host launcher ----------------
static inline void* sym(const void* s) {
    void* p = nullptr;
    cudaGetSymbolAddress(&p, s);
    return p;
}

extern "C" void kernel_launch(void* const* d_in, const int* in_sizes, int n_in,
                              void* d_out, int out_size) {
    // one-time stream/event setup (host-side resources only; identical GPU work every call)
    static cudaStream_t s1 = nullptr;
    static cudaEvent_t ev0 = nullptr, ev1 = nullptr;
    if (s1 == nullptr) {
        cudaStreamCreateWithFlags(&s1, cudaStreamNonBlocking);
        cudaEventCreateWithFlags(&ev0, cudaEventDisableTiming);
        cudaEventCreateWithFlags(&ev1, cudaEventDisableTiming);
    }

    const float* x_paper  = (const float*)d_in[0];
    const float* x_author = (const float*)d_in[1];
    const float* x_field  = (const float*)d_in[2];
    const int* ei_wr = (const int*)d_in[3];
    const int* ei_rw = (const int*)d_in[4];
    const int* ei_ci = (const int*)d_in[5];
    const int* ei_ht = (const int*)d_in[6];
    const int* ei_rh = (const int*)d_in[7];
    const int nE_wr = in_sizes[3] / 2;
    const int nE_rw = in_sizes[4] / 2;
    const int nE_ci = in_sizes[5] / 2;
    const int nE_ht = in_sizes[6] / 2;
    const int nE_rh = in_sizes[7] / 2;

    const float* wl1_wr = (const float*)d_in[8];
    const float* wr1_wr = (const float*)d_in[9];
    const float* b1_wr  = (const float*)d_in[10];
    const float* wl1_rw = (const float*)d_in[11];
    const float* wr1_rw = (const float*)d_in[12];
    const float* b1_rw  = (const float*)d_in[13];
    const float* wl1_ci = (const float*)d_in[14];
    const float* wr1_ci = (const float*)d_in[15];
    const float* b1_ci  = (const float*)d_in[16];
    const float* wl1_ht = (const float*)d_in[17];
    const float* wr1_ht = (const float*)d_in[18];
    const float* b1_ht  = (const float*)d_in[19];
    const float* wl1_rh = (const float*)d_in[20];
    const float* wr1_rh = (const float*)d_in[21];
    const float* b1_rh  = (const float*)d_in[22];
    const float* wl2_wr = (const float*)d_in[23];
    const float* wr2_wr = (const float*)d_in[24];
    const float* b2_wr  = (const float*)d_in[25];
    const float* wl2_ci = (const float*)d_in[26];
    const float* wr2_ci = (const float*)d_in[27];
    const float* b2_ci  = (const float*)d_in[28];
    const float* wl2_rh = (const float*)d_in[29];
    const float* wr2_rh = (const float*)d_in[30];
    const float* b2_rh  = (const float*)d_in[31];

    float* out = (float*)d_out;

    float* hs_wr = (float*)sym(g_hs_wr);
    float* hs_rw = (float*)sym(g_hs_rw);
    float* hs_ci = (float*)sym(g_hs_ci);
    float* hs_ht = (float*)sym(g_hs_ht);
    float* hs_rh = (float*)sym(g_hs_rh);
    float* selfP = (float*)sym(g_selfP);
    float* selfA = (float*)sym(g_selfA);
    float* selfF = (float*)sym(g_selfF);
    float* a1 = (float*)sym(g_a1);
    float* f1 = (float*)sym(g_f1);
    float* p1 = (float*)sym(g_p1);
    float* m2_wr = (float*)sym(g_m2_wr);
    float* m2_ci = (float*)sym(g_m2_ci);
    float* m2_rh = (float*)sym(g_m2_rh);
    int* cnt = (int*)sym(g_cnt);
    int* rp_rw = (int*)sym(g_rp_rw);
    int* rp_ht = (int*)sym(g_rp_ht);
    int* csr_rw = (int*)sym(g_csr_rw);
    int* csr_ht = (int*)sym(g_csr_ht);
    float* wsumP = (float*)sym(g_wsumP);
    float* w2sum = (float*)sym(g_w2sum);

    // ---- fork: side stream does weight prep + layer-1 GEMMs ----
    cudaEventRecord(ev0, 0);
    cudaStreamWaitEvent(s1, ev0, 0);

    prep_weights<<<(HID * OUTF + 255) / 256, 256, 0, s1>>>(
        wr1_wr, wr1_ci, wr1_rh, wr2_wr, wr2_ci, wr2_rh,
        b1_wr, b1_ci, b1_rh, b2_wr, b2_ci, b2_rh);

    const int gP = (NP + 127) / 128, gA = (NA + 127) / 128, gF = (NF + 127) / 128;
    {
        GemmBatch bp;
        bp.B[0] = wl1_rw; bp.C[0] = hs_rw;
        bp.B[1] = wl1_ci; bp.C[1] = hs_ci;
        bp.B[2] = wl1_ht; bp.C[2] = hs_ht;
        bp.B[3] = wsumP;  bp.C[3] = selfP;
        gemm_tf32_f128<<<dim3(gP, 4), 256, 0, s1>>>(x_paper, bp, NP);
        GemmBatch ba;
        ba.B[0] = wl1_wr; ba.C[0] = hs_wr;
        ba.B[1] = wr1_rw; ba.C[1] = selfA;
        ba.B[2] = wl1_wr; ba.C[2] = hs_wr;
        ba.B[3] = wl1_wr; ba.C[3] = hs_wr;
        gemm_tf32_f128<<<dim3(gA, 2), 256, 0, s1>>>(x_author, ba, NA);
        GemmBatch bf;
        bf.B[0] = wl1_rh; bf.C[0] = hs_rh;
        bf.B[1] = wr1_ht; bf.C[1] = selfF;
        bf.B[2] = wl1_rh; bf.C[2] = hs_rh;
        bf.B[3] = wl1_rh; bf.C[3] = hs_rh;
        gemm_tf32_f128<<<dim3(gF, 2), 256, 0, s1>>>(x_field, bf, NF);
    }
    cudaEventRecord(ev1, s1);

    // ---- default stream: CSR build ----
    cudaMemsetAsync(cnt, 0, sizeof(int) * CNT_TOT, 0);

    EJobs ep;
    ep.ei[0] = ei_wr; ep.E[0] = nE_wr;
    ep.ei[1] = ei_rw; ep.E[1] = nE_rw;
    ep.ei[2] = ei_ci; ep.E[2] = nE_ci;
    ep.ei[3] = ei_ht; ep.E[3] = nE_ht;
    ep.ei[4] = ei_rh; ep.E[4] = nE_rh;
    ep.bs[0] = 0;
    for (int i = 0; i < 5; ++i) ep.bs[i + 1] = ep.bs[i] + (ep.E[i] + 255) / 256;

    k_count_all<<<ep.bs[5], 256>>>(ep);
    k_blocksum_all<<<dim3((NP + 1023) / 1024, 5), 256>>>();
    k_scan_bsums_all<<<5, 256>>>();
    k_scan_write_all<<<dim3((NP + 1023) / 1024, 5), 256>>>();
    k_fill_all<<<ep.bs[5], 256>>>(ep);

    // ---- join ----
    cudaStreamWaitEvent(0, ev1, 0);

    // ---- layer-1 fused pulls (mean + self + bias + relu) ----
    k_layer1_paper<<<(NP * 16 + 255) / 256, 256>>>();
    k_layer1_af<<<(NA * 16 + 255) / 256, 256>>>(hs_rw, rp_rw, csr_rw, selfA, b1_rw, a1, NA);
    k_layer1_af<<<(NF * 16 + 255) / 256, 256>>>(hs_ht, rp_ht, csr_ht, selfF, b1_ht, f1, NF);

    // ---- layer-2 pulls (one kernel, CSRs reused) ----
    k_layer2_pulls<<<(NP * 16 + 255) / 256, 256>>>();

    // ---- output GEMM (tf32) ----
    dim3 g2(gP, (OUTF + 63) / 64);
    gemm_out_tf32<<<g2, 256>>>(m2_wr, m2_ci, m2_rh, p1,
                               wl2_wr, wl2_ci, wl2_rh, w2sum,
                               out, NP);
}

// round 5
// speedup vs baseline: 1.7664x; 1.0301x over previous
#include <cuda_runtime.h>
#include <cstdint>

#define NP 100000
#define NA 100000
#define NF 50000
#define FIN 128
#define HID 64
#define OUTF 349

#define E_WR 1000000
#define E_RW 1000000
#define E_CI 2000000
#define E_HT 1000000
#define E_RH 1000000

#define CNT_TOT (NP + NA + NP + NF + NP)   // 450000

// ---------------- scratch (device globals; no runtime allocation) ----------------
static __device__ __align__(256) float g_hs_wr[NA * HID];
static __device__ __align__(256) float g_hs_rw[NP * HID];
static __device__ __align__(256) float g_hs_ci[NP * HID];
static __device__ __align__(256) float g_hs_ht[NP * HID];
static __device__ __align__(256) float g_hs_rh[NF * HID];
static __device__ __align__(256) float g_selfP[NP * HID];
static __device__ __align__(256) float g_selfA[NA * HID];
static __device__ __align__(256) float g_selfF[NF * HID];
static __device__ __align__(256) float g_p1[NP * HID];
static __device__ __align__(256) float g_a1[NA * HID];
static __device__ __align__(256) float g_f1[NF * HID];
static __device__ __align__(256) float g_m2_wr[NP * HID];
static __device__ __align__(256) float g_m2_ci[NP * HID];
static __device__ __align__(256) float g_m2_rh[NP * HID];
// CSR machinery
static __device__ int g_cnt[CNT_TOT];
static __device__ int g_fl[CNT_TOT];
static __device__ int g_rp_wr[NP + 1], g_rp_rw[NA + 1], g_rp_ci[NP + 1], g_rp_ht[NF + 1], g_rp_rh[NP + 1];
static __device__ int g_csr_wr[E_WR], g_csr_rw[E_RW], g_csr_ci[E_CI], g_csr_ht[E_HT], g_csr_rh[E_RH];
static __device__ int g_bsumA[5][128];
// summed weights / biases
static __device__ __align__(256) float g_wsumP[FIN * HID];
static __device__ __align__(256) float g_w2sum[HID * OUTF];
static __device__ __align__(256) float g_bsum1[HID];
static __device__ __align__(256) float g_bsum2[OUTF];

__constant__ int c_n[5] = {NP, NA, NP, NF, NP};
__constant__ int c_off[5] = {0, NP, NP + NA, NP + NA + NP, NP + NA + NP + NF};

__device__ __forceinline__ int* rp_of(int ty) {
    switch (ty) {
        case 0: return g_rp_wr;
        case 1: return g_rp_rw;
        case 2: return g_rp_ci;
        case 3: return g_rp_ht;
        default: return g_rp_rh;
    }
}
__device__ __forceinline__ int* csr_of(int ty) {
    switch (ty) {
        case 0: return g_csr_wr;
        case 1: return g_csr_rw;
        case 2: return g_csr_ci;
        case 3: return g_csr_ht;
        default: return g_csr_rh;
    }
}

// ---------------- tf32 helpers ----------------
__device__ __forceinline__ uint32_t to_tf32(float x) {
    uint32_t r;
    asm("cvt.rna.tf32.f32 %0, %1;" : "=r"(r) : "f"(x));
    return r;
}

__device__ __forceinline__ void mma_tf32(float c[4], uint32_t a0, uint32_t a1,
                                         uint32_t a2, uint32_t a3,
                                         uint32_t b0, uint32_t b1) {
    asm volatile("mma.sync.aligned.m16n8k8.row.col.f32.tf32.tf32.f32 "
                 "{%0,%1,%2,%3}, {%4,%5,%6,%7}, {%8,%9}, {%0,%1,%2,%3};"
                 : "+f"(c[0]), "+f"(c[1]), "+f"(c[2]), "+f"(c[3])
                 : "r"(a0), "r"(a1), "r"(a2), "r"(a3), "r"(b0), "r"(b1));
}

// ---------------- weight/bias prep ----------------
__global__ void prep_weights(const float* __restrict__ wr1a, const float* __restrict__ wr1b,
                             const float* __restrict__ wr1c,
                             const float* __restrict__ wr2a, const float* __restrict__ wr2b,
                             const float* __restrict__ wr2c,
                             const float* __restrict__ b1a, const float* __restrict__ b1b,
                             const float* __restrict__ b1c,
                             const float* __restrict__ b2a, const float* __restrict__ b2b,
                             const float* __restrict__ b2c) {
    int i = blockIdx.x * blockDim.x + threadIdx.x;
    if (i < FIN * HID) g_wsumP[i] = wr1a[i] + wr1b[i] + wr1c[i];
    if (i < HID * OUTF) g_w2sum[i] = wr2a[i] + wr2b[i] + wr2c[i];
    if (i < HID) g_bsum1[i] = b1a[i] + b1b[i] + b1c[i];
    if (i < OUTF) g_bsum2[i] = b2a[i] + b2b[i] + b2c[i];
}

// ---------------- CSR build (batched over all 5 edge types) ----------------
struct EJobs {
    const int* ei[5];
    int E[5];
    int bs[6];
};

__global__ void k_count_all(EJobs ep) {
    int b = blockIdx.x;
    int ty = 0;
    while (b >= ep.bs[ty + 1]) ++ty;
    int e = (b - ep.bs[ty]) * 256 + threadIdx.x;
    if (e >= ep.E[ty]) return;
    int d = __ldg(ep.ei[ty] + ep.E[ty] + e);
    atomicAdd(g_cnt + c_off[ty] + d, 1);
}

__global__ void k_blocksum_all() {
    __shared__ int s[256];
    int ty = blockIdx.y;
    int n = c_n[ty];
    int base = blockIdx.x * 1024;
    if (base >= n) { if (threadIdx.x == 0) g_bsumA[ty][blockIdx.x] = 0; return; }
    const int* c = g_cnt + c_off[ty];
    int t = threadIdx.x;
    int v = 0;
#pragma unroll
    for (int j = 0; j < 4; ++j) {
        int i = base + t * 4 + j;
        if (i < n) v += c[i];
    }
    s[t] = v;
    __syncthreads();
    for (int o = 128; o > 0; o >>= 1) {
        if (t < o) s[t] += s[t + o];
        __syncthreads();
    }
    if (t == 0) g_bsumA[ty][blockIdx.x] = s[0];
}

__global__ void k_scan_bsums_all() {
    __shared__ int s[256];
    int ty = blockIdx.x;
    int n = c_n[ty];
    int nb = (n + 1023) / 1024;
    int t = threadIdx.x;
    int v = (t < nb) ? g_bsumA[ty][t] : 0;
    s[t] = v;
    __syncthreads();
    for (int o = 1; o < 256; o <<= 1) {
        int x = (t >= o) ? s[t - o] : 0;
        __syncthreads();
        s[t] += x;
        __syncthreads();
    }
    if (t < nb) g_bsumA[ty][t] = s[t] - v;
    if (t == 0) rp_of(ty)[n] = s[255];
}

__global__ void k_scan_write_all() {
    __shared__ int s[256];
    int ty = blockIdx.y;
    int n = c_n[ty];
    int base = blockIdx.x * 1024;
    if (base >= n) return;
    const int* c = g_cnt + c_off[ty];
    int* rowptr = rp_of(ty);
    int* fill = g_fl + c_off[ty];
    int t = threadIdx.x;
    int loc[4];
    int v = 0;
#pragma unroll
    for (int j = 0; j < 4; ++j) {
        int i = base + t * 4 + j;
        loc[j] = v;
        v += (i < n) ? c[i] : 0;
    }
    s[t] = v;
    __syncthreads();
    for (int o = 1; o < 256; o <<= 1) {
        int x = (t >= o) ? s[t - o] : 0;
        __syncthreads();
        s[t] += x;
        __syncthreads();
    }
    int ex = s[t] - v;
    int off = g_bsumA[ty][blockIdx.x] + ex;
#pragma unroll
    for (int j = 0; j < 4; ++j) {
        int i = base + t * 4 + j;
        if (i < n) {
            int r = off + loc[j];
            rowptr[i] = r;
            fill[i] = r;
        }
    }
}

__global__ void k_fill_all(EJobs ep) {
    int b = blockIdx.x;
    int ty = 0;
    while (b >= ep.bs[ty + 1]) ++ty;
    int e = (b - ep.bs[ty]) * 256 + threadIdx.x;
    if (e >= ep.E[ty]) return;
    int s = __ldg(ep.ei[ty] + e);
    int d = __ldg(ep.ei[ty] + ep.E[ty] + e);
    int pos = atomicAdd(g_fl + c_off[ty] + d, 1);
    csr_of(ty)[pos] = s;
}

// ---------------- pull primitive: mean over neighbors, unroll-4 for MLP ----------------
__device__ __forceinline__ float4 pull_mean(const float* __restrict__ feat,
                                            const int* __restrict__ rowptr,
                                            const int* __restrict__ csr,
                                            int g, int lane) {
    int beg = __ldg(rowptr + g), end = __ldg(rowptr + g + 1);
    float4 acc = make_float4(0.f, 0.f, 0.f, 0.f);
    int j = beg;
    for (; j + 3 < end; j += 4) {
        int s0 = __ldg(csr + j);
        int s1 = __ldg(csr + j + 1);
        int s2 = __ldg(csr + j + 2);
        int s3 = __ldg(csr + j + 3);
        float4 v0 = *(const float4*)(feat + (size_t)s0 * HID + lane * 4);
        float4 v1 = *(const float4*)(feat + (size_t)s1 * HID + lane * 4);
        float4 v2 = *(const float4*)(feat + (size_t)s2 * HID + lane * 4);
        float4 v3 = *(const float4*)(feat + (size_t)s3 * HID + lane * 4);
        acc.x += (v0.x + v1.x) + (v2.x + v3.x);
        acc.y += (v0.y + v1.y) + (v2.y + v3.y);
        acc.z += (v0.z + v1.z) + (v2.z + v3.z);
        acc.w += (v0.w + v1.w) + (v2.w + v3.w);
    }
    for (; j < end; ++j) {
        int s0 = __ldg(csr + j);
        float4 v0 = *(const float4*)(feat + (size_t)s0 * HID + lane * 4);
        acc.x += v0.x; acc.y += v0.y; acc.z += v0.z; acc.w += v0.w;
    }
    float inv = 1.f / fmaxf((float)(end - beg), 1.f);
    acc.x *= inv; acc.y *= inv; acc.z *= inv; acc.w *= inv;
    return acc;
}

// layer-1 paper: pull 3 edge types + self + bias + relu -> p1
__global__ void k_layer1_paper() {
    int t = blockIdx.x * blockDim.x + threadIdx.x;
    if (t >= NP * 16) return;
    int g = t >> 4, lane = t & 15;
    float4 aw = pull_mean(g_hs_wr, g_rp_wr, g_csr_wr, g, lane);
    float4 ac = pull_mean(g_hs_ci, g_rp_ci, g_csr_ci, g, lane);
    float4 ar = pull_mean(g_hs_rh, g_rp_rh, g_csr_rh, g, lane);
    float4 s = ((const float4*)g_selfP)[t];
    float4 b = ((const float4*)g_bsum1)[lane];
    float4 o;
    o.x = fmaxf(s.x + b.x + aw.x + ac.x + ar.x, 0.f);
    o.y = fmaxf(s.y + b.y + aw.y + ac.y + ar.y, 0.f);
    o.z = fmaxf(s.z + b.z + aw.z + ac.z + ar.z, 0.f);
    o.w = fmaxf(s.w + b.w + aw.w + ac.w + ar.w, 0.f);
    ((float4*)g_p1)[t] = o;
}

// layer-1 author/field: pull 1 edge type + self + bias + relu -> out
__global__ void k_layer1_af(const float* __restrict__ feat, const int* __restrict__ rowptr,
                            const int* __restrict__ csr, const float* __restrict__ selfX,
                            const float* __restrict__ bias, float* __restrict__ out, int n) {
    int t = blockIdx.x * blockDim.x + threadIdx.x;
    if (t >= n * 16) return;
    int g = t >> 4, lane = t & 15;
    float4 a = pull_mean(feat, rowptr, csr, g, lane);
    float4 s = ((const float4*)selfX)[t];
    float4 b = ((const float4*)bias)[lane];
    float4 o;
    o.x = fmaxf(s.x + b.x + a.x, 0.f);
    o.y = fmaxf(s.y + b.y + a.y, 0.f);
    o.z = fmaxf(s.z + b.z + a.z, 0.f);
    o.w = fmaxf(s.w + b.w + a.w, 0.f);
    ((float4*)out)[t] = o;
}

// layer-2: three pulls into m2 buffers in one kernel
__global__ void k_layer2_pulls() {
    int t = blockIdx.x * blockDim.x + threadIdx.x;
    if (t >= NP * 16) return;
    int g = t >> 4, lane = t & 15;
    ((float4*)g_m2_wr)[t] = pull_mean(g_a1, g_rp_wr, g_csr_wr, g, lane);
    ((float4*)g_m2_ci)[t] = pull_mean(g_p1, g_rp_ci, g_csr_ci, g, lane);
    ((float4*)g_m2_rh)[t] = pull_mean(g_f1, g_rp_rh, g_csr_rh, g, lane);
}

// ---------------- tf32 GEMM: C[M,64] = A[M,128] @ B[128,64], batched ----------------
struct GemmBatch {
    const float* B[4];
    float* C[4];
};

__global__ void __launch_bounds__(256, 4)
gemm_tf32_f128(const float* __restrict__ A, GemmBatch p, int M) {
    __shared__ uint32_t As[128 * 36];
    __shared__ uint32_t BsT[64 * 36];
    const float* __restrict__ Bp = p.B[blockIdx.y];
    float* __restrict__ Cp = p.C[blockIdx.y];
    const int t = threadIdx.x;
    const int wid = t >> 5, lane = t & 31;
    const int g = lane >> 2, tg = lane & 3;
    const int rowBase = blockIdx.x * 128;
    const int wrow = wid * 16;

    float c[8][4] = {};

    for (int kb = 0; kb < 4; ++kb) {
#pragma unroll
        for (int j = 0; j < 4; ++j) {
            int idx = t + j * 256;
            int r = idx >> 3, c4 = idx & 7;
            int gr = rowBase + r;
            if (gr >= M) gr = M - 1;
            float4 av = *(const float4*)(A + (size_t)gr * FIN + kb * 32 + c4 * 4);
            uint32_t* d = &As[r * 36 + c4 * 4];
            d[0] = to_tf32(av.x); d[1] = to_tf32(av.y);
            d[2] = to_tf32(av.z); d[3] = to_tf32(av.w);
        }
#pragma unroll
        for (int j = 0; j < 2; ++j) {
            int idx = t + j * 256;
            int r = idx >> 4, c4 = idx & 15;
            float4 bv = *(const float4*)(Bp + (size_t)(kb * 32 + r) * HID + c4 * 4);
            BsT[(c4 * 4 + 0) * 36 + r] = to_tf32(bv.x);
            BsT[(c4 * 4 + 1) * 36 + r] = to_tf32(bv.y);
            BsT[(c4 * 4 + 2) * 36 + r] = to_tf32(bv.z);
            BsT[(c4 * 4 + 3) * 36 + r] = to_tf32(bv.w);
        }
        __syncthreads();
#pragma unroll
        for (int ks = 0; ks < 4; ++ks) {
            int k0 = ks * 8;
            uint32_t a0 = As[(wrow + g) * 36 + k0 + tg];
            uint32_t a1 = As[(wrow + g + 8) * 36 + k0 + tg];
            uint32_t a2 = As[(wrow + g) * 36 + k0 + tg + 4];
            uint32_t a3 = As[(wrow + g + 8) * 36 + k0 + tg + 4];
#pragma unroll
            for (int nt = 0; nt < 8; ++nt) {
                uint32_t b0 = BsT[(nt * 8 + g) * 36 + k0 + tg];
                uint32_t b1 = BsT[(nt * 8 + g) * 36 + k0 + tg + 4];
                mma_tf32(c[nt], a0, a1, a2, a3, b0, b1);
            }
        }
        __syncthreads();
    }

    int r0 = rowBase + wrow + g, r1 = r0 + 8;
#pragma unroll
    for (int nt = 0; nt < 8; ++nt) {
        int col = nt * 8 + tg * 2;
        if (r0 < M) *(float2*)(Cp + (size_t)r0 * HID + col) = make_float2(c[nt][0], c[nt][1]);
        if (r1 < M) *(float2*)(Cp + (size_t)r1 * HID + col) = make_float2(c[nt][2], c[nt][3]);
    }
}

// ---------------- tf32 output GEMM ----------------
__global__ void __launch_bounds__(256, 4)
gemm_out_tf32(const float* __restrict__ A0, const float* __restrict__ A1,
              const float* __restrict__ A2, const float* __restrict__ A3,
              const float* __restrict__ B0, const float* __restrict__ B1,
              const float* __restrict__ B2, const float* __restrict__ B3,
              float* __restrict__ C, int M) {
    __shared__ uint32_t As[128 * 36];
    __shared__ uint32_t BsT[64 * 36];
    const int t = threadIdx.x;
    const int wid = t >> 5, lane = t & 31;
    const int g = lane >> 2, tg = lane & 3;
    const int rowBase = blockIdx.x * 128;
    const int colBase = blockIdx.y * 64;
    const int wrow = wid * 16;

    const float* Aps[4] = {A0, A1, A2, A3};
    const float* Bps[4] = {B0, B1, B2, B3};

    float c[8][4] = {};

    for (int m = 0; m < 4; ++m) {
        const float* __restrict__ Ap = Aps[m];
        const float* __restrict__ Bp = Bps[m];
        for (int kb = 0; kb < 2; ++kb) {
#pragma unroll
            for (int j = 0; j < 4; ++j) {
                int idx = t + j * 256;
                int r = idx >> 3, c4 = idx & 7;
                int gr = rowBase + r;
                if (gr >= M) gr = M - 1;
                float4 av = *(const float4*)(Ap + (size_t)gr * HID + kb * 32 + c4 * 4);
                uint32_t* d = &As[r * 36 + c4 * 4];
                d[0] = to_tf32(av.x); d[1] = to_tf32(av.y);
                d[2] = to_tf32(av.z); d[3] = to_tf32(av.w);
            }
#pragma unroll
            for (int j = 0; j < 8; ++j) {
                int idx = t + j * 256;
                int r = idx >> 6, cc = idx & 63;
                int col = colBase + cc;
                float v = (col < OUTF) ? Bp[(size_t)(kb * 32 + r) * OUTF + col] : 0.f;
                BsT[cc * 36 + r] = to_tf32(v);
            }
            __syncthreads();
#pragma unroll
            for (int ks = 0; ks < 4; ++ks) {
                int k0 = ks * 8;
                uint32_t a0 = As[(wrow + g) * 36 + k0 + tg];
                uint32_t a1 = As[(wrow + g + 8) * 36 + k0 + tg];
                uint32_t a2 = As[(wrow + g) * 36 + k0 + tg + 4];
                uint32_t a3 = As[(wrow + g + 8) * 36 + k0 + tg + 4];
#pragma unroll
                for (int nt = 0; nt < 8; ++nt) {
                    uint32_t b0 = BsT[(nt * 8 + g) * 36 + k0 + tg];
                    uint32_t b1 = BsT[(nt * 8 + g) * 36 + k0 + tg + 4];
                    mma_tf32(c[nt], a0, a1, a2, a3, b0, b1);
                }
            }
            __syncthreads();
        }
    }

    int r0 = rowBase + wrow + g, r1 = r0 + 8;
#pragma unroll
    for (int nt = 0; nt < 8; ++nt) {
        int col = colBase + nt * 8 + tg * 2;
        if (col < OUTF) {
            float bia = g_bsum2[col];
            if (r0 < M) C[(size_t)r0 * OUTF + col] = c[nt][0] + bia;
            if (r1 < M) C[(size_t)r1 * OUTF + col] = c[nt][2] + bia;
        }
        if (col + 1 < OUTF) {
            float bib = g_bsum2[col + 1];
            if (r0 < M) C[(size_t)r0 * OUTF + col + 1] = c[nt][1] + bib;
            if (r1 < M) C[(size_t)r1 * OUTF + col + 1] = c[nt][3] + bib;
        }
    }
}

// ---------------- host launcher ----------------
static inline void* sym(const void* s) {
    void* p = nullptr;
    cudaGetSymbolAddress(&p, s);
    return p;
}

extern "C" void kernel_launch(void* const* d_in, const int* in_sizes, int n_in,
                              void* d_out, int out_size) {
    static cudaStream_t s1 = nullptr;
    static cudaEvent_t ev0 = nullptr, ev1 = nullptr;
    if (s1 == nullptr) {
        cudaStreamCreateWithFlags(&s1, cudaStreamNonBlocking);
        cudaEventCreateWithFlags(&ev0, cudaEventDisableTiming);
        cudaEventCreateWithFlags(&ev1, cudaEventDisableTiming);
    }

    const float* x_paper  = (const float*)d_in[0];
    const float* x_author = (const float*)d_in[1];
    const float* x_field  = (const float*)d_in[2];
    const int* ei_wr = (const int*)d_in[3];
    const int* ei_rw = (const int*)d_in[4];
    const int* ei_ci = (const int*)d_in[5];
    const int* ei_ht = (const int*)d_in[6];
    const int* ei_rh = (const int*)d_in[7];
    const int nE_wr = in_sizes[3] / 2;
    const int nE_rw = in_sizes[4] / 2;
    const int nE_ci = in_sizes[5] / 2;
    const int nE_ht = in_sizes[6] / 2;
    const int nE_rh = in_sizes[7] / 2;

    const float* wl1_wr = (const float*)d_in[8];
    const float* wr1_wr = (const float*)d_in[9];
    const float* b1_wr  = (const float*)d_in[10];
    const float* wl1_rw = (const float*)d_in[11];
    const float* wr1_rw = (const float*)d_in[12];
    const float* b1_rw  = (const float*)d_in[13];
    const float* wl1_ci = (const float*)d_in[14];
    const float* wr1_ci = (const float*)d_in[15];
    const float* b1_ci  = (const float*)d_in[16];
    const float* wl1_ht = (const float*)d_in[17];
    const float* wr1_ht = (const float*)d_in[18];
    const float* b1_ht  = (const float*)d_in[19];
    const float* wl1_rh = (const float*)d_in[20];
    const float* wr1_rh = (const float*)d_in[21];
    const float* b1_rh  = (const float*)d_in[22];
    const float* wl2_wr = (const float*)d_in[23];
    const float* wr2_wr = (const float*)d_in[24];
    const float* b2_wr  = (const float*)d_in[25];
    const float* wl2_ci = (const float*)d_in[26];
    const float* wr2_ci = (const float*)d_in[27];
    const float* b2_ci  = (const float*)d_in[28];
    const float* wl2_rh = (const float*)d_in[29];
    const float* wr2_rh = (const float*)d_in[30];
    const float* b2_rh  = (const float*)d_in[31];

    float* out = (float*)d_out;

    float* hs_wr = (float*)sym(g_hs_wr);
    float* hs_rw = (float*)sym(g_hs_rw);
    float* hs_ci = (float*)sym(g_hs_ci);
    float* hs_ht = (float*)sym(g_hs_ht);
    float* hs_rh = (float*)sym(g_hs_rh);
    float* selfP = (float*)sym(g_selfP);
    float* selfA = (float*)sym(g_selfA);
    float* selfF = (float*)sym(g_selfF);
    float* a1 = (float*)sym(g_a1);
    float* f1 = (float*)sym(g_f1);
    float* p1 = (float*)sym(g_p1);
    float* m2_wr = (float*)sym(g_m2_wr);
    float* m2_ci = (float*)sym(g_m2_ci);
    float* m2_rh = (float*)sym(g_m2_rh);
    int* cnt = (int*)sym(g_cnt);
    int* rp_rw = (int*)sym(g_rp_rw);
    int* rp_ht = (int*)sym(g_rp_ht);
    int* csr_rw = (int*)sym(g_csr_rw);
    int* csr_ht = (int*)sym(g_csr_ht);
    float* wsumP = (float*)sym(g_wsumP);
    float* w2sum = (float*)sym(g_w2sum);

    // ---- fork: side stream does weight prep + layer-1 GEMMs ----
    cudaEventRecord(ev0, 0);
    cudaStreamWaitEvent(s1, ev0, 0);

    prep_weights<<<(HID * OUTF + 255) / 256, 256, 0, s1>>>(
        wr1_wr, wr1_ci, wr1_rh, wr2_wr, wr2_ci, wr2_rh,
        b1_wr, b1_ci, b1_rh, b2_wr, b2_ci, b2_rh);

    const int gP = (NP + 127) / 128, gA = (NA + 127) / 128, gF = (NF + 127) / 128;
    {
        GemmBatch bp;
        bp.B[0] = wl1_rw; bp.C[0] = hs_rw;
        bp.B[1] = wl1_ci; bp.C[1] = hs_ci;
        bp.B[2] = wl1_ht; bp.C[2] = hs_ht;
        bp.B[3] = wsumP;  bp.C[3] = selfP;
        gemm_tf32_f128<<<dim3(gP, 4), 256, 0, s1>>>(x_paper, bp, NP);
        GemmBatch ba;
        ba.B[0] = wl1_wr; ba.C[0] = hs_wr;
        ba.B[1] = wr1_rw; ba.C[1] = selfA;
        ba.B[2] = wl1_wr; ba.C[2] = hs_wr;
        ba.B[3] = wl1_wr; ba.C[3] = hs_wr;
        gemm_tf32_f128<<<dim3(gA, 2), 256, 0, s1>>>(x_author, ba, NA);
        GemmBatch bf;
        bf.B[0] = wl1_rh; bf.C[0] = hs_rh;
        bf.B[1] = wr1_ht; bf.C[1] = selfF;
        bf.B[2] = wl1_rh; bf.C[2] = hs_rh;
        bf.B[3] = wl1_rh; bf.C[3] = hs_rh;
        gemm_tf32_f128<<<dim3(gF, 2), 256, 0, s1>>>(x_field, bf, NF);
    }
    cudaEventRecord(ev1, s1);

    // ---- default stream: CSR build ----
    cudaMemsetAsync(cnt, 0, sizeof(int) * CNT_TOT, 0);

    EJobs ep;
    ep.ei[0] = ei_wr; ep.E[0] = nE_wr;
    ep.ei[1] = ei_rw; ep.E[1] = nE_rw;
    ep.ei[2] = ei_ci; ep.E[2] = nE_ci;
    ep.ei[3] = ei_ht; ep.E[3] = nE_ht;
    ep.ei[4] = ei_rh; ep.E[4] = nE_rh;
    ep.bs[0] = 0;
    for (int i = 0; i < 5; ++i) ep.bs[i + 1] = ep.bs[i] + (ep.E[i] + 255) / 256;

    k_count_all<<<ep.bs[5], 256>>>(ep);
    k_blocksum_all<<<dim3((NP + 1023) / 1024, 5), 256>>>();
    k_scan_bsums_all<<<5, 256>>>();
    k_scan_write_all<<<dim3((NP + 1023) / 1024, 5), 256>>>();
    k_fill_all<<<ep.bs[5], 256>>>(ep);

    // ---- join ----
    cudaStreamWaitEvent(0, ev1, 0);

    // ---- layer-1 fused pulls (mean + self + bias + relu) ----
    k_layer1_paper<<<(NP * 16 + 255) / 256, 256>>>();
    k_layer1_af<<<(NA * 16 + 255) / 256, 256>>>(hs_rw, rp_rw, csr_rw, selfA, b1_rw, a1, NA);
    k_layer1_af<<<(NF * 16 + 255) / 256, 256>>>(hs_ht, rp_ht, csr_ht, selfF, b1_ht, f1, NF);

    // ---- layer-2 pulls (one kernel, CSRs reused) ----
    k_layer2_pulls<<<(NP * 16 + 255) / 256, 256>>>();

    // ---- output GEMM (tf32) ----
    dim3 g2(gP, (OUTF + 63) / 64);
    gemm_out_tf32<<<g2, 256>>>(m2_wr, m2_ci, m2_rh, p1,
                               wl2_wr, wl2_ci, wl2_rh, w2sum,
                               out, NP);
}

// round 6
// speedup vs baseline: 1.8095x; 1.0244x over previous
#include <cuda_runtime.h>
#include <cuda_fp16.h>
#include <cstdint>

#define NP 100000
#define NA 100000
#define NF 50000
#define FIN 128
#define HID 64
#define OUTF 349

#define E_WR 1000000
#define E_RW 1000000
#define E_CI 2000000
#define E_HT 1000000
#define E_RH 1000000

#define CNT_TOT (NP + NA + NP + NF + NP)   // 450000

// ---------------- scratch (device globals; no runtime allocation) ----------------
// fp16 transformed features + layer-1 outputs (pull sources)
static __device__ __align__(256) __half g_hs_wr[NA * HID];
static __device__ __align__(256) __half g_hs_rw[NP * HID];
static __device__ __align__(256) __half g_hs_ci[NP * HID];
static __device__ __align__(256) __half g_hs_ht[NP * HID];
static __device__ __align__(256) __half g_hs_rh[NF * HID];
static __device__ __align__(256) __half g_selfP[NP * HID];
static __device__ __align__(256) __half g_selfA[NA * HID];
static __device__ __align__(256) __half g_selfF[NF * HID];
static __device__ __align__(256) __half g_p1h[NP * HID];
static __device__ __align__(256) __half g_a1h[NA * HID];
static __device__ __align__(256) __half g_f1h[NF * HID];
// fp32 buffers feeding the output GEMM
static __device__ __align__(256) float g_p1[NP * HID];
static __device__ __align__(256) float g_m2_wr[NP * HID];
static __device__ __align__(256) float g_m2_ci[NP * HID];
static __device__ __align__(256) float g_m2_rh[NP * HID];
// CSR machinery
static __device__ int g_cnt[CNT_TOT];
static __device__ int g_fl[CNT_TOT];
static __device__ int g_rp_wr[NP + 1], g_rp_rw[NA + 1], g_rp_ci[NP + 1], g_rp_ht[NF + 1], g_rp_rh[NP + 1];
static __device__ int g_csr_wr[E_WR], g_csr_rw[E_RW], g_csr_ci[E_CI], g_csr_ht[E_HT], g_csr_rh[E_RH];
static __device__ int g_bsumA[5][128];
// summed weights / biases
static __device__ __align__(256) float g_wsumP[FIN * HID];
static __device__ __align__(256) float g_w2sum[HID * OUTF];
static __device__ __align__(256) float g_bsum1[HID];
static __device__ __align__(256) float g_bsum2[OUTF];

__constant__ int c_n[5] = {NP, NA, NP, NF, NP};
__constant__ int c_off[5] = {0, NP, NP + NA, NP + NA + NP, NP + NA + NP + NF};

__device__ __forceinline__ int* rp_of(int ty) {
    switch (ty) {
        case 0: return g_rp_wr;
        case 1: return g_rp_rw;
        case 2: return g_rp_ci;
        case 3: return g_rp_ht;
        default: return g_rp_rh;
    }
}
__device__ __forceinline__ int* csr_of(int ty) {
    switch (ty) {
        case 0: return g_csr_wr;
        case 1: return g_csr_rw;
        case 2: return g_csr_ci;
        case 3: return g_csr_ht;
        default: return g_csr_rh;
    }
}

// ---------------- tf32 helpers ----------------
__device__ __forceinline__ uint32_t to_tf32(float x) {
    uint32_t r;
    asm("cvt.rna.tf32.f32 %0, %1;" : "=r"(r) : "f"(x));
    return r;
}

__device__ __forceinline__ void mma_tf32(float c[4], uint32_t a0, uint32_t a1,
                                         uint32_t a2, uint32_t a3,
                                         uint32_t b0, uint32_t b1) {
    asm volatile("mma.sync.aligned.m16n8k8.row.col.f32.tf32.tf32.f32 "
                 "{%0,%1,%2,%3}, {%4,%5,%6,%7}, {%8,%9}, {%0,%1,%2,%3};"
                 : "+f"(c[0]), "+f"(c[1]), "+f"(c[2]), "+f"(c[3])
                 : "r"(a0), "r"(a1), "r"(a2), "r"(a3), "r"(b0), "r"(b1));
}

// ---------------- weight/bias prep ----------------
__global__ void prep_weights(const float* __restrict__ wr1a, const float* __restrict__ wr1b,
                             const float* __restrict__ wr1c,
                             const float* __restrict__ wr2a, const float* __restrict__ wr2b,
                             const float* __restrict__ wr2c,
                             const float* __restrict__ b1a, const float* __restrict__ b1b,
                             const float* __restrict__ b1c,
                             const float* __restrict__ b2a, const float* __restrict__ b2b,
                             const float* __restrict__ b2c) {
    int i = blockIdx.x * blockDim.x + threadIdx.x;
    if (i < FIN * HID) g_wsumP[i] = wr1a[i] + wr1b[i] + wr1c[i];
    if (i < HID * OUTF) g_w2sum[i] = wr2a[i] + wr2b[i] + wr2c[i];
    if (i < HID) g_bsum1[i] = b1a[i] + b1b[i] + b1c[i];
    if (i < OUTF) g_bsum2[i] = b2a[i] + b2b[i] + b2c[i];
}

// ---------------- CSR build (batched over all 5 edge types) ----------------
struct EJobs {
    const int* ei[5];
    int E[5];
    int bs[6];
};

__global__ void k_count_all(EJobs ep) {
    int b = blockIdx.x;
    int ty = 0;
    while (b >= ep.bs[ty + 1]) ++ty;
    int e = (b - ep.bs[ty]) * 256 + threadIdx.x;
    if (e >= ep.E[ty]) return;
    int d = __ldg(ep.ei[ty] + ep.E[ty] + e);
    atomicAdd(g_cnt + c_off[ty] + d, 1);
}

__global__ void k_blocksum_all() {
    __shared__ int s[256];
    int ty = blockIdx.y;
    int n = c_n[ty];
    int base = blockIdx.x * 1024;
    if (base >= n) { if (threadIdx.x == 0) g_bsumA[ty][blockIdx.x] = 0; return; }
    const int* c = g_cnt + c_off[ty];
    int t = threadIdx.x;
    int v = 0;
#pragma unroll
    for (int j = 0; j < 4; ++j) {
        int i = base + t * 4 + j;
        if (i < n) v += c[i];
    }
    s[t] = v;
    __syncthreads();
    for (int o = 128; o > 0; o >>= 1) {
        if (t < o) s[t] += s[t + o];
        __syncthreads();
    }
    if (t == 0) g_bsumA[ty][blockIdx.x] = s[0];
}

__global__ void k_scan_bsums_all() {
    __shared__ int s[256];
    int ty = blockIdx.x;
    int n = c_n[ty];
    int nb = (n + 1023) / 1024;
    int t = threadIdx.x;
    int v = (t < nb) ? g_bsumA[ty][t] : 0;
    s[t] = v;
    __syncthreads();
    for (int o = 1; o < 256; o <<= 1) {
        int x = (t >= o) ? s[t - o] : 0;
        __syncthreads();
        s[t] += x;
        __syncthreads();
    }
    if (t < nb) g_bsumA[ty][t] = s[t] - v;
    if (t == 0) rp_of(ty)[n] = s[255];
}

__global__ void k_scan_write_all() {
    __shared__ int s[256];
    int ty = blockIdx.y;
    int n = c_n[ty];
    int base = blockIdx.x * 1024;
    if (base >= n) return;
    const int* c = g_cnt + c_off[ty];
    int* rowptr = rp_of(ty);
    int* fill = g_fl + c_off[ty];
    int t = threadIdx.x;
    int loc[4];
    int v = 0;
#pragma unroll
    for (int j = 0; j < 4; ++j) {
        int i = base + t * 4 + j;
        loc[j] = v;
        v += (i < n) ? c[i] : 0;
    }
    s[t] = v;
    __syncthreads();
    for (int o = 1; o < 256; o <<= 1) {
        int x = (t >= o) ? s[t - o] : 0;
        __syncthreads();
        s[t] += x;
        __syncthreads();
    }
    int ex = s[t] - v;
    int off = g_bsumA[ty][blockIdx.x] + ex;
#pragma unroll
    for (int j = 0; j < 4; ++j) {
        int i = base + t * 4 + j;
        if (i < n) {
            int r = off + loc[j];
            rowptr[i] = r;
            fill[i] = r;
        }
    }
}

__global__ void k_fill_all(EJobs ep) {
    int b = blockIdx.x;
    int ty = 0;
    while (b >= ep.bs[ty + 1]) ++ty;
    int e = (b - ep.bs[ty]) * 256 + threadIdx.x;
    if (e >= ep.E[ty]) return;
    int s = __ldg(ep.ei[ty] + e);
    int d = __ldg(ep.ei[ty] + ep.E[ty] + e);
    int pos = atomicAdd(g_fl + c_off[ty] + d, 1);
    csr_of(ty)[pos] = s;
}

// ---------------- fp16 pull: 8 lanes/node, 16B per lane, fp32 accumulate ----------------
__device__ __forceinline__ void acc_h8(float acc[8], uint4 v) {
    float2 f0 = __half22float2(*reinterpret_cast<const __half2*>(&v.x));
    float2 f1 = __half22float2(*reinterpret_cast<const __half2*>(&v.y));
    float2 f2 = __half22float2(*reinterpret_cast<const __half2*>(&v.z));
    float2 f3 = __half22float2(*reinterpret_cast<const __half2*>(&v.w));
    acc[0] += f0.x; acc[1] += f0.y;
    acc[2] += f1.x; acc[3] += f1.y;
    acc[4] += f2.x; acc[5] += f2.y;
    acc[6] += f3.x; acc[7] += f3.y;
}

__device__ __forceinline__ void pull_mean_h(const __half* __restrict__ feat,
                                            const int* __restrict__ rowptr,
                                            const int* __restrict__ csr,
                                            int g, int lane, float acc[8]) {
#pragma unroll
    for (int i = 0; i < 8; ++i) acc[i] = 0.f;
    int beg = __ldg(rowptr + g), end = __ldg(rowptr + g + 1);
    int j = beg;
    for (; j + 3 < end; j += 4) {
        int s0 = __ldg(csr + j);
        int s1 = __ldg(csr + j + 1);
        int s2 = __ldg(csr + j + 2);
        int s3 = __ldg(csr + j + 3);
        uint4 v0 = *(const uint4*)(feat + (size_t)s0 * HID + lane * 8);
        uint4 v1 = *(const uint4*)(feat + (size_t)s1 * HID + lane * 8);
        uint4 v2 = *(const uint4*)(feat + (size_t)s2 * HID + lane * 8);
        uint4 v3 = *(const uint4*)(feat + (size_t)s3 * HID + lane * 8);
        acc_h8(acc, v0); acc_h8(acc, v1); acc_h8(acc, v2); acc_h8(acc, v3);
    }
    for (; j < end; ++j) {
        int s0 = __ldg(csr + j);
        uint4 v0 = *(const uint4*)(feat + (size_t)s0 * HID + lane * 8);
        acc_h8(acc, v0);
    }
    float inv = 1.f / fmaxf((float)(end - beg), 1.f);
#pragma unroll
    for (int i = 0; i < 8; ++i) acc[i] *= inv;
}

__device__ __forceinline__ uint4 pack_h8(const float v[8]) {
    uint4 o;
    *reinterpret_cast<__half2*>(&o.x) = __floats2half2_rn(v[0], v[1]);
    *reinterpret_cast<__half2*>(&o.y) = __floats2half2_rn(v[2], v[3]);
    *reinterpret_cast<__half2*>(&o.z) = __floats2half2_rn(v[4], v[5]);
    *reinterpret_cast<__half2*>(&o.w) = __floats2half2_rn(v[6], v[7]);
    return o;
}

// layer-1 paper: pull 3 edge types + self + bias + relu -> p1 (fp16 + fp32)
__global__ void k_layer1_paper() {
    int t = blockIdx.x * blockDim.x + threadIdx.x;
    if (t >= NP * 8) return;
    int g = t >> 3, lane = t & 7;
    float aw[8], ac[8], ar[8];
    pull_mean_h(g_hs_wr, g_rp_wr, g_csr_wr, g, lane, aw);
    pull_mean_h(g_hs_ci, g_rp_ci, g_csr_ci, g, lane, ac);
    pull_mean_h(g_hs_rh, g_rp_rh, g_csr_rh, g, lane, ar);
    uint4 sv = *(const uint4*)(g_selfP + (size_t)g * HID + lane * 8);
    float s[8] = {};
    acc_h8(s, sv);
    float o[8];
#pragma unroll
    for (int i = 0; i < 8; ++i) {
        float b = g_bsum1[lane * 8 + i];
        o[i] = fmaxf(s[i] + b + aw[i] + ac[i] + ar[i], 0.f);
    }
    *(uint4*)(g_p1h + (size_t)g * HID + lane * 8) = pack_h8(o);
    float* pf = g_p1 + (size_t)g * HID + lane * 8;
    *(float4*)(pf + 0) = make_float4(o[0], o[1], o[2], o[3]);
    *(float4*)(pf + 4) = make_float4(o[4], o[5], o[6], o[7]);
}

// layer-1 author/field: pull 1 edge type + self + bias + relu -> fp16 out
__global__ void k_layer1_af(const __half* __restrict__ feat, const int* __restrict__ rowptr,
                            const int* __restrict__ csr, const __half* __restrict__ selfX,
                            const float* __restrict__ bias, __half* __restrict__ out, int n) {
    int t = blockIdx.x * blockDim.x + threadIdx.x;
    if (t >= n * 8) return;
    int g = t >> 3, lane = t & 7;
    float a[8];
    pull_mean_h(feat, rowptr, csr, g, lane, a);
    uint4 sv = *(const uint4*)(selfX + (size_t)g * HID + lane * 8);
    float s[8] = {};
    acc_h8(s, sv);
    float o[8];
#pragma unroll
    for (int i = 0; i < 8; ++i) {
        float b = bias[lane * 8 + i];
        o[i] = fmaxf(s[i] + b + a[i], 0.f);
    }
    *(uint4*)(out + (size_t)g * HID + lane * 8) = pack_h8(o);
}

// layer-2: three fp16 pulls -> fp32 m2 buffers
__global__ void k_layer2_pulls() {
    int t = blockIdx.x * blockDim.x + threadIdx.x;
    if (t >= NP * 8) return;
    int g = t >> 3, lane = t & 7;
    float a[8];
    size_t off = (size_t)g * HID + lane * 8;
    pull_mean_h(g_a1h, g_rp_wr, g_csr_wr, g, lane, a);
    *(float4*)(g_m2_wr + off) = make_float4(a[0], a[1], a[2], a[3]);
    *(float4*)(g_m2_wr + off + 4) = make_float4(a[4], a[5], a[6], a[7]);
    pull_mean_h(g_p1h, g_rp_ci, g_csr_ci, g, lane, a);
    *(float4*)(g_m2_ci + off) = make_float4(a[0], a[1], a[2], a[3]);
    *(float4*)(g_m2_ci + off + 4) = make_float4(a[4], a[5], a[6], a[7]);
    pull_mean_h(g_f1h, g_rp_rh, g_csr_rh, g, lane, a);
    *(float4*)(g_m2_rh + off) = make_float4(a[0], a[1], a[2], a[3]);
    *(float4*)(g_m2_rh + off + 4) = make_float4(a[4], a[5], a[6], a[7]);
}

// ---------------- tf32 GEMM: C[M,64](fp16) = A[M,128] @ B[128,64], batched ----------------
struct GemmBatch {
    const float* B[4];
    __half* C[4];
};

__global__ void gemm_tf32_f128(const float* __restrict__ A, GemmBatch p, int M) {
    __shared__ uint32_t As[128 * 36];
    __shared__ uint32_t BsT[64 * 36];
    const float* __restrict__ Bp = p.B[blockIdx.y];
    __half* __restrict__ Cp = p.C[blockIdx.y];
    const int t = threadIdx.x;
    const int wid = t >> 5, lane = t & 31;
    const int g = lane >> 2, tg = lane & 3;
    const int rowBase = blockIdx.x * 128;
    const int wrow = wid * 16;

    float c[8][4] = {};

    for (int kb = 0; kb < 4; ++kb) {
#pragma unroll
        for (int j = 0; j < 4; ++j) {
            int idx = t + j * 256;
            int r = idx >> 3, c4 = idx & 7;
            int gr = rowBase + r;
            if (gr >= M) gr = M - 1;
            float4 av = *(const float4*)(A + (size_t)gr * FIN + kb * 32 + c4 * 4);
            uint32_t* d = &As[r * 36 + c4 * 4];
            d[0] = to_tf32(av.x); d[1] = to_tf32(av.y);
            d[2] = to_tf32(av.z); d[3] = to_tf32(av.w);
        }
#pragma unroll
        for (int j = 0; j < 2; ++j) {
            int idx = t + j * 256;
            int r = idx >> 4, c4 = idx & 15;
            float4 bv = *(const float4*)(Bp + (size_t)(kb * 32 + r) * HID + c4 * 4);
            BsT[(c4 * 4 + 0) * 36 + r] = to_tf32(bv.x);
            BsT[(c4 * 4 + 1) * 36 + r] = to_tf32(bv.y);
            BsT[(c4 * 4 + 2) * 36 + r] = to_tf32(bv.z);
            BsT[(c4 * 4 + 3) * 36 + r] = to_tf32(bv.w);
        }
        __syncthreads();
#pragma unroll
        for (int ks = 0; ks < 4; ++ks) {
            int k0 = ks * 8;
            uint32_t a0 = As[(wrow + g) * 36 + k0 + tg];
            uint32_t a1 = As[(wrow + g + 8) * 36 + k0 + tg];
            uint32_t a2 = As[(wrow + g) * 36 + k0 + tg + 4];
            uint32_t a3 = As[(wrow + g + 8) * 36 + k0 + tg + 4];
#pragma unroll
            for (int nt = 0; nt < 8; ++nt) {
                uint32_t b0 = BsT[(nt * 8 + g) * 36 + k0 + tg];
                uint32_t b1 = BsT[(nt * 8 + g) * 36 + k0 + tg + 4];
                mma_tf32(c[nt], a0, a1, a2, a3, b0, b1);
            }
        }
        __syncthreads();
    }

    int r0 = rowBase + wrow + g, r1 = r0 + 8;
#pragma unroll
    for (int nt = 0; nt < 8; ++nt) {
        int col = nt * 8 + tg * 2;
        if (r0 < M)
            *reinterpret_cast<__half2*>(Cp + (size_t)r0 * HID + col) = __floats2half2_rn(c[nt][0], c[nt][1]);
        if (r1 < M)
            *reinterpret_cast<__half2*>(Cp + (size_t)r1 * HID + col) = __floats2half2_rn(c[nt][2], c[nt][3]);
    }
}

// ---------------- tf32 output GEMM: fp32 in/out ----------------
__global__ void gemm_out_tf32(const float* __restrict__ A0, const float* __restrict__ A1,
                              const float* __restrict__ A2, const float* __restrict__ A3,
                              const float* __restrict__ B0, const float* __restrict__ B1,
                              const float* __restrict__ B2, const float* __restrict__ B3,
                              float* __restrict__ C, int M) {
    __shared__ uint32_t As[128 * 36];
    __shared__ uint32_t BsT[64 * 36];
    const int t = threadIdx.x;
    const int wid = t >> 5, lane = t & 31;
    const int g = lane >> 2, tg = lane & 3;
    const int rowBase = blockIdx.x * 128;
    const int colBase = blockIdx.y * 64;
    const int wrow = wid * 16;

    const float* Aps[4] = {A0, A1, A2, A3};
    const float* Bps[4] = {B0, B1, B2, B3};

    float c[8][4] = {};

    for (int m = 0; m < 4; ++m) {
        const float* __restrict__ Ap = Aps[m];
        const float* __restrict__ Bp = Bps[m];
        for (int kb = 0; kb < 2; ++kb) {
#pragma unroll
            for (int j = 0; j < 4; ++j) {
                int idx = t + j * 256;
                int r = idx >> 3, c4 = idx & 7;
                int gr = rowBase + r;
                if (gr >= M) gr = M - 1;
                float4 av = *(const float4*)(Ap + (size_t)gr * HID + kb * 32 + c4 * 4);
                uint32_t* d = &As[r * 36 + c4 * 4];
                d[0] = to_tf32(av.x); d[1] = to_tf32(av.y);
                d[2] = to_tf32(av.z); d[3] = to_tf32(av.w);
            }
#pragma unroll
            for (int j = 0; j < 8; ++j) {
                int idx = t + j * 256;
                int r = idx >> 6, cc = idx & 63;
                int col = colBase + cc;
                float v = (col < OUTF) ? Bp[(size_t)(kb * 32 + r) * OUTF + col] : 0.f;
                BsT[cc * 36 + r] = to_tf32(v);
            }
            __syncthreads();
#pragma unroll
            for (int ks = 0; ks < 4; ++ks) {
                int k0 = ks * 8;
                uint32_t a0 = As[(wrow + g) * 36 + k0 + tg];
                uint32_t a1 = As[(wrow + g + 8) * 36 + k0 + tg];
                uint32_t a2 = As[(wrow + g) * 36 + k0 + tg + 4];
                uint32_t a3 = As[(wrow + g + 8) * 36 + k0 + tg + 4];
#pragma unroll
                for (int nt = 0; nt < 8; ++nt) {
                    uint32_t b0 = BsT[(nt * 8 + g) * 36 + k0 + tg];
                    uint32_t b1 = BsT[(nt * 8 + g) * 36 + k0 + tg + 4];
                    mma_tf32(c[nt], a0, a1, a2, a3, b0, b1);
                }
            }
            __syncthreads();
        }
    }

    int r0 = rowBase + wrow + g, r1 = r0 + 8;
#pragma unroll
    for (int nt = 0; nt < 8; ++nt) {
        int col = colBase + nt * 8 + tg * 2;
        if (col < OUTF) {
            float bia = g_bsum2[col];
            if (r0 < M) C[(size_t)r0 * OUTF + col] = c[nt][0] + bia;
            if (r1 < M) C[(size_t)r1 * OUTF + col] = c[nt][2] + bia;
        }
        if (col + 1 < OUTF) {
            float bib = g_bsum2[col + 1];
            if (r0 < M) C[(size_t)r0 * OUTF + col + 1] = c[nt][1] + bib;
            if (r1 < M) C[(size_t)r1 * OUTF + col + 1] = c[nt][3] + bib;
        }
    }
}

// ---------------- host launcher ----------------
static inline void* sym(const void* s) {
    void* p = nullptr;
    cudaGetSymbolAddress(&p, s);
    return p;
}

extern "C" void kernel_launch(void* const* d_in, const int* in_sizes, int n_in,
                              void* d_out, int out_size) {
    static cudaStream_t s1 = nullptr;
    static cudaEvent_t ev0 = nullptr, ev1 = nullptr;
    if (s1 == nullptr) {
        cudaStreamCreateWithFlags(&s1, cudaStreamNonBlocking);
        cudaEventCreateWithFlags(&ev0, cudaEventDisableTiming);
        cudaEventCreateWithFlags(&ev1, cudaEventDisableTiming);
    }

    const float* x_paper  = (const float*)d_in[0];
    const float* x_author = (const float*)d_in[1];
    const float* x_field  = (const float*)d_in[2];
    const int* ei_wr = (const int*)d_in[3];
    const int* ei_rw = (const int*)d_in[4];
    const int* ei_ci = (const int*)d_in[5];
    const int* ei_ht = (const int*)d_in[6];
    const int* ei_rh = (const int*)d_in[7];
    const int nE_wr = in_sizes[3] / 2;
    const int nE_rw = in_sizes[4] / 2;
    const int nE_ci = in_sizes[5] / 2;
    const int nE_ht = in_sizes[6] / 2;
    const int nE_rh = in_sizes[7] / 2;

    const float* wl1_wr = (const float*)d_in[8];
    const float* wr1_wr = (const float*)d_in[9];
    const float* b1_wr  = (const float*)d_in[10];
    const float* wl1_rw = (const float*)d_in[11];
    const float* wr1_rw = (const float*)d_in[12];
    const float* b1_rw  = (const float*)d_in[13];
    const float* wl1_ci = (const float*)d_in[14];
    const float* wr1_ci = (const float*)d_in[15];
    const float* b1_ci  = (const float*)d_in[16];
    const float* wl1_ht = (const float*)d_in[17];
    const float* wr1_ht = (const float*)d_in[18];
    const float* b1_ht  = (const float*)d_in[19];
    const float* wl1_rh = (const float*)d_in[20];
    const float* wr1_rh = (const float*)d_in[21];
    const float* b1_rh  = (const float*)d_in[22];
    const float* wl2_wr = (const float*)d_in[23];
    const float* wr2_wr = (const float*)d_in[24];
    const float* b2_wr  = (const float*)d_in[25];
    const float* wl2_ci = (const float*)d_in[26];
    const float* wr2_ci = (const float*)d_in[27];
    const float* b2_ci  = (const float*)d_in[28];
    const float* wl2_rh = (const float*)d_in[29];
    const float* wr2_rh = (const float*)d_in[30];
    const float* b2_rh  = (const float*)d_in[31];

    float* out = (float*)d_out;

    __half* hs_wr = (__half*)sym(g_hs_wr);
    __half* hs_rw = (__half*)sym(g_hs_rw);
    __half* hs_ci = (__half*)sym(g_hs_ci);
    __half* hs_ht = (__half*)sym(g_hs_ht);
    __half* hs_rh = (__half*)sym(g_hs_rh);
    __half* selfP = (__half*)sym(g_selfP);
    __half* selfA = (__half*)sym(g_selfA);
    __half* selfF = (__half*)sym(g_selfF);
    __half* a1h = (__half*)sym(g_a1h);
    __half* f1h = (__half*)sym(g_f1h);
    float* p1 = (float*)sym(g_p1);
    float* m2_wr = (float*)sym(g_m2_wr);
    float* m2_ci = (float*)sym(g_m2_ci);
    float* m2_rh = (float*)sym(g_m2_rh);
    int* cnt = (int*)sym(g_cnt);
    int* rp_rw = (int*)sym(g_rp_rw);
    int* rp_ht = (int*)sym(g_rp_ht);
    int* csr_rw = (int*)sym(g_csr_rw);
    int* csr_ht = (int*)sym(g_csr_ht);
    float* wsumP = (float*)sym(g_wsumP);
    float* w2sum = (float*)sym(g_w2sum);

    // ---- fork: side stream does weight prep + layer-1 GEMMs ----
    cudaEventRecord(ev0, 0);
    cudaStreamWaitEvent(s1, ev0, 0);

    prep_weights<<<(HID * OUTF + 255) / 256, 256, 0, s1>>>(
        wr1_wr, wr1_ci, wr1_rh, wr2_wr, wr2_ci, wr2_rh,
        b1_wr, b1_ci, b1_rh, b2_wr, b2_ci, b2_rh);

    const int gP = (NP + 127) / 128, gA = (NA + 127) / 128, gF = (NF + 127) / 128;
    {
        GemmBatch bp;
        bp.B[0] = wl1_rw; bp.C[0] = hs_rw;
        bp.B[1] = wl1_ci; bp.C[1] = hs_ci;
        bp.B[2] = wl1_ht; bp.C[2] = hs_ht;
        bp.B[3] = wsumP;  bp.C[3] = selfP;
        gemm_tf32_f128<<<dim3(gP, 4), 256, 0, s1>>>(x_paper, bp, NP);
        GemmBatch ba;
        ba.B[0] = wl1_wr; ba.C[0] = hs_wr;
        ba.B[1] = wr1_rw; ba.C[1] = selfA;
        ba.B[2] = wl1_wr; ba.C[2] = hs_wr;
        ba.B[3] = wl1_wr; ba.C[3] = hs_wr;
        gemm_tf32_f128<<<dim3(gA, 2), 256, 0, s1>>>(x_author, ba, NA);
        GemmBatch bf;
        bf.B[0] = wl1_rh; bf.C[0] = hs_rh;
        bf.B[1] = wr1_ht; bf.C[1] = selfF;
        bf.B[2] = wl1_rh; bf.C[2] = hs_rh;
        bf.B[3] = wl1_rh; bf.C[3] = hs_rh;
        gemm_tf32_f128<<<dim3(gF, 2), 256, 0, s1>>>(x_field, bf, NF);
    }
    cudaEventRecord(ev1, s1);

    // ---- default stream: CSR build ----
    cudaMemsetAsync(cnt, 0, sizeof(int) * CNT_TOT, 0);

    EJobs ep;
    ep.ei[0] = ei_wr; ep.E[0] = nE_wr;
    ep.ei[1] = ei_rw; ep.E[1] = nE_rw;
    ep.ei[2] = ei_ci; ep.E[2] = nE_ci;
    ep.ei[3] = ei_ht; ep.E[3] = nE_ht;
    ep.ei[4] = ei_rh; ep.E[4] = nE_rh;
    ep.bs[0] = 0;
    for (int i = 0; i < 5; ++i) ep.bs[i + 1] = ep.bs[i] + (ep.E[i] + 255) / 256;

    k_count_all<<<ep.bs[5], 256>>>(ep);
    k_blocksum_all<<<dim3((NP + 1023) / 1024, 5), 256>>>();
    k_scan_bsums_all<<<5, 256>>>();
    k_scan_write_all<<<dim3((NP + 1023) / 1024, 5), 256>>>();
    k_fill_all<<<ep.bs[5], 256>>>(ep);

    // ---- join ----
    cudaStreamWaitEvent(0, ev1, 0);

    // ---- layer-1 fused pulls (mean + self + bias + relu), fp16 gathers ----
    k_layer1_paper<<<(NP * 8 + 255) / 256, 256>>>();
    k_layer1_af<<<(NA * 8 + 255) / 256, 256>>>(hs_rw, rp_rw, csr_rw, selfA, b1_rw, a1h, NA);
    k_layer1_af<<<(NF * 8 + 255) / 256, 256>>>(hs_ht, rp_ht, csr_ht, selfF, b1_ht, f1h, NF);

    // ---- layer-2 pulls (one kernel, CSRs reused, fp16 gathers) ----
    k_layer2_pulls<<<(NP * 8 + 255) / 256, 256>>>();

    // ---- output GEMM (tf32) ----
    dim3 g2(gP, (OUTF + 63) / 64);
    gemm_out_tf32<<<g2, 256>>>(m2_wr, m2_ci, m2_rh, p1,
                               wl2_wr, wl2_ci, wl2_rh, w2sum,
                               out, NP);
}

// round 7
// speedup vs baseline: 1.9674x; 1.0873x over previous
#include <cuda_runtime.h>
#include <cuda_fp16.h>
#include <cstdint>

#define NP 100000
#define NA 100000
#define NF 50000
#define FIN 128
#define HID 64
#define OUTF 349

#define E_WR 1000000
#define E_RW 1000000
#define E_CI 2000000
#define E_HT 1000000
#define E_RH 1000000

#define CNT_TOT (NP + NA + NP + NF + NP)   // 450000

// ---------------- scratch ----------------
static __device__ __align__(256) __half g_hs_wr[NA * HID];
static __device__ __align__(256) __half g_hs_rw[NP * HID];
static __device__ __align__(256) __half g_hs_ci[NP * HID];
static __device__ __align__(256) __half g_hs_ht[NP * HID];
static __device__ __align__(256) __half g_hs_rh[NF * HID];
static __device__ __align__(256) __half g_selfP[NP * HID];
static __device__ __align__(256) __half g_selfA[NA * HID];
static __device__ __align__(256) __half g_selfF[NF * HID];
static __device__ __align__(256) __half g_p1h[NP * HID];
static __device__ __align__(256) __half g_a1h[NA * HID];
static __device__ __align__(256) __half g_f1h[NF * HID];
static __device__ __align__(256) __half g_m2_wr[NP * HID];
static __device__ __align__(256) __half g_m2_ci[NP * HID];
static __device__ __align__(256) __half g_m2_rh[NP * HID];
// CSR machinery
static __device__ int g_cnt[CNT_TOT];
static __device__ int g_fl[CNT_TOT];
static __device__ int g_rp_wr[NP + 1], g_rp_rw[NA + 1], g_rp_ci[NP + 1], g_rp_ht[NF + 1], g_rp_rh[NP + 1];
static __device__ int g_csr_wr[E_WR], g_csr_rw[E_RW], g_csr_ci[E_CI], g_csr_ht[E_HT], g_csr_rh[E_RH];
static __device__ int g_bsumA[5][128];
// summed weights / biases
static __device__ __align__(256) float g_wsumP[FIN * HID];
static __device__ __align__(256) float g_w2sum[HID * OUTF];
static __device__ __align__(256) float g_bsum1[HID];
static __device__ __align__(256) float g_bsum2[OUTF];

__constant__ int c_n[5] = {NP, NA, NP, NF, NP};
__constant__ int c_off[5] = {0, NP, NP + NA, NP + NA + NP, NP + NA + NP + NF};

__device__ __forceinline__ int* rp_of(int ty) {
    switch (ty) {
        case 0: return g_rp_wr;
        case 1: return g_rp_rw;
        case 2: return g_rp_ci;
        case 3: return g_rp_ht;
        default: return g_rp_rh;
    }
}
__device__ __forceinline__ int* csr_of(int ty) {
    switch (ty) {
        case 0: return g_csr_wr;
        case 1: return g_csr_rw;
        case 2: return g_csr_ci;
        case 3: return g_csr_ht;
        default: return g_csr_rh;
    }
}

// ---------------- tf32 helpers ----------------
__device__ __forceinline__ uint32_t to_tf32(float x) {
    uint32_t r;
    asm("cvt.rna.tf32.f32 %0, %1;" : "=r"(r) : "f"(x));
    return r;
}

__device__ __forceinline__ void mma_tf32(float c[4], uint32_t a0, uint32_t a1,
                                         uint32_t a2, uint32_t a3,
                                         uint32_t b0, uint32_t b1) {
    asm volatile("mma.sync.aligned.m16n8k8.row.col.f32.tf32.tf32.f32 "
                 "{%0,%1,%2,%3}, {%4,%5,%6,%7}, {%8,%9}, {%0,%1,%2,%3};"
                 : "+f"(c[0]), "+f"(c[1]), "+f"(c[2]), "+f"(c[3])
                 : "r"(a0), "r"(a1), "r"(a2), "r"(a3), "r"(b0), "r"(b1));
}

// ---------------- weight/bias prep ----------------
__global__ void prep_weights(const float* __restrict__ wr1a, const float* __restrict__ wr1b,
                             const float* __restrict__ wr1c,
                             const float* __restrict__ wr2a, const float* __restrict__ wr2b,
                             const float* __restrict__ wr2c,
                             const float* __restrict__ b1a, const float* __restrict__ b1b,
                             const float* __restrict__ b1c,
                             const float* __restrict__ b2a, const float* __restrict__ b2b,
                             const float* __restrict__ b2c) {
    int i = blockIdx.x * blockDim.x + threadIdx.x;
    if (i < FIN * HID) g_wsumP[i] = wr1a[i] + wr1b[i] + wr1c[i];
    if (i < HID * OUTF) g_w2sum[i] = wr2a[i] + wr2b[i] + wr2c[i];
    if (i < HID) g_bsum1[i] = b1a[i] + b1b[i] + b1c[i];
    if (i < OUTF) g_bsum2[i] = b2a[i] + b2b[i] + b2c[i];
}

// ---------------- CSR build ----------------
struct EJobs {
    const int* ei[5];
    int E[5];
    int bs[6];
};

__global__ void k_count_all(EJobs ep) {
    int b = blockIdx.x;
    int ty = 0;
    while (b >= ep.bs[ty + 1]) ++ty;
    int e = (b - ep.bs[ty]) * 256 + threadIdx.x;
    if (e >= ep.E[ty]) return;
    int d = __ldg(ep.ei[ty] + ep.E[ty] + e);
    atomicAdd(g_cnt + c_off[ty] + d, 1);
}

__global__ void k_blocksum_all() {
    __shared__ int s[256];
    int ty = blockIdx.y;
    int n = c_n[ty];
    int base = blockIdx.x * 1024;
    if (base >= n) { if (threadIdx.x == 0) g_bsumA[ty][blockIdx.x] = 0; return; }
    const int* c = g_cnt + c_off[ty];
    int t = threadIdx.x;
    int v = 0;
#pragma unroll
    for (int j = 0; j < 4; ++j) {
        int i = base + t * 4 + j;
        if (i < n) v += c[i];
    }
    s[t] = v;
    __syncthreads();
    for (int o = 128; o > 0; o >>= 1) {
        if (t < o) s[t] += s[t + o];
        __syncthreads();
    }
    if (t == 0) g_bsumA[ty][blockIdx.x] = s[0];
}

__global__ void k_scan_bsums_all() {
    __shared__ int s[256];
    int ty = blockIdx.x;
    int n = c_n[ty];
    int nb = (n + 1023) / 1024;
    int t = threadIdx.x;
    int v = (t < nb) ? g_bsumA[ty][t] : 0;
    s[t] = v;
    __syncthreads();
    for (int o = 1; o < 256; o <<= 1) {
        int x = (t >= o) ? s[t - o] : 0;
        __syncthreads();
        s[t] += x;
        __syncthreads();
    }
    if (t < nb) g_bsumA[ty][t] = s[t] - v;
    if (t == 0) rp_of(ty)[n] = s[255];
}

__global__ void k_scan_write_all() {
    __shared__ int s[256];
    int ty = blockIdx.y;
    int n = c_n[ty];
    int base = blockIdx.x * 1024;
    if (base >= n) return;
    const int* c = g_cnt + c_off[ty];
    int* rowptr = rp_of(ty);
    int* fill = g_fl + c_off[ty];
    int t = threadIdx.x;
    int loc[4];
    int v = 0;
#pragma unroll
    for (int j = 0; j < 4; ++j) {
        int i = base + t * 4 + j;
        loc[j] = v;
        v += (i < n) ? c[i] : 0;
    }
    s[t] = v;
    __syncthreads();
    for (int o = 1; o < 256; o <<= 1) {
        int x = (t >= o) ? s[t - o] : 0;
        __syncthreads();
        s[t] += x;
        __syncthreads();
    }
    int ex = s[t] - v;
    int off = g_bsumA[ty][blockIdx.x] + ex;
#pragma unroll
    for (int j = 0; j < 4; ++j) {
        int i = base + t * 4 + j;
        if (i < n) {
            int r = off + loc[j];
            rowptr[i] = r;
            fill[i] = r;
        }
    }
}

__global__ void k_fill_all(EJobs ep) {
    int b = blockIdx.x;
    int ty = 0;
    while (b >= ep.bs[ty + 1]) ++ty;
    int e = (b - ep.bs[ty]) * 256 + threadIdx.x;
    if (e >= ep.E[ty]) return;
    int s = __ldg(ep.ei[ty] + e);
    int d = __ldg(ep.ei[ty] + ep.E[ty] + e);
    int pos = atomicAdd(g_fl + c_off[ty] + d, 1);
    csr_of(ty)[pos] = s;
}

// ---------------- warp-per-node pull: 4 edge-teams x 8 feature lanes ----------------
__device__ __forceinline__ void acc_h8(float acc[8], uint4 v) {
    float2 f0 = __half22float2(*reinterpret_cast<const __half2*>(&v.x));
    float2 f1 = __half22float2(*reinterpret_cast<const __half2*>(&v.y));
    float2 f2 = __half22float2(*reinterpret_cast<const __half2*>(&v.z));
    float2 f3 = __half22float2(*reinterpret_cast<const __half2*>(&v.w));
    acc[0] += f0.x; acc[1] += f0.y;
    acc[2] += f1.x; acc[3] += f1.y;
    acc[4] += f2.x; acc[5] += f2.y;
    acc[6] += f3.x; acc[7] += f3.y;
}

// team = lane>>3 (0..3), c = lane&7 (feature chunk). After the shfl tree all
// 32 lanes hold the full mean for their chunk c.
__device__ __forceinline__ void pull_mean_warp(const __half* __restrict__ feat,
                                               const int* __restrict__ rowptr,
                                               const int* __restrict__ csr,
                                               int g, int team, int c, float acc[8]) {
#pragma unroll
    for (int i = 0; i < 8; ++i) acc[i] = 0.f;
    int beg = __ldg(rowptr + g), end = __ldg(rowptr + g + 1);
    int j = beg + team;
    for (; j + 4 < end; j += 8) {
        int s0 = __ldg(csr + j);
        int s1 = __ldg(csr + j + 4);
        uint4 v0 = *(const uint4*)(feat + (size_t)s0 * HID + c * 8);
        uint4 v1 = *(const uint4*)(feat + (size_t)s1 * HID + c * 8);
        acc_h8(acc, v0);
        acc_h8(acc, v1);
    }
    if (j < end) {
        int s0 = __ldg(csr + j);
        uint4 v0 = *(const uint4*)(feat + (size_t)s0 * HID + c * 8);
        acc_h8(acc, v0);
    }
#pragma unroll
    for (int i = 0; i < 8; ++i) {
        acc[i] += __shfl_xor_sync(0xffffffffu, acc[i], 8);
        acc[i] += __shfl_xor_sync(0xffffffffu, acc[i], 16);
    }
    float inv = 1.f / fmaxf((float)(end - beg), 1.f);
#pragma unroll
    for (int i = 0; i < 8; ++i) acc[i] *= inv;
}

__device__ __forceinline__ uint4 pack_h8(const float v[8]) {
    uint4 o;
    *reinterpret_cast<__half2*>(&o.x) = __floats2half2_rn(v[0], v[1]);
    *reinterpret_cast<__half2*>(&o.y) = __floats2half2_rn(v[2], v[3]);
    *reinterpret_cast<__half2*>(&o.z) = __floats2half2_rn(v[4], v[5]);
    *reinterpret_cast<__half2*>(&o.w) = __floats2half2_rn(v[6], v[7]);
    return o;
}

// layer-1 paper: 3 pulls + self + bias + relu -> p1h
__global__ void k_paper_warp() {
    int wg = (blockIdx.x * blockDim.x + threadIdx.x) >> 5;
    if (wg >= NP) return;
    int lane = threadIdx.x & 31;
    int team = lane >> 3, c = lane & 7;
    float aw[8], ac[8], ar[8];
    pull_mean_warp(g_hs_wr, g_rp_wr, g_csr_wr, wg, team, c, aw);
    pull_mean_warp(g_hs_ci, g_rp_ci, g_csr_ci, wg, team, c, ac);
    pull_mean_warp(g_hs_rh, g_rp_rh, g_csr_rh, wg, team, c, ar);
    if (team == 0) {
        uint4 sv = *(const uint4*)(g_selfP + (size_t)wg * HID + c * 8);
        float s[8] = {};
        acc_h8(s, sv);
        float o[8];
#pragma unroll
        for (int i = 0; i < 8; ++i) {
            float b = g_bsum1[c * 8 + i];
            o[i] = fmaxf(s[i] + b + aw[i] + ac[i] + ar[i], 0.f);
        }
        *(uint4*)(g_p1h + (size_t)wg * HID + c * 8) = pack_h8(o);
    }
}

// layer-1 author/field: 1 pull + self + bias + relu -> fp16 out
__global__ void k_af_warp(const __half* __restrict__ feat, const int* __restrict__ rowptr,
                          const int* __restrict__ csr, const __half* __restrict__ selfX,
                          const float* __restrict__ bias, __half* __restrict__ out, int n) {
    int wg = (blockIdx.x * blockDim.x + threadIdx.x) >> 5;
    if (wg >= n) return;
    int lane = threadIdx.x & 31;
    int team = lane >> 3, c = lane & 7;
    float a[8];
    pull_mean_warp(feat, rowptr, csr, wg, team, c, a);
    if (team == 0) {
        uint4 sv = *(const uint4*)(selfX + (size_t)wg * HID + c * 8);
        float s[8] = {};
        acc_h8(s, sv);
        float o[8];
#pragma unroll
        for (int i = 0; i < 8; ++i) {
            float b = bias[c * 8 + i];
            o[i] = fmaxf(s[i] + b + a[i], 0.f);
        }
        *(uint4*)(out + (size_t)wg * HID + c * 8) = pack_h8(o);
    }
}

// layer-2 single pull -> fp16 mean buffer
__global__ void k_l2_warp(const __half* __restrict__ feat, const int* __restrict__ rowptr,
                          const int* __restrict__ csr, __half* __restrict__ out, int n) {
    int wg = (blockIdx.x * blockDim.x + threadIdx.x) >> 5;
    if (wg >= n) return;
    int lane = threadIdx.x & 31;
    int team = lane >> 3, c = lane & 7;
    float a[8];
    pull_mean_warp(feat, rowptr, csr, wg, team, c, a);
    if (team == 0)
        *(uint4*)(out + (size_t)wg * HID + c * 8) = pack_h8(a);
}

// ---------------- tf32 GEMM: C[M,64](fp16) = A[M,128] @ B[128,64], batched ----------------
struct GemmBatch {
    const float* B[4];
    __half* C[4];
};

__global__ void gemm_tf32_f128(const float* __restrict__ A, GemmBatch p, int M) {
    __shared__ uint32_t As[128 * 36];
    __shared__ uint32_t BsT[64 * 36];
    const float* __restrict__ Bp = p.B[blockIdx.y];
    __half* __restrict__ Cp = p.C[blockIdx.y];
    const int t = threadIdx.x;
    const int wid = t >> 5, lane = t & 31;
    const int g = lane >> 2, tg = lane & 3;
    const int rowBase = blockIdx.x * 128;
    const int wrow = wid * 16;

    float c[8][4] = {};

    for (int kb = 0; kb < 4; ++kb) {
#pragma unroll
        for (int j = 0; j < 4; ++j) {
            int idx = t + j * 256;
            int r = idx >> 3, c4 = idx & 7;
            int gr = rowBase + r;
            if (gr >= M) gr = M - 1;
            float4 av = *(const float4*)(A + (size_t)gr * FIN + kb * 32 + c4 * 4);
            uint32_t* d = &As[r * 36 + c4 * 4];
            d[0] = to_tf32(av.x); d[1] = to_tf32(av.y);
            d[2] = to_tf32(av.z); d[3] = to_tf32(av.w);
        }
#pragma unroll
        for (int j = 0; j < 2; ++j) {
            int idx = t + j * 256;
            int r = idx >> 4, c4 = idx & 15;
            float4 bv = *(const float4*)(Bp + (size_t)(kb * 32 + r) * HID + c4 * 4);
            BsT[(c4 * 4 + 0) * 36 + r] = to_tf32(bv.x);
            BsT[(c4 * 4 + 1) * 36 + r] = to_tf32(bv.y);
            BsT[(c4 * 4 + 2) * 36 + r] = to_tf32(bv.z);
            BsT[(c4 * 4 + 3) * 36 + r] = to_tf32(bv.w);
        }
        __syncthreads();
#pragma unroll
        for (int ks = 0; ks < 4; ++ks) {
            int k0 = ks * 8;
            uint32_t a0 = As[(wrow + g) * 36 + k0 + tg];
            uint32_t a1 = As[(wrow + g + 8) * 36 + k0 + tg];
            uint32_t a2 = As[(wrow + g) * 36 + k0 + tg + 4];
            uint32_t a3 = As[(wrow + g + 8) * 36 + k0 + tg + 4];
#pragma unroll
            for (int nt = 0; nt < 8; ++nt) {
                uint32_t b0 = BsT[(nt * 8 + g) * 36 + k0 + tg];
                uint32_t b1 = BsT[(nt * 8 + g) * 36 + k0 + tg + 4];
                mma_tf32(c[nt], a0, a1, a2, a3, b0, b1);
            }
        }
        __syncthreads();
    }

    int r0 = rowBase + wrow + g, r1 = r0 + 8;
#pragma unroll
    for (int nt = 0; nt < 8; ++nt) {
        int col = nt * 8 + tg * 2;
        if (r0 < M)
            *reinterpret_cast<__half2*>(Cp + (size_t)r0 * HID + col) = __floats2half2_rn(c[nt][0], c[nt][1]);
        if (r1 < M)
            *reinterpret_cast<__half2*>(Cp + (size_t)r1 * HID + col) = __floats2half2_rn(c[nt][2], c[nt][3]);
    }
}

// ---------------- tf32 output GEMM: fp16 A inputs, fp32 out ----------------
__global__ void gemm_out_tf32(const __half* __restrict__ A0, const __half* __restrict__ A1,
                              const __half* __restrict__ A2, const __half* __restrict__ A3,
                              const float* __restrict__ B0, const float* __restrict__ B1,
                              const float* __restrict__ B2, const float* __restrict__ B3,
                              float* __restrict__ C, int M) {
    __shared__ uint32_t As[128 * 36];
    __shared__ uint32_t BsT[64 * 36];
    const int t = threadIdx.x;
    const int wid = t >> 5, lane = t & 31;
    const int g = lane >> 2, tg = lane & 3;
    const int rowBase = blockIdx.x * 128;
    const int colBase = blockIdx.y * 64;
    const int wrow = wid * 16;

    const __half* Aps[4] = {A0, A1, A2, A3};
    const float* Bps[4] = {B0, B1, B2, B3};

    float c[8][4] = {};

    for (int m = 0; m < 4; ++m) {
        const __half* __restrict__ Ap = Aps[m];
        const float* __restrict__ Bp = Bps[m];
        for (int kb = 0; kb < 2; ++kb) {
            // A chunk: 128 rows x 32 halves (64B/row) -> tf32
#pragma unroll
            for (int j = 0; j < 2; ++j) {
                int idx = t + j * 256;          // 0..511
                int r = idx >> 2, q = idx & 3;
                int gr = rowBase + r;
                if (gr >= M) gr = M - 1;
                uint4 hv = *(const uint4*)(Ap + (size_t)gr * HID + kb * 32 + q * 8);
                float2 f0 = __half22float2(*reinterpret_cast<const __half2*>(&hv.x));
                float2 f1 = __half22float2(*reinterpret_cast<const __half2*>(&hv.y));
                float2 f2 = __half22float2(*reinterpret_cast<const __half2*>(&hv.z));
                float2 f3 = __half22float2(*reinterpret_cast<const __half2*>(&hv.w));
                uint32_t* d = &As[r * 36 + q * 8];
                d[0] = to_tf32(f0.x); d[1] = to_tf32(f0.y);
                d[2] = to_tf32(f1.x); d[3] = to_tf32(f1.y);
                d[4] = to_tf32(f2.x); d[5] = to_tf32(f2.y);
                d[6] = to_tf32(f3.x); d[7] = to_tf32(f3.y);
            }
#pragma unroll
            for (int j = 0; j < 8; ++j) {
                int idx = t + j * 256;
                int r = idx >> 6, cc = idx & 63;
                int col = colBase + cc;
                float v = (col < OUTF) ? Bp[(size_t)(kb * 32 + r) * OUTF + col] : 0.f;
                BsT[cc * 36 + r] = to_tf32(v);
            }
            __syncthreads();
#pragma unroll
            for (int ks = 0; ks < 4; ++ks) {
                int k0 = ks * 8;
                uint32_t a0 = As[(wrow + g) * 36 + k0 + tg];
                uint32_t a1 = As[(wrow + g + 8) * 36 + k0 + tg];
                uint32_t a2 = As[(wrow + g) * 36 + k0 + tg + 4];
                uint32_t a3 = As[(wrow + g + 8) * 36 + k0 + tg + 4];
#pragma unroll
                for (int nt = 0; nt < 8; ++nt) {
                    uint32_t b0 = BsT[(nt * 8 + g) * 36 + k0 + tg];
                    uint32_t b1 = BsT[(nt * 8 + g) * 36 + k0 + tg + 4];
                    mma_tf32(c[nt], a0, a1, a2, a3, b0, b1);
                }
            }
            __syncthreads();
        }
    }

    int r0 = rowBase + wrow + g, r1 = r0 + 8;
#pragma unroll
    for (int nt = 0; nt < 8; ++nt) {
        int col = colBase + nt * 8 + tg * 2;
        if (col < OUTF) {
            float bia = g_bsum2[col];
            if (r0 < M) C[(size_t)r0 * OUTF + col] = c[nt][0] + bia;
            if (r1 < M) C[(size_t)r1 * OUTF + col] = c[nt][2] + bia;
        }
        if (col + 1 < OUTF) {
            float bib = g_bsum2[col + 1];
            if (r0 < M) C[(size_t)r0 * OUTF + col + 1] = c[nt][1] + bib;
            if (r1 < M) C[(size_t)r1 * OUTF + col + 1] = c[nt][3] + bib;
        }
    }
}

// ---------------- host launcher ----------------
static inline void* sym(const void* s) {
    void* p = nullptr;
    cudaGetSymbolAddress(&p, s);
    return p;
}

extern "C" void kernel_launch(void* const* d_in, const int* in_sizes, int n_in,
                              void* d_out, int out_size) {
    static cudaStream_t s1 = nullptr;
    static cudaEvent_t ev0 = nullptr, ev1 = nullptr, ev2 = nullptr, ev3 = nullptr;
    if (s1 == nullptr) {
        cudaStreamCreateWithFlags(&s1, cudaStreamNonBlocking);
        cudaEventCreateWithFlags(&ev0, cudaEventDisableTiming);
        cudaEventCreateWithFlags(&ev1, cudaEventDisableTiming);
        cudaEventCreateWithFlags(&ev2, cudaEventDisableTiming);
        cudaEventCreateWithFlags(&ev3, cudaEventDisableTiming);
    }

    const float* x_paper  = (const float*)d_in[0];
    const float* x_author = (const float*)d_in[1];
    const float* x_field  = (const float*)d_in[2];
    const int* ei_wr = (const int*)d_in[3];
    const int* ei_rw = (const int*)d_in[4];
    const int* ei_ci = (const int*)d_in[5];
    const int* ei_ht = (const int*)d_in[6];
    const int* ei_rh = (const int*)d_in[7];
    const int nE_wr = in_sizes[3] / 2;
    const int nE_rw = in_sizes[4] / 2;
    const int nE_ci = in_sizes[5] / 2;
    const int nE_ht = in_sizes[6] / 2;
    const int nE_rh = in_sizes[7] / 2;

    const float* wl1_wr = (const float*)d_in[8];
    const float* wr1_wr = (const float*)d_in[9];
    const float* b1_wr  = (const float*)d_in[10];
    const float* wl1_rw = (const float*)d_in[11];
    const float* wr1_rw = (const float*)d_in[12];
    const float* b1_rw  = (const float*)d_in[13];
    const float* wl1_ci = (const float*)d_in[14];
    const float* wr1_ci = (const float*)d_in[15];
    const float* b1_ci  = (const float*)d_in[16];
    const float* wl1_ht = (const float*)d_in[17];
    const float* wr1_ht = (const float*)d_in[18];
    const float* b1_ht  = (const float*)d_in[19];
    const float* wl1_rh = (const float*)d_in[20];
    const float* wr1_rh = (const float*)d_in[21];
    const float* b1_rh  = (const float*)d_in[22];
    const float* wl2_wr = (const float*)d_in[23];
    const float* wr2_wr = (const float*)d_in[24];
    const float* b2_wr  = (const float*)d_in[25];
    const float* wl2_ci = (const float*)d_in[26];
    const float* wr2_ci = (const float*)d_in[27];
    const float* b2_ci  = (const float*)d_in[28];
    const float* wl2_rh = (const float*)d_in[29];
    const float* wr2_rh = (const float*)d_in[30];
    const float* b2_rh  = (const float*)d_in[31];

    float* out = (float*)d_out;

    __half* hs_wr = (__half*)sym(g_hs_wr);
    __half* hs_rw = (__half*)sym(g_hs_rw);
    __half* hs_ci = (__half*)sym(g_hs_ci);
    __half* hs_ht = (__half*)sym(g_hs_ht);
    __half* hs_rh = (__half*)sym(g_hs_rh);
    __half* selfP = (__half*)sym(g_selfP);
    __half* selfA = (__half*)sym(g_selfA);
    __half* selfF = (__half*)sym(g_selfF);
    __half* a1h = (__half*)sym(g_a1h);
    __half* f1h = (__half*)sym(g_f1h);
    __half* p1h = (__half*)sym(g_p1h);
    __half* m2_wr = (__half*)sym(g_m2_wr);
    __half* m2_ci = (__half*)sym(g_m2_ci);
    __half* m2_rh = (__half*)sym(g_m2_rh);
    int* cnt = (int*)sym(g_cnt);
    int* rp_wr = (int*)sym(g_rp_wr);
    int* rp_rw = (int*)sym(g_rp_rw);
    int* rp_ci = (int*)sym(g_rp_ci);
    int* rp_ht = (int*)sym(g_rp_ht);
    int* rp_rh = (int*)sym(g_rp_rh);
    int* csr_wr = (int*)sym(g_csr_wr);
    int* csr_rw = (int*)sym(g_csr_rw);
    int* csr_ci = (int*)sym(g_csr_ci);
    int* csr_ht = (int*)sym(g_csr_ht);
    int* csr_rh = (int*)sym(g_csr_rh);
    float* wsumP = (float*)sym(g_wsumP);
    float* w2sum = (float*)sym(g_w2sum);

    // ---- fork: s1 does weight prep + layer-1 GEMMs ----
    cudaEventRecord(ev0, 0);
    cudaStreamWaitEvent(s1, ev0, 0);

    prep_weights<<<(HID * OUTF + 255) / 256, 256, 0, s1>>>(
        wr1_wr, wr1_ci, wr1_rh, wr2_wr, wr2_ci, wr2_rh,
        b1_wr, b1_ci, b1_rh, b2_wr, b2_ci, b2_rh);

    const int gP = (NP + 127) / 128, gA = (NA + 127) / 128, gF = (NF + 127) / 128;
    {
        GemmBatch bp;
        bp.B[0] = wl1_rw; bp.C[0] = hs_rw;
        bp.B[1] = wl1_ci; bp.C[1] = hs_ci;
        bp.B[2] = wl1_ht; bp.C[2] = hs_ht;
        bp.B[3] = wsumP;  bp.C[3] = selfP;
        gemm_tf32_f128<<<dim3(gP, 4), 256, 0, s1>>>(x_paper, bp, NP);
        GemmBatch ba;
        ba.B[0] = wl1_wr; ba.C[0] = hs_wr;
        ba.B[1] = wr1_rw; ba.C[1] = selfA;
        ba.B[2] = wl1_wr; ba.C[2] = hs_wr;
        ba.B[3] = wl1_wr; ba.C[3] = hs_wr;
        gemm_tf32_f128<<<dim3(gA, 2), 256, 0, s1>>>(x_author, ba, NA);
        GemmBatch bf;
        bf.B[0] = wl1_rh; bf.C[0] = hs_rh;
        bf.B[1] = wr1_ht; bf.C[1] = selfF;
        bf.B[2] = wl1_rh; bf.C[2] = hs_rh;
        bf.B[3] = wl1_rh; bf.C[3] = hs_rh;
        gemm_tf32_f128<<<dim3(gF, 2), 256, 0, s1>>>(x_field, bf, NF);
    }
    cudaEventRecord(ev1, s1);

    // ---- stream 0: CSR build ----
    cudaMemsetAsync(cnt, 0, sizeof(int) * CNT_TOT, 0);

    EJobs ep;
    ep.ei[0] = ei_wr; ep.E[0] = nE_wr;
    ep.ei[1] = ei_rw; ep.E[1] = nE_rw;
    ep.ei[2] = ei_ci; ep.E[2] = nE_ci;
    ep.ei[3] = ei_ht; ep.E[3] = nE_ht;
    ep.ei[4] = ei_rh; ep.E[4] = nE_rh;
    ep.bs[0] = 0;
    for (int i = 0; i < 5; ++i) ep.bs[i + 1] = ep.bs[i] + (ep.E[i] + 255) / 256;

    k_count_all<<<ep.bs[5], 256>>>(ep);
    k_blocksum_all<<<dim3((NP + 1023) / 1024, 5), 256>>>();
    k_scan_bsums_all<<<5, 256>>>();
    k_scan_write_all<<<dim3((NP + 1023) / 1024, 5), 256>>>();
    k_fill_all<<<ep.bs[5], 256>>>(ep);
    cudaEventRecord(ev2, 0);

    // ---- stream 0 chain: paper layer-1 -> layer-2 ci pull ----
    cudaStreamWaitEvent(0, ev1, 0);      // needs hs_* from s1
    auto wg = [](int n) { return (n * 32 + 255) / 256; };
    k_paper_warp<<<wg(NP), 256>>>();
    k_l2_warp<<<wg(NP), 256>>>(p1h, rp_ci, csr_ci, m2_ci, NP);

    // ---- s1 chain: author/field layer-1 -> layer-2 wr/rh pulls ----
    cudaStreamWaitEvent(s1, ev2, 0);     // needs CSR from stream 0
    k_af_warp<<<wg(NA), 256, 0, s1>>>(hs_rw, rp_rw, csr_rw, selfA, b1_rw, a1h, NA);
    k_l2_warp<<<wg(NP), 256, 0, s1>>>(a1h, rp_wr, csr_wr, m2_wr, NP);
    k_af_warp<<<wg(NF), 256, 0, s1>>>(hs_ht, rp_ht, csr_ht, selfF, b1_ht, f1h, NF);
    k_l2_warp<<<wg(NP), 256, 0, s1>>>(f1h, rp_rh, csr_rh, m2_rh, NP);
    cudaEventRecord(ev3, s1);

    // ---- join + output GEMM ----
    cudaStreamWaitEvent(0, ev3, 0);
    dim3 g2(gP, (OUTF + 63) / 64);
    gemm_out_tf32<<<g2, 256>>>(m2_wr, m2_ci, m2_rh, p1h,
                               wl2_wr, wl2_ci, wl2_rh, w2sum,
                               out, NP);
}

// round 8
// speedup vs baseline: 2.4943x; 1.2678x over previous
#include <cuda_runtime.h>
#include <cuda_fp16.h>
#include <cstdint>

#define NP 100000
#define NA 100000
#define NF 50000
#define FIN 128
#define HID 64
#define OUTF 349

#define E_WR 1000000
#define E_RW 1000000
#define E_CI 2000000
#define E_HT 1000000
#define E_RH 1000000

#define CNT_TOT (NP + NA + NP + NF + NP)   // 450000

// ---------------- scratch ----------------
static __device__ __align__(256) __half g_hs_wr[NA * HID];
static __device__ __align__(256) __half g_hs_rw[NP * HID];
static __device__ __align__(256) __half g_hs_ci[NP * HID];
static __device__ __align__(256) __half g_hs_ht[NP * HID];
static __device__ __align__(256) __half g_hs_rh[NF * HID];
static __device__ __align__(256) __half g_selfP[NP * HID];
static __device__ __align__(256) __half g_selfA[NA * HID];
static __device__ __align__(256) __half g_selfF[NF * HID];
static __device__ __align__(256) __half g_p1h[NP * HID];
static __device__ __align__(256) __half g_a1h[NA * HID];
static __device__ __align__(256) __half g_f1h[NF * HID];
static __device__ __align__(256) __half g_m2_wr[NP * HID];
static __device__ __align__(256) __half g_m2_ci[NP * HID];
static __device__ __align__(256) __half g_m2_rh[NP * HID];
// CSR machinery
static __device__ int g_cnt[CNT_TOT];
static __device__ int g_fl[CNT_TOT];
static __device__ int g_rp_wr[NP + 1], g_rp_rw[NA + 1], g_rp_ci[NP + 1], g_rp_ht[NF + 1], g_rp_rh[NP + 1];
static __device__ int g_csr_wr[E_WR], g_csr_rw[E_RW], g_csr_ci[E_CI], g_csr_ht[E_HT], g_csr_rh[E_RH];
static __device__ int g_bsumA[5][128];
// summed weights / biases
static __device__ __align__(256) float g_wsumP[FIN * HID];
static __device__ __align__(256) float g_w2sum[HID * OUTF];
static __device__ __align__(256) float g_bsum1[HID];
static __device__ __align__(256) float g_bsum2[OUTF];

__constant__ int c_n[5] = {NP, NA, NP, NF, NP};
__constant__ int c_off[5] = {0, NP, NP + NA, NP + NA + NP, NP + NA + NP + NF};

__device__ __forceinline__ int* rp_of(int ty) {
    switch (ty) {
        case 0: return g_rp_wr;
        case 1: return g_rp_rw;
        case 2: return g_rp_ci;
        case 3: return g_rp_ht;
        default: return g_rp_rh;
    }
}
__device__ __forceinline__ int* csr_of(int ty) {
    switch (ty) {
        case 0: return g_csr_wr;
        case 1: return g_csr_rw;
        case 2: return g_csr_ci;
        case 3: return g_csr_ht;
        default: return g_csr_rh;
    }
}

// ---------------- fp16 MMA helpers ----------------
__device__ __forceinline__ uint32_t packh2(float a, float b) {
    __half2 h = __floats2half2_rn(a, b);
    return *reinterpret_cast<uint32_t*>(&h);
}

__device__ __forceinline__ void mma_f16(float c[4], uint32_t a0, uint32_t a1,
                                        uint32_t a2, uint32_t a3,
                                        uint32_t b0, uint32_t b1) {
    asm volatile("mma.sync.aligned.m16n8k16.row.col.f32.f16.f16.f32 "
                 "{%0,%1,%2,%3}, {%4,%5,%6,%7}, {%8,%9}, {%0,%1,%2,%3};"
                 : "+f"(c[0]), "+f"(c[1]), "+f"(c[2]), "+f"(c[3])
                 : "r"(a0), "r"(a1), "r"(a2), "r"(a3), "r"(b0), "r"(b1));
}

// ---------------- weight/bias prep ----------------
__global__ void prep_weights(const float* __restrict__ wr1a, const float* __restrict__ wr1b,
                             const float* __restrict__ wr1c,
                             const float* __restrict__ wr2a, const float* __restrict__ wr2b,
                             const float* __restrict__ wr2c,
                             const float* __restrict__ b1a, const float* __restrict__ b1b,
                             const float* __restrict__ b1c,
                             const float* __restrict__ b2a, const float* __restrict__ b2b,
                             const float* __restrict__ b2c) {
    int i = blockIdx.x * blockDim.x + threadIdx.x;
    if (i < FIN * HID) g_wsumP[i] = wr1a[i] + wr1b[i] + wr1c[i];
    if (i < HID * OUTF) g_w2sum[i] = wr2a[i] + wr2b[i] + wr2c[i];
    if (i < HID) g_bsum1[i] = b1a[i] + b1b[i] + b1c[i];
    if (i < OUTF) g_bsum2[i] = b2a[i] + b2b[i] + b2c[i];
}

// ---------------- CSR build ----------------
struct EJobs {
    const int* ei[5];
    int E[5];
    int bs[6];
};

__global__ void k_count_all(EJobs ep) {
    int b = blockIdx.x;
    int ty = 0;
    while (b >= ep.bs[ty + 1]) ++ty;
    int e = (b - ep.bs[ty]) * 256 + threadIdx.x;
    if (e >= ep.E[ty]) return;
    int d = __ldg(ep.ei[ty] + ep.E[ty] + e);
    atomicAdd(g_cnt + c_off[ty] + d, 1);
}

__global__ void k_blocksum_all() {
    __shared__ int s[256];
    int ty = blockIdx.y;
    int n = c_n[ty];
    int base = blockIdx.x * 1024;
    if (base >= n) { if (threadIdx.x == 0) g_bsumA[ty][blockIdx.x] = 0; return; }
    const int* c = g_cnt + c_off[ty];
    int t = threadIdx.x;
    int v = 0;
#pragma unroll
    for (int j = 0; j < 4; ++j) {
        int i = base + t * 4 + j;
        if (i < n) v += c[i];
    }
    s[t] = v;
    __syncthreads();
    for (int o = 128; o > 0; o >>= 1) {
        if (t < o) s[t] += s[t + o];
        __syncthreads();
    }
    if (t == 0) g_bsumA[ty][blockIdx.x] = s[0];
}

__global__ void k_scan_bsums_all() {
    __shared__ int s[256];
    int ty = blockIdx.x;
    int n = c_n[ty];
    int nb = (n + 1023) / 1024;
    int t = threadIdx.x;
    int v = (t < nb) ? g_bsumA[ty][t] : 0;
    s[t] = v;
    __syncthreads();
    for (int o = 1; o < 256; o <<= 1) {
        int x = (t >= o) ? s[t - o] : 0;
        __syncthreads();
        s[t] += x;
        __syncthreads();
    }
    if (t < nb) g_bsumA[ty][t] = s[t] - v;
    if (t == 0) rp_of(ty)[n] = s[255];
}

__global__ void k_scan_write_all() {
    __shared__ int s[256];
    int ty = blockIdx.y;
    int n = c_n[ty];
    int base = blockIdx.x * 1024;
    if (base >= n) return;
    const int* c = g_cnt + c_off[ty];
    int* rowptr = rp_of(ty);
    int* fill = g_fl + c_off[ty];
    int t = threadIdx.x;
    int loc[4];
    int v = 0;
#pragma unroll
    for (int j = 0; j < 4; ++j) {
        int i = base + t * 4 + j;
        loc[j] = v;
        v += (i < n) ? c[i] : 0;
    }
    s[t] = v;
    __syncthreads();
    for (int o = 1; o < 256; o <<= 1) {
        int x = (t >= o) ? s[t - o] : 0;
        __syncthreads();
        s[t] += x;
        __syncthreads();
    }
    int ex = s[t] - v;
    int off = g_bsumA[ty][blockIdx.x] + ex;
#pragma unroll
    for (int j = 0; j < 4; ++j) {
        int i = base + t * 4 + j;
        if (i < n) {
            int r = off + loc[j];
            rowptr[i] = r;
            fill[i] = r;
        }
    }
}

__global__ void k_fill_all(EJobs ep) {
    int b = blockIdx.x;
    int ty = 0;
    while (b >= ep.bs[ty + 1]) ++ty;
    int e = (b - ep.bs[ty]) * 256 + threadIdx.x;
    if (e >= ep.E[ty]) return;
    int s = __ldg(ep.ei[ty] + e);
    int d = __ldg(ep.ei[ty] + ep.E[ty] + e);
    int pos = atomicAdd(g_fl + c_off[ty] + d, 1);
    csr_of(ty)[pos] = s;
}

// ---------------- warp-per-node pull: 4 edge-teams x 8 feature lanes ----------------
__device__ __forceinline__ void acc_h8(float acc[8], uint4 v) {
    float2 f0 = __half22float2(*reinterpret_cast<const __half2*>(&v.x));
    float2 f1 = __half22float2(*reinterpret_cast<const __half2*>(&v.y));
    float2 f2 = __half22float2(*reinterpret_cast<const __half2*>(&v.z));
    float2 f3 = __half22float2(*reinterpret_cast<const __half2*>(&v.w));
    acc[0] += f0.x; acc[1] += f0.y;
    acc[2] += f1.x; acc[3] += f1.y;
    acc[4] += f2.x; acc[5] += f2.y;
    acc[6] += f3.x; acc[7] += f3.y;
}

// After the shfl tree all 32 lanes hold the mean for their feature chunk c;
// result is ADDED into out[8].
__device__ __forceinline__ void pull_mean_warp_add(const __half* __restrict__ feat,
                                                   const int* __restrict__ rowptr,
                                                   const int* __restrict__ csr,
                                                   int g, int team, int c, float out[8]) {
    float acc[8];
#pragma unroll
    for (int i = 0; i < 8; ++i) acc[i] = 0.f;
    int beg = __ldg(rowptr + g), end = __ldg(rowptr + g + 1);
    int j = beg + team;
    for (; j + 4 < end; j += 8) {
        int s0 = __ldg(csr + j);
        int s1 = __ldg(csr + j + 4);
        uint4 v0 = *(const uint4*)(feat + (size_t)s0 * HID + c * 8);
        uint4 v1 = *(const uint4*)(feat + (size_t)s1 * HID + c * 8);
        acc_h8(acc, v0);
        acc_h8(acc, v1);
    }
    if (j < end) {
        int s0 = __ldg(csr + j);
        uint4 v0 = *(const uint4*)(feat + (size_t)s0 * HID + c * 8);
        acc_h8(acc, v0);
    }
#pragma unroll
    for (int i = 0; i < 8; ++i) {
        acc[i] += __shfl_xor_sync(0xffffffffu, acc[i], 8);
        acc[i] += __shfl_xor_sync(0xffffffffu, acc[i], 16);
    }
    float inv = 1.f / fmaxf((float)(end - beg), 1.f);
#pragma unroll
    for (int i = 0; i < 8; ++i) out[i] += acc[i] * inv;
}

__device__ __forceinline__ uint4 pack_h8v(const float v[8]) {
    uint4 o;
    *reinterpret_cast<__half2*>(&o.x) = __floats2half2_rn(v[0], v[1]);
    *reinterpret_cast<__half2*>(&o.y) = __floats2half2_rn(v[2], v[3]);
    *reinterpret_cast<__half2*>(&o.z) = __floats2half2_rn(v[4], v[5]);
    *reinterpret_cast<__half2*>(&o.w) = __floats2half2_rn(v[6], v[7]);
    return o;
}

// layer-1 paper: 3 pulls + self + bias + relu -> p1h
__global__ void k_paper_warp() {
    int wg = (blockIdx.x * blockDim.x + threadIdx.x) >> 5;
    if (wg >= NP) return;
    int lane = threadIdx.x & 31;
    int team = lane >> 3, c = lane & 7;
    float o[8];
    uint4 sv = *(const uint4*)(g_selfP + (size_t)wg * HID + c * 8);
#pragma unroll
    for (int i = 0; i < 8; ++i) o[i] = g_bsum1[c * 8 + i];
    acc_h8(o, sv);
    pull_mean_warp_add(g_hs_wr, g_rp_wr, g_csr_wr, wg, team, c, o);
    pull_mean_warp_add(g_hs_ci, g_rp_ci, g_csr_ci, wg, team, c, o);
    pull_mean_warp_add(g_hs_rh, g_rp_rh, g_csr_rh, wg, team, c, o);
    if (team == 0) {
#pragma unroll
        for (int i = 0; i < 8; ++i) o[i] = fmaxf(o[i], 0.f);
        *(uint4*)(g_p1h + (size_t)wg * HID + c * 8) = pack_h8v(o);
    }
}

// layer-1 author/field: 1 pull + self + bias + relu -> fp16 out
__global__ void k_af_warp(const __half* __restrict__ feat, const int* __restrict__ rowptr,
                          const int* __restrict__ csr, const __half* __restrict__ selfX,
                          const float* __restrict__ bias, __half* __restrict__ out, int n) {
    int wg = (blockIdx.x * blockDim.x + threadIdx.x) >> 5;
    if (wg >= n) return;
    int lane = threadIdx.x & 31;
    int team = lane >> 3, c = lane & 7;
    float o[8];
    uint4 sv = *(const uint4*)(selfX + (size_t)wg * HID + c * 8);
#pragma unroll
    for (int i = 0; i < 8; ++i) o[i] = bias[c * 8 + i];
    acc_h8(o, sv);
    pull_mean_warp_add(feat, rowptr, csr, wg, team, c, o);
    if (team == 0) {
#pragma unroll
        for (int i = 0; i < 8; ++i) o[i] = fmaxf(o[i], 0.f);
        *(uint4*)(out + (size_t)wg * HID + c * 8) = pack_h8v(o);
    }
}

// layer-2 single pull -> fp16 mean buffer
__global__ void k_l2_warp(const __half* __restrict__ feat, const int* __restrict__ rowptr,
                          const int* __restrict__ csr, __half* __restrict__ out, int n) {
    int wg = (blockIdx.x * blockDim.x + threadIdx.x) >> 5;
    if (wg >= n) return;
    int lane = threadIdx.x & 31;
    int team = lane >> 3, c = lane & 7;
    float o[8] = {};
    pull_mean_warp_add(feat, rowptr, csr, wg, team, c, o);
    if (team == 0)
        *(uint4*)(out + (size_t)wg * HID + c * 8) = pack_h8v(o);
}

// ---------------- fp16 HMMA GEMM: C[M,64](fp16) = A[M,128] @ B[128,64], batched ----------------
// SMEM layout: packed half2 along k, stride 20 uint32 per row.
struct GemmBatch {
    const float* B[4];
    __half* C[4];
};

__global__ void gemm_f16_f128(const float* __restrict__ A, GemmBatch p, int M) {
    __shared__ uint32_t As[128 * 20];
    __shared__ uint32_t Bs[64 * 20];
    const float* __restrict__ Bp = p.B[blockIdx.y];
    __half* __restrict__ Cp = p.C[blockIdx.y];
    const int t = threadIdx.x;
    const int wid = t >> 5, lane = t & 31;
    const int g = lane >> 2, tg = lane & 3;
    const int rowBase = blockIdx.x * 128;
    const int wrow = wid * 16;

    float c[8][4] = {};

    for (int kb = 0; kb < 4; ++kb) {
        // A: 128 rows x 32 k floats -> packed half2
#pragma unroll
        for (int j = 0; j < 4; ++j) {
            int idx = t + j * 256;          // 0..1023
            int r = idx >> 3, q = idx & 7;  // q: float4 slot within 32-float row
            int gr = rowBase + r;
            if (gr >= M) gr = M - 1;
            float4 av = *(const float4*)(A + (size_t)gr * FIN + kb * 32 + q * 4);
            As[r * 20 + q * 2 + 0] = packh2(av.x, av.y);
            As[r * 20 + q * 2 + 1] = packh2(av.z, av.w);
        }
        // B: 32 k x 64 n -> Bs[n][kh] packed (B[2kh][n], B[2kh+1][n])
#pragma unroll
        for (int j = 0; j < 4; ++j) {
            int idx = t + j * 256;          // 0..1023
            int n = idx & 63, kh = idx >> 6;
            float v0 = Bp[(size_t)(kb * 32 + 2 * kh) * HID + n];
            float v1 = Bp[(size_t)(kb * 32 + 2 * kh + 1) * HID + n];
            Bs[n * 20 + kh] = packh2(v0, v1);
        }
        __syncthreads();
#pragma unroll
        for (int ks = 0; ks < 2; ++ks) {
            int kh0 = ks * 8;
            uint32_t a0 = As[(wrow + g) * 20 + kh0 + tg];
            uint32_t a1 = As[(wrow + g + 8) * 20 + kh0 + tg];
            uint32_t a2 = As[(wrow + g) * 20 + kh0 + tg + 4];
            uint32_t a3 = As[(wrow + g + 8) * 20 + kh0 + tg + 4];
#pragma unroll
            for (int nt = 0; nt < 8; ++nt) {
                int n = nt * 8 + g;
                uint32_t b0 = Bs[n * 20 + kh0 + tg];
                uint32_t b1 = Bs[n * 20 + kh0 + tg + 4];
                mma_f16(c[nt], a0, a1, a2, a3, b0, b1);
            }
        }
        __syncthreads();
    }

    int r0 = rowBase + wrow + g, r1 = r0 + 8;
#pragma unroll
    for (int nt = 0; nt < 8; ++nt) {
        int col = nt * 8 + tg * 2;
        if (r0 < M)
            *reinterpret_cast<__half2*>(Cp + (size_t)r0 * HID + col) = __floats2half2_rn(c[nt][0], c[nt][1]);
        if (r1 < M)
            *reinterpret_cast<__half2*>(Cp + (size_t)r1 * HID + col) = __floats2half2_rn(c[nt][2], c[nt][3]);
    }
}

// ---------------- fp16 HMMA output GEMM: fp16 A inputs, fp32 out ----------------
__global__ void gemm_out_f16(const __half* __restrict__ A0, const __half* __restrict__ A1,
                             const __half* __restrict__ A2, const __half* __restrict__ A3,
                             const float* __restrict__ B0, const float* __restrict__ B1,
                             const float* __restrict__ B2, const float* __restrict__ B3,
                             float* __restrict__ C, int M) {
    __shared__ uint32_t As[128 * 20];
    __shared__ uint32_t Bs[64 * 20];
    const int t = threadIdx.x;
    const int wid = t >> 5, lane = t & 31;
    const int g = lane >> 2, tg = lane & 3;
    const int rowBase = blockIdx.x * 128;
    const int colBase = blockIdx.y * 64;
    const int wrow = wid * 16;

    const __half* Aps[4] = {A0, A1, A2, A3};
    const float* Bps[4] = {B0, B1, B2, B3};

    float c[8][4] = {};

    for (int m = 0; m < 4; ++m) {
        const __half* __restrict__ Ap = Aps[m];
        const float* __restrict__ Bp = Bps[m];
        for (int kb = 0; kb < 2; ++kb) {
            // A: 128 rows x 32 halves — straight uint4 copy (already packed half2)
#pragma unroll
            for (int j = 0; j < 2; ++j) {
                int idx = t + j * 256;      // 0..511
                int r = idx >> 2, q = idx & 3;  // q: uint4 slot (8 halves)
                int gr = rowBase + r;
                if (gr >= M) gr = M - 1;
                uint4 hv = *(const uint4*)(Ap + (size_t)gr * HID + kb * 32 + q * 8);
                uint32_t* d = &As[r * 20 + q * 4];
                d[0] = hv.x; d[1] = hv.y; d[2] = hv.z; d[3] = hv.w;
            }
            // B: 32 k x 64 n (OUTF stride, col guard) -> packed half2
#pragma unroll
            for (int j = 0; j < 4; ++j) {
                int idx = t + j * 256;
                int n = idx & 63, kh = idx >> 6;
                int col = colBase + n;
                float v0 = 0.f, v1 = 0.f;
                if (col < OUTF) {
                    v0 = Bp[(size_t)(kb * 32 + 2 * kh) * OUTF + col];
                    v1 = Bp[(size_t)(kb * 32 + 2 * kh + 1) * OUTF + col];
                }
                Bs[n * 20 + kh] = packh2(v0, v1);
            }
            __syncthreads();
#pragma unroll
            for (int ks = 0; ks < 2; ++ks) {
                int kh0 = ks * 8;
                uint32_t a0 = As[(wrow + g) * 20 + kh0 + tg];
                uint32_t a1 = As[(wrow + g + 8) * 20 + kh0 + tg];
                uint32_t a2 = As[(wrow + g) * 20 + kh0 + tg + 4];
                uint32_t a3 = As[(wrow + g + 8) * 20 + kh0 + tg + 4];
#pragma unroll
                for (int nt = 0; nt < 8; ++nt) {
                    int n = nt * 8 + g;
                    uint32_t b0 = Bs[n * 20 + kh0 + tg];
                    uint32_t b1 = Bs[n * 20 + kh0 + tg + 4];
                    mma_f16(c[nt], a0, a1, a2, a3, b0, b1);
                }
            }
            __syncthreads();
        }
    }

    int r0 = rowBase + wrow + g, r1 = r0 + 8;
#pragma unroll
    for (int nt = 0; nt < 8; ++nt) {
        int col = colBase + nt * 8 + tg * 2;
        if (col < OUTF) {
            float bia = g_bsum2[col];
            if (r0 < M) C[(size_t)r0 * OUTF + col] = c[nt][0] + bia;
            if (r1 < M) C[(size_t)r1 * OUTF + col] = c[nt][2] + bia;
        }
        if (col + 1 < OUTF) {
            float bib = g_bsum2[col + 1];
            if (r0 < M) C[(size_t)r0 * OUTF + col + 1] = c[nt][1] + bib;
            if (r1 < M) C[(size_t)r1 * OUTF + col + 1] = c[nt][3] + bib;
        }
    }
}

// ---------------- host launcher ----------------
static inline void* sym(const void* s) {
    void* p = nullptr;
    cudaGetSymbolAddress(&p, s);
    return p;
}

extern "C" void kernel_launch(void* const* d_in, const int* in_sizes, int n_in,
                              void* d_out, int out_size) {
    static cudaStream_t s1 = nullptr, s2 = nullptr;
    static cudaEvent_t ev0 = nullptr, ev1 = nullptr, ev2 = nullptr, ev3 = nullptr, ev4 = nullptr;
    if (s1 == nullptr) {
        cudaStreamCreateWithFlags(&s1, cudaStreamNonBlocking);
        cudaStreamCreateWithFlags(&s2, cudaStreamNonBlocking);
        cudaEventCreateWithFlags(&ev0, cudaEventDisableTiming);
        cudaEventCreateWithFlags(&ev1, cudaEventDisableTiming);
        cudaEventCreateWithFlags(&ev2, cudaEventDisableTiming);
        cudaEventCreateWithFlags(&ev3, cudaEventDisableTiming);
        cudaEventCreateWithFlags(&ev4, cudaEventDisableTiming);
    }

    const float* x_paper  = (const float*)d_in[0];
    const float* x_author = (const float*)d_in[1];
    const float* x_field  = (const float*)d_in[2];
    const int* ei_wr = (const int*)d_in[3];
    const int* ei_rw = (const int*)d_in[4];
    const int* ei_ci = (const int*)d_in[5];
    const int* ei_ht = (const int*)d_in[6];
    const int* ei_rh = (const int*)d_in[7];
    const int nE_wr = in_sizes[3] / 2;
    const int nE_rw = in_sizes[4] / 2;
    const int nE_ci = in_sizes[5] / 2;
    const int nE_ht = in_sizes[6] / 2;
    const int nE_rh = in_sizes[7] / 2;

    const float* wl1_wr = (const float*)d_in[8];
    const float* wr1_wr = (const float*)d_in[9];
    const float* b1_wr  = (const float*)d_in[10];
    const float* wl1_rw = (const float*)d_in[11];
    const float* wr1_rw = (const float*)d_in[12];
    const float* b1_rw  = (const float*)d_in[13];
    const float* wl1_ci = (const float*)d_in[14];
    const float* wr1_ci = (const float*)d_in[15];
    const float* b1_ci  = (const float*)d_in[16];
    const float* wl1_ht = (const float*)d_in[17];
    const float* wr1_ht = (const float*)d_in[18];
    const float* b1_ht  = (const float*)d_in[19];
    const float* wl1_rh = (const float*)d_in[20];
    const float* wr1_rh = (const float*)d_in[21];
    const float* b1_rh  = (const float*)d_in[22];
    const float* wl2_wr = (const float*)d_in[23];
    const float* wr2_wr = (const float*)d_in[24];
    const float* b2_wr  = (const float*)d_in[25];
    const float* wl2_ci = (const float*)d_in[26];
    const float* wr2_ci = (const float*)d_in[27];
    const float* b2_ci  = (const float*)d_in[28];
    const float* wl2_rh = (const float*)d_in[29];
    const float* wr2_rh = (const float*)d_in[30];
    const float* b2_rh  = (const float*)d_in[31];

    float* out = (float*)d_out;

    __half* hs_wr = (__half*)sym(g_hs_wr);
    __half* hs_rw = (__half*)sym(g_hs_rw);
    __half* hs_ci = (__half*)sym(g_hs_ci);
    __half* hs_ht = (__half*)sym(g_hs_ht);
    __half* hs_rh = (__half*)sym(g_hs_rh);
    __half* selfP = (__half*)sym(g_selfP);
    __half* selfA = (__half*)sym(g_selfA);
    __half* selfF = (__half*)sym(g_selfF);
    __half* a1h = (__half*)sym(g_a1h);
    __half* f1h = (__half*)sym(g_f1h);
    __half* p1h = (__half*)sym(g_p1h);
    __half* m2_wr = (__half*)sym(g_m2_wr);
    __half* m2_ci = (__half*)sym(g_m2_ci);
    __half* m2_rh = (__half*)sym(g_m2_rh);
    int* cnt = (int*)sym(g_cnt);
    int* rp_wr = (int*)sym(g_rp_wr);
    int* rp_rw = (int*)sym(g_rp_rw);
    int* rp_ci = (int*)sym(g_rp_ci);
    int* rp_ht = (int*)sym(g_rp_ht);
    int* rp_rh = (int*)sym(g_rp_rh);
    int* csr_wr = (int*)sym(g_csr_wr);
    int* csr_rw = (int*)sym(g_csr_rw);
    int* csr_ci = (int*)sym(g_csr_ci);
    int* csr_ht = (int*)sym(g_csr_ht);
    int* csr_rh = (int*)sym(g_csr_rh);
    float* wsumP = (float*)sym(g_wsumP);
    float* w2sum = (float*)sym(g_w2sum);

    // ---- fork: s1 does weight prep + layer-1 GEMMs ----
    cudaEventRecord(ev0, 0);
    cudaStreamWaitEvent(s1, ev0, 0);

    prep_weights<<<(HID * OUTF + 255) / 256, 256, 0, s1>>>(
        wr1_wr, wr1_ci, wr1_rh, wr2_wr, wr2_ci, wr2_rh,
        b1_wr, b1_ci, b1_rh, b2_wr, b2_ci, b2_rh);

    const int gP = (NP + 127) / 128, gA = (NA + 127) / 128, gF = (NF + 127) / 128;
    {
        GemmBatch bp;
        bp.B[0] = wl1_rw; bp.C[0] = hs_rw;
        bp.B[1] = wl1_ci; bp.C[1] = hs_ci;
        bp.B[2] = wl1_ht; bp.C[2] = hs_ht;
        bp.B[3] = wsumP;  bp.C[3] = selfP;
        gemm_f16_f128<<<dim3(gP, 4), 256, 0, s1>>>(x_paper, bp, NP);
        GemmBatch ba;
        ba.B[0] = wl1_wr; ba.C[0] = hs_wr;
        ba.B[1] = wr1_rw; ba.C[1] = selfA;
        ba.B[2] = wl1_wr; ba.C[2] = hs_wr;
        ba.B[3] = wl1_wr; ba.C[3] = hs_wr;
        gemm_f16_f128<<<dim3(gA, 2), 256, 0, s1>>>(x_author, ba, NA);
        GemmBatch bf;
        bf.B[0] = wl1_rh; bf.C[0] = hs_rh;
        bf.B[1] = wr1_ht; bf.C[1] = selfF;
        bf.B[2] = wl1_rh; bf.C[2] = hs_rh;
        bf.B[3] = wl1_rh; bf.C[3] = hs_rh;
        gemm_f16_f128<<<dim3(gF, 2), 256, 0, s1>>>(x_field, bf, NF);
    }
    cudaEventRecord(ev1, s1);

    // ---- stream 0: CSR build ----
    cudaMemsetAsync(cnt, 0, sizeof(int) * CNT_TOT, 0);

    EJobs ep;
    ep.ei[0] = ei_wr; ep.E[0] = nE_wr;
    ep.ei[1] = ei_rw; ep.E[1] = nE_rw;
    ep.ei[2] = ei_ci; ep.E[2] = nE_ci;
    ep.ei[3] = ei_ht; ep.E[3] = nE_ht;
    ep.ei[4] = ei_rh; ep.E[4] = nE_rh;
    ep.bs[0] = 0;
    for (int i = 0; i < 5; ++i) ep.bs[i + 1] = ep.bs[i] + (ep.E[i] + 255) / 256;

    k_count_all<<<ep.bs[5], 256>>>(ep);
    k_blocksum_all<<<dim3((NP + 1023) / 1024, 5), 256>>>();
    k_scan_bsums_all<<<5, 256>>>();
    k_scan_write_all<<<dim3((NP + 1023) / 1024, 5), 256>>>();
    k_fill_all<<<ep.bs[5], 256>>>(ep);
    cudaEventRecord(ev2, 0);

    auto wg = [](int n) { return (n * 32 + 255) / 256; };

    // ---- stream 0 chain: paper layer-1 -> layer-2 ci pull ----
    cudaStreamWaitEvent(0, ev1, 0);      // needs hs_* from s1
    k_paper_warp<<<wg(NP), 256>>>();
    k_l2_warp<<<wg(NP), 256>>>(p1h, rp_ci, csr_ci, m2_ci, NP);

    // ---- s1 chain: author layer-1 -> layer-2 wr pull ----
    cudaStreamWaitEvent(s1, ev2, 0);     // needs CSR from stream 0
    k_af_warp<<<wg(NA), 256, 0, s1>>>(hs_rw, rp_rw, csr_rw, selfA, b1_rw, a1h, NA);
    k_l2_warp<<<wg(NP), 256, 0, s1>>>(a1h, rp_wr, csr_wr, m2_wr, NP);
    cudaEventRecord(ev3, s1);

    // ---- s2 chain: field layer-1 -> layer-2 rh pull ----
    cudaStreamWaitEvent(s2, ev1, 0);
    cudaStreamWaitEvent(s2, ev2, 0);
    k_af_warp<<<wg(NF), 256, 0, s2>>>(hs_ht, rp_ht, csr_ht, selfF, b1_ht, f1h, NF);
    k_l2_warp<<<wg(NP), 256, 0, s2>>>(f1h, rp_rh, csr_rh, m2_rh, NP);
    cudaEventRecord(ev4, s2);

    // ---- join + output GEMM ----
    cudaStreamWaitEvent(0, ev3, 0);
    cudaStreamWaitEvent(0, ev4, 0);
    dim3 g2(gP, (OUTF + 63) / 64);
    gemm_out_f16<<<g2, 256>>>(m2_wr, m2_ci, m2_rh, p1h,
                              wl2_wr, wl2_ci, wl2_rh, w2sum,
                              out, NP);
}

// round 9
// speedup vs baseline: 2.6195x; 1.0502x over previous
#include <cuda_runtime.h>
#include <cuda_fp16.h>
#include <cstdint>

#define NP 100000
#define NA 100000
#define NF 50000
#define FIN 128
#define HID 64
#define OUTF 349

#define E_WR 1000000
#define E_RW 1000000
#define E_CI 2000000
#define E_HT 1000000
#define E_RH 1000000

#define CNT_TOT (NP + NA + NP + NF + NP)   // 450000

// ---------------- scratch ----------------
static __device__ __align__(256) __half g_hs_wr[NA * HID];
static __device__ __align__(256) __half g_hs_rw[NP * HID];
static __device__ __align__(256) __half g_hs_ci[NP * HID];
static __device__ __align__(256) __half g_hs_ht[NP * HID];
static __device__ __align__(256) __half g_hs_rh[NF * HID];
static __device__ __align__(256) __half g_selfP[NP * HID];
static __device__ __align__(256) __half g_selfA[NA * HID];
static __device__ __align__(256) __half g_selfF[NF * HID];
static __device__ __align__(256) __half g_p1h[NP * HID];
static __device__ __align__(256) __half g_a1h[NA * HID];
static __device__ __align__(256) __half g_f1h[NF * HID];
static __device__ __align__(256) __half g_m2_wr[NP * HID];
static __device__ __align__(256) __half g_m2_ci[NP * HID];
static __device__ __align__(256) __half g_m2_rh[NP * HID];
// CSR machinery
static __device__ int g_cnt[CNT_TOT];
static __device__ int g_fl[CNT_TOT];
static __device__ int g_rp_wr[NP + 1], g_rp_rw[NA + 1], g_rp_ci[NP + 1], g_rp_ht[NF + 1], g_rp_rh[NP + 1];
static __device__ int g_csr_wr[E_WR], g_csr_rw[E_RW], g_csr_ci[E_CI], g_csr_ht[E_HT], g_csr_rh[E_RH];
static __device__ int g_bsumA[5][128];
// summed weights / biases
static __device__ __align__(256) float g_wsumP[FIN * HID];
static __device__ __align__(256) float g_w2sum[HID * OUTF];
static __device__ __align__(256) float g_bsum1[HID];
static __device__ __align__(256) float g_bsum2[OUTF];

__constant__ int c_n[5] = {NP, NA, NP, NF, NP};
__constant__ int c_off[5] = {0, NP, NP + NA, NP + NA + NP, NP + NA + NP + NF};

__device__ __forceinline__ int* rp_of(int ty) {
    switch (ty) {
        case 0: return g_rp_wr;
        case 1: return g_rp_rw;
        case 2: return g_rp_ci;
        case 3: return g_rp_ht;
        default: return g_rp_rh;
    }
}
__device__ __forceinline__ int* csr_of(int ty) {
    switch (ty) {
        case 0: return g_csr_wr;
        case 1: return g_csr_rw;
        case 2: return g_csr_ci;
        case 3: return g_csr_ht;
        default: return g_csr_rh;
    }
}

// ---------------- fp16 MMA helpers ----------------
__device__ __forceinline__ uint32_t packh2(float a, float b) {
    __half2 h = __floats2half2_rn(a, b);
    return *reinterpret_cast<uint32_t*>(&h);
}

__device__ __forceinline__ void mma_f16(float c[4], uint32_t a0, uint32_t a1,
                                        uint32_t a2, uint32_t a3,
                                        uint32_t b0, uint32_t b1) {
    asm volatile("mma.sync.aligned.m16n8k16.row.col.f32.f16.f16.f32 "
                 "{%0,%1,%2,%3}, {%4,%5,%6,%7}, {%8,%9}, {%0,%1,%2,%3};"
                 : "+f"(c[0]), "+f"(c[1]), "+f"(c[2]), "+f"(c[3])
                 : "r"(a0), "r"(a1), "r"(a2), "r"(a3), "r"(b0), "r"(b1));
}

// ---------------- weight/bias prep ----------------
__global__ void prep_weights(const float* __restrict__ wr1a, const float* __restrict__ wr1b,
                             const float* __restrict__ wr1c,
                             const float* __restrict__ wr2a, const float* __restrict__ wr2b,
                             const float* __restrict__ wr2c,
                             const float* __restrict__ b1a, const float* __restrict__ b1b,
                             const float* __restrict__ b1c,
                             const float* __restrict__ b2a, const float* __restrict__ b2b,
                             const float* __restrict__ b2c) {
    int i = blockIdx.x * blockDim.x + threadIdx.x;
    if (i < FIN * HID) g_wsumP[i] = wr1a[i] + wr1b[i] + wr1c[i];
    if (i < HID * OUTF) g_w2sum[i] = wr2a[i] + wr2b[i] + wr2c[i];
    if (i < HID) g_bsum1[i] = b1a[i] + b1b[i] + b1c[i];
    if (i < OUTF) g_bsum2[i] = b2a[i] + b2b[i] + b2c[i];
}

// ---------------- CSR build ----------------
struct EJobs {
    const int* ei[5];
    int E[5];
    int bs[6];
};

__global__ void k_count_all(EJobs ep) {
    int b = blockIdx.x;
    int ty = 0;
    while (b >= ep.bs[ty + 1]) ++ty;
    int e = (b - ep.bs[ty]) * 256 + threadIdx.x;
    if (e >= ep.E[ty]) return;
    int d = __ldg(ep.ei[ty] + ep.E[ty] + e);
    atomicAdd(g_cnt + c_off[ty] + d, 1);
}

__global__ void k_blocksum_all() {
    __shared__ int s[256];
    int ty = blockIdx.y;
    int n = c_n[ty];
    int base = blockIdx.x * 1024;
    if (base >= n) { if (threadIdx.x == 0) g_bsumA[ty][blockIdx.x] = 0; return; }
    const int* c = g_cnt + c_off[ty];
    int t = threadIdx.x;
    int v = 0;
#pragma unroll
    for (int j = 0; j < 4; ++j) {
        int i = base + t * 4 + j;
        if (i < n) v += c[i];
    }
    s[t] = v;
    __syncthreads();
    for (int o = 128; o > 0; o >>= 1) {
        if (t < o) s[t] += s[t + o];
        __syncthreads();
    }
    if (t == 0) g_bsumA[ty][blockIdx.x] = s[0];
}

__global__ void k_scan_bsums_all() {
    __shared__ int s[256];
    int ty = blockIdx.x;
    int n = c_n[ty];
    int nb = (n + 1023) / 1024;
    int t = threadIdx.x;
    int v = (t < nb) ? g_bsumA[ty][t] : 0;
    s[t] = v;
    __syncthreads();
    for (int o = 1; o < 256; o <<= 1) {
        int x = (t >= o) ? s[t - o] : 0;
        __syncthreads();
        s[t] += x;
        __syncthreads();
    }
    if (t < nb) g_bsumA[ty][t] = s[t] - v;
    if (t == 0) rp_of(ty)[n] = s[255];
}

__global__ void k_scan_write_all() {
    __shared__ int s[256];
    int ty = blockIdx.y;
    int n = c_n[ty];
    int base = blockIdx.x * 1024;
    if (base >= n) return;
    const int* c = g_cnt + c_off[ty];
    int* rowptr = rp_of(ty);
    int* fill = g_fl + c_off[ty];
    int t = threadIdx.x;
    int loc[4];
    int v = 0;
#pragma unroll
    for (int j = 0; j < 4; ++j) {
        int i = base + t * 4 + j;
        loc[j] = v;
        v += (i < n) ? c[i] : 0;
    }
    s[t] = v;
    __syncthreads();
    for (int o = 1; o < 256; o <<= 1) {
        int x = (t >= o) ? s[t - o] : 0;
        __syncthreads();
        s[t] += x;
        __syncthreads();
    }
    int ex = s[t] - v;
    int off = g_bsumA[ty][blockIdx.x] + ex;
#pragma unroll
    for (int j = 0; j < 4; ++j) {
        int i = base + t * 4 + j;
        if (i < n) {
            int r = off + loc[j];
            rowptr[i] = r;
            fill[i] = r;
        }
    }
}

__global__ void k_fill_all(EJobs ep) {
    int b = blockIdx.x;
    int ty = 0;
    while (b >= ep.bs[ty + 1]) ++ty;
    int e = (b - ep.bs[ty]) * 256 + threadIdx.x;
    if (e >= ep.E[ty]) return;
    int s = __ldg(ep.ei[ty] + e);
    int d = __ldg(ep.ei[ty] + ep.E[ty] + e);
    int pos = atomicAdd(g_fl + c_off[ty] + d, 1);
    csr_of(ty)[pos] = s;
}

// ---------------- pull primitives ----------------
// acc += half8(v) * s
__device__ __forceinline__ void acc_h8_s(float acc[8], uint4 v, float s) {
    float2 f0 = __half22float2(*reinterpret_cast<const __half2*>(&v.x));
    float2 f1 = __half22float2(*reinterpret_cast<const __half2*>(&v.y));
    float2 f2 = __half22float2(*reinterpret_cast<const __half2*>(&v.z));
    float2 f3 = __half22float2(*reinterpret_cast<const __half2*>(&v.w));
    acc[0] += f0.x * s; acc[1] += f0.y * s;
    acc[2] += f1.x * s; acc[3] += f1.y * s;
    acc[4] += f2.x * s; acc[5] += f2.y * s;
    acc[6] += f3.x * s; acc[7] += f3.y * s;
}

__device__ __forceinline__ void acc_h8(float acc[8], uint4 v) {
    float2 f0 = __half22float2(*reinterpret_cast<const __half2*>(&v.x));
    float2 f1 = __half22float2(*reinterpret_cast<const __half2*>(&v.y));
    float2 f2 = __half22float2(*reinterpret_cast<const __half2*>(&v.z));
    float2 f3 = __half22float2(*reinterpret_cast<const __half2*>(&v.w));
    acc[0] += f0.x; acc[1] += f0.y;
    acc[2] += f1.x; acc[3] += f1.y;
    acc[4] += f2.x; acc[5] += f2.y;
    acc[6] += f3.x; acc[7] += f3.y;
}

__device__ __forceinline__ void shfl_reduce8(float acc[8]) {
#pragma unroll
    for (int i = 0; i < 8; ++i) {
        acc[i] += __shfl_xor_sync(0xffffffffu, acc[i], 8);
        acc[i] += __shfl_xor_sync(0xffffffffu, acc[i], 16);
    }
}

__device__ __forceinline__ uint4 pack_h8v(const float v[8]) {
    uint4 o;
    *reinterpret_cast<__half2*>(&o.x) = __floats2half2_rn(v[0], v[1]);
    *reinterpret_cast<__half2*>(&o.y) = __floats2half2_rn(v[2], v[3]);
    *reinterpret_cast<__half2*>(&o.z) = __floats2half2_rn(v[4], v[5]);
    *reinterpret_cast<__half2*>(&o.w) = __floats2half2_rn(v[6], v[7]);
    return o;
}

// branchless single-list pull: 4 clamp-indexed loads per iteration, scaled add.
__device__ __forceinline__ void pull1_scaled(const __half* __restrict__ feat,
                                             const int* __restrict__ csr,
                                             int beg, int end, int team, int c,
                                             float inv, float acc[8]) {
    int j = beg + team;
    while (j < end) {
        bool p1 = j + 4 < end, p2 = j + 8 < end, p3 = j + 12 < end;
        int i0 = j;
        int i1 = p1 ? j + 4 : i0;
        int i2 = p2 ? j + 8 : i0;
        int i3 = p3 ? j + 12 : i0;
        int s0 = __ldg(csr + i0);
        int s1 = __ldg(csr + i1);
        int s2 = __ldg(csr + i2);
        int s3 = __ldg(csr + i3);
        uint4 v0 = *(const uint4*)(feat + (size_t)s0 * HID + c * 8);
        uint4 v1 = *(const uint4*)(feat + (size_t)s1 * HID + c * 8);
        uint4 v2 = *(const uint4*)(feat + (size_t)s2 * HID + c * 8);
        uint4 v3 = *(const uint4*)(feat + (size_t)s3 * HID + c * 8);
        acc_h8_s(acc, v0, inv);
        acc_h8_s(acc, v1, p1 ? inv : 0.f);
        acc_h8_s(acc, v2, p2 ? inv : 0.f);
        acc_h8_s(acc, v3, p3 ? inv : 0.f);
        j += 16;
    }
}

// layer-1 paper: 3 edge lists fused in one loop (6 gathers/iter in flight),
// one scaled accumulator, one shfl tree.
__global__ void k_paper_warp() {
    int wg = (blockIdx.x * blockDim.x + threadIdx.x) >> 5;
    if (wg >= NP) return;
    int lane = threadIdx.x & 31;
    int team = lane >> 3, c = lane & 7;

    int bw = __ldg(g_rp_wr + wg), ew = __ldg(g_rp_wr + wg + 1);
    int bc = __ldg(g_rp_ci + wg), ec = __ldg(g_rp_ci + wg + 1);
    int br = __ldg(g_rp_rh + wg), er = __ldg(g_rp_rh + wg + 1);
    float invw = 1.f / fmaxf((float)(ew - bw), 1.f);
    float invc = 1.f / fmaxf((float)(ec - bc), 1.f);
    float invr = 1.f / fmaxf((float)(er - br), 1.f);

    float acc[8] = {};
    int jw = bw + team, jc = bc + team, jr = br + team;
    while (jw < ew || jc < ec || jr < er) {
        bool pw0 = jw < ew, pw1 = jw + 4 < ew;
        bool pc0 = jc < ec, pc1 = jc + 4 < ec;
        bool pr0 = jr < er, pr1 = jr + 4 < er;
        int iw0 = pw0 ? jw : 0, iw1 = pw1 ? jw + 4 : iw0;
        int ic0 = pc0 ? jc : 0, ic1 = pc1 ? jc + 4 : ic0;
        int ir0 = pr0 ? jr : 0, ir1 = pr1 ? jr + 4 : ir0;
        int sw0 = __ldg(g_csr_wr + iw0), sw1 = __ldg(g_csr_wr + iw1);
        int sc0 = __ldg(g_csr_ci + ic0), sc1 = __ldg(g_csr_ci + ic1);
        int sr0 = __ldg(g_csr_rh + ir0), sr1 = __ldg(g_csr_rh + ir1);
        uint4 vw0 = *(const uint4*)(g_hs_wr + (size_t)sw0 * HID + c * 8);
        uint4 vw1 = *(const uint4*)(g_hs_wr + (size_t)sw1 * HID + c * 8);
        uint4 vc0 = *(const uint4*)(g_hs_ci + (size_t)sc0 * HID + c * 8);
        uint4 vc1 = *(const uint4*)(g_hs_ci + (size_t)sc1 * HID + c * 8);
        uint4 vr0 = *(const uint4*)(g_hs_rh + (size_t)sr0 * HID + c * 8);
        uint4 vr1 = *(const uint4*)(g_hs_rh + (size_t)sr1 * HID + c * 8);
        acc_h8_s(acc, vw0, pw0 ? invw : 0.f);
        acc_h8_s(acc, vw1, pw1 ? invw : 0.f);
        acc_h8_s(acc, vc0, pc0 ? invc : 0.f);
        acc_h8_s(acc, vc1, pc1 ? invc : 0.f);
        acc_h8_s(acc, vr0, pr0 ? invr : 0.f);
        acc_h8_s(acc, vr1, pr1 ? invr : 0.f);
        jw += 8; jc += 8; jr += 8;
    }
    shfl_reduce8(acc);
    if (team == 0) {
        uint4 sv = *(const uint4*)(g_selfP + (size_t)wg * HID + c * 8);
        acc_h8(acc, sv);
        float o[8];
#pragma unroll
        for (int i = 0; i < 8; ++i)
            o[i] = fmaxf(acc[i] + g_bsum1[c * 8 + i], 0.f);
        *(uint4*)(g_p1h + (size_t)wg * HID + c * 8) = pack_h8v(o);
    }
}

// layer-1 author/field: 1 pull + self + bias + relu -> fp16 out
__global__ void k_af_warp(const __half* __restrict__ feat, const int* __restrict__ rowptr,
                          const int* __restrict__ csr, const __half* __restrict__ selfX,
                          const float* __restrict__ bias, __half* __restrict__ out, int n) {
    int wg = (blockIdx.x * blockDim.x + threadIdx.x) >> 5;
    if (wg >= n) return;
    int lane = threadIdx.x & 31;
    int team = lane >> 3, c = lane & 7;
    int beg = __ldg(rowptr + wg), end = __ldg(rowptr + wg + 1);
    float inv = 1.f / fmaxf((float)(end - beg), 1.f);
    float acc[8] = {};
    pull1_scaled(feat, csr, beg, end, team, c, inv, acc);
    shfl_reduce8(acc);
    if (team == 0) {
        uint4 sv = *(const uint4*)(selfX + (size_t)wg * HID + c * 8);
        acc_h8(acc, sv);
        float o[8];
#pragma unroll
        for (int i = 0; i < 8; ++i)
            o[i] = fmaxf(acc[i] + bias[c * 8 + i], 0.f);
        *(uint4*)(out + (size_t)wg * HID + c * 8) = pack_h8v(o);
    }
}

// layer-2 single pull -> fp16 mean buffer
__global__ void k_l2_warp(const __half* __restrict__ feat, const int* __restrict__ rowptr,
                          const int* __restrict__ csr, __half* __restrict__ out, int n) {
    int wg = (blockIdx.x * blockDim.x + threadIdx.x) >> 5;
    if (wg >= n) return;
    int lane = threadIdx.x & 31;
    int team = lane >> 3, c = lane & 7;
    int beg = __ldg(rowptr + wg), end = __ldg(rowptr + wg + 1);
    float inv = 1.f / fmaxf((float)(end - beg), 1.f);
    float acc[8] = {};
    pull1_scaled(feat, csr, beg, end, team, c, inv, acc);
    shfl_reduce8(acc);
    if (team == 0)
        *(uint4*)(out + (size_t)wg * HID + c * 8) = pack_h8v(acc);
}

// ---------------- fp16 HMMA GEMM: C[M,64](fp16) = A[M,128] @ B[128,64], batched ----------------
struct GemmBatch {
    const float* B[4];
    __half* C[4];
};

__global__ void gemm_f16_f128(const float* __restrict__ A, GemmBatch p, int M) {
    __shared__ uint32_t As[128 * 20];
    __shared__ uint32_t Bs[64 * 20];
    const float* __restrict__ Bp = p.B[blockIdx.y];
    __half* __restrict__ Cp = p.C[blockIdx.y];
    const int t = threadIdx.x;
    const int wid = t >> 5, lane = t & 31;
    const int g = lane >> 2, tg = lane & 3;
    const int rowBase = blockIdx.x * 128;
    const int wrow = wid * 16;

    float c[8][4] = {};

    for (int kb = 0; kb < 4; ++kb) {
#pragma unroll
        for (int j = 0; j < 4; ++j) {
            int idx = t + j * 256;
            int r = idx >> 3, q = idx & 7;
            int gr = rowBase + r;
            if (gr >= M) gr = M - 1;
            float4 av = *(const float4*)(A + (size_t)gr * FIN + kb * 32 + q * 4);
            As[r * 20 + q * 2 + 0] = packh2(av.x, av.y);
            As[r * 20 + q * 2 + 1] = packh2(av.z, av.w);
        }
#pragma unroll
        for (int j = 0; j < 4; ++j) {
            int idx = t + j * 256;
            int n = idx & 63, kh = idx >> 6;
            float v0 = Bp[(size_t)(kb * 32 + 2 * kh) * HID + n];
            float v1 = Bp[(size_t)(kb * 32 + 2 * kh + 1) * HID + n];
            Bs[n * 20 + kh] = packh2(v0, v1);
        }
        __syncthreads();
#pragma unroll
        for (int ks = 0; ks < 2; ++ks) {
            int kh0 = ks * 8;
            uint32_t a0 = As[(wrow + g) * 20 + kh0 + tg];
            uint32_t a1 = As[(wrow + g + 8) * 20 + kh0 + tg];
            uint32_t a2 = As[(wrow + g) * 20 + kh0 + tg + 4];
            uint32_t a3 = As[(wrow + g + 8) * 20 + kh0 + tg + 4];
#pragma unroll
            for (int nt = 0; nt < 8; ++nt) {
                int n = nt * 8 + g;
                uint32_t b0 = Bs[n * 20 + kh0 + tg];
                uint32_t b1 = Bs[n * 20 + kh0 + tg + 4];
                mma_f16(c[nt], a0, a1, a2, a3, b0, b1);
            }
        }
        __syncthreads();
    }

    int r0 = rowBase + wrow + g, r1 = r0 + 8;
#pragma unroll
    for (int nt = 0; nt < 8; ++nt) {
        int col = nt * 8 + tg * 2;
        if (r0 < M)
            *reinterpret_cast<__half2*>(Cp + (size_t)r0 * HID + col) = __floats2half2_rn(c[nt][0], c[nt][1]);
        if (r1 < M)
            *reinterpret_cast<__half2*>(Cp + (size_t)r1 * HID + col) = __floats2half2_rn(c[nt][2], c[nt][3]);
    }
}

// ---------------- fp16 HMMA output GEMM: fp16 A inputs, fp32 out ----------------
__global__ void gemm_out_f16(const __half* __restrict__ A0, const __half* __restrict__ A1,
                             const __half* __restrict__ A2, const __half* __restrict__ A3,
                             const float* __restrict__ B0, const float* __restrict__ B1,
                             const float* __restrict__ B2, const float* __restrict__ B3,
                             float* __restrict__ C, int M) {
    __shared__ uint32_t As[128 * 20];
    __shared__ uint32_t Bs[64 * 20];
    const int t = threadIdx.x;
    const int wid = t >> 5, lane = t & 31;
    const int g = lane >> 2, tg = lane & 3;
    const int rowBase = blockIdx.x * 128;
    const int colBase = blockIdx.y * 64;
    const int wrow = wid * 16;

    const __half* Aps[4] = {A0, A1, A2, A3};
    const float* Bps[4] = {B0, B1, B2, B3};

    float c[8][4] = {};

    for (int m = 0; m < 4; ++m) {
        const __half* __restrict__ Ap = Aps[m];
        const float* __restrict__ Bp = Bps[m];
        for (int kb = 0; kb < 2; ++kb) {
#pragma unroll
            for (int j = 0; j < 2; ++j) {
                int idx = t + j * 256;
                int r = idx >> 2, q = idx & 3;
                int gr = rowBase + r;
                if (gr >= M) gr = M - 1;
                uint4 hv = *(const uint4*)(Ap + (size_t)gr * HID + kb * 32 + q * 8);
                uint32_t* d = &As[r * 20 + q * 4];
                d[0] = hv.x; d[1] = hv.y; d[2] = hv.z; d[3] = hv.w;
            }
#pragma unroll
            for (int j = 0; j < 4; ++j) {
                int idx = t + j * 256;
                int n = idx & 63, kh = idx >> 6;
                int col = colBase + n;
                float v0 = 0.f, v1 = 0.f;
                if (col < OUTF) {
                    v0 = Bp[(size_t)(kb * 32 + 2 * kh) * OUTF + col];
                    v1 = Bp[(size_t)(kb * 32 + 2 * kh + 1) * OUTF + col];
                }
                Bs[n * 20 + kh] = packh2(v0, v1);
            }
            __syncthreads();
#pragma unroll
            for (int ks = 0; ks < 2; ++ks) {
                int kh0 = ks * 8;
                uint32_t a0 = As[(wrow + g) * 20 + kh0 + tg];
                uint32_t a1 = As[(wrow + g + 8) * 20 + kh0 + tg];
                uint32_t a2 = As[(wrow + g) * 20 + kh0 + tg + 4];
                uint32_t a3 = As[(wrow + g + 8) * 20 + kh0 + tg + 4];
#pragma unroll
                for (int nt = 0; nt < 8; ++nt) {
                    int n = nt * 8 + g;
                    uint32_t b0 = Bs[n * 20 + kh0 + tg];
                    uint32_t b1 = Bs[n * 20 + kh0 + tg + 4];
                    mma_f16(c[nt], a0, a1, a2, a3, b0, b1);
                }
            }
            __syncthreads();
        }
    }

    int r0 = rowBase + wrow + g, r1 = r0 + 8;
#pragma unroll
    for (int nt = 0; nt < 8; ++nt) {
        int col = colBase + nt * 8 + tg * 2;
        if (col < OUTF) {
            float bia = g_bsum2[col];
            if (r0 < M) C[(size_t)r0 * OUTF + col] = c[nt][0] + bia;
            if (r1 < M) C[(size_t)r1 * OUTF + col] = c[nt][2] + bia;
        }
        if (col + 1 < OUTF) {
            float bib = g_bsum2[col + 1];
            if (r0 < M) C[(size_t)r0 * OUTF + col + 1] = c[nt][1] + bib;
            if (r1 < M) C[(size_t)r1 * OUTF + col + 1] = c[nt][3] + bib;
        }
    }
}

// ---------------- host launcher ----------------
static inline void* sym(const void* s) {
    void* p = nullptr;
    cudaGetSymbolAddress(&p, s);
    return p;
}

extern "C" void kernel_launch(void* const* d_in, const int* in_sizes, int n_in,
                              void* d_out, int out_size) {
    static cudaStream_t s1 = nullptr, s2 = nullptr;
    static cudaEvent_t ev0 = nullptr, ev1 = nullptr, ev2 = nullptr, ev3 = nullptr, ev4 = nullptr;
    if (s1 == nullptr) {
        cudaStreamCreateWithFlags(&s1, cudaStreamNonBlocking);
        cudaStreamCreateWithFlags(&s2, cudaStreamNonBlocking);
        cudaEventCreateWithFlags(&ev0, cudaEventDisableTiming);
        cudaEventCreateWithFlags(&ev1, cudaEventDisableTiming);
        cudaEventCreateWithFlags(&ev2, cudaEventDisableTiming);
        cudaEventCreateWithFlags(&ev3, cudaEventDisableTiming);
        cudaEventCreateWithFlags(&ev4, cudaEventDisableTiming);
    }

    const float* x_paper  = (const float*)d_in[0];
    const float* x_author = (const float*)d_in[1];
    const float* x_field  = (const float*)d_in[2];
    const int* ei_wr = (const int*)d_in[3];
    const int* ei_rw = (const int*)d_in[4];
    const int* ei_ci = (const int*)d_in[5];
    const int* ei_ht = (const int*)d_in[6];
    const int* ei_rh = (const int*)d_in[7];
    const int nE_wr = in_sizes[3] / 2;
    const int nE_rw = in_sizes[4] / 2;
    const int nE_ci = in_sizes[5] / 2;
    const int nE_ht = in_sizes[6] / 2;
    const int nE_rh = in_sizes[7] / 2;

    const float* wl1_wr = (const float*)d_in[8];
    const float* wr1_wr = (const float*)d_in[9];
    const float* b1_wr  = (const float*)d_in[10];
    const float* wl1_rw = (const float*)d_in[11];
    const float* wr1_rw = (const float*)d_in[12];
    const float* b1_rw  = (const float*)d_in[13];
    const float* wl1_ci = (const float*)d_in[14];
    const float* wr1_ci = (const float*)d_in[15];
    const float* b1_ci  = (const float*)d_in[16];
    const float* wl1_ht = (const float*)d_in[17];
    const float* wr1_ht = (const float*)d_in[18];
    const float* b1_ht  = (const float*)d_in[19];
    const float* wl1_rh = (const float*)d_in[20];
    const float* wr1_rh = (const float*)d_in[21];
    const float* b1_rh  = (const float*)d_in[22];
    const float* wl2_wr = (const float*)d_in[23];
    const float* wr2_wr = (const float*)d_in[24];
    const float* b2_wr  = (const float*)d_in[25];
    const float* wl2_ci = (const float*)d_in[26];
    const float* wr2_ci = (const float*)d_in[27];
    const float* b2_ci  = (const float*)d_in[28];
    const float* wl2_rh = (const float*)d_in[29];
    const float* wr2_rh = (const float*)d_in[30];
    const float* b2_rh  = (const float*)d_in[31];

    float* out = (float*)d_out;

    __half* hs_wr = (__half*)sym(g_hs_wr);
    __half* hs_rw = (__half*)sym(g_hs_rw);
    __half* hs_ci = (__half*)sym(g_hs_ci);
    __half* hs_ht = (__half*)sym(g_hs_ht);
    __half* hs_rh = (__half*)sym(g_hs_rh);
    __half* selfP = (__half*)sym(g_selfP);
    __half* selfA = (__half*)sym(g_selfA);
    __half* selfF = (__half*)sym(g_selfF);
    __half* a1h = (__half*)sym(g_a1h);
    __half* f1h = (__half*)sym(g_f1h);
    __half* p1h = (__half*)sym(g_p1h);
    __half* m2_wr = (__half*)sym(g_m2_wr);
    __half* m2_ci = (__half*)sym(g_m2_ci);
    __half* m2_rh = (__half*)sym(g_m2_rh);
    int* cnt = (int*)sym(g_cnt);
    int* rp_wr = (int*)sym(g_rp_wr);
    int* rp_rw = (int*)sym(g_rp_rw);
    int* rp_ci = (int*)sym(g_rp_ci);
    int* rp_ht = (int*)sym(g_rp_ht);
    int* rp_rh = (int*)sym(g_rp_rh);
    int* csr_wr = (int*)sym(g_csr_wr);
    int* csr_rw = (int*)sym(g_csr_rw);
    int* csr_ci = (int*)sym(g_csr_ci);
    int* csr_ht = (int*)sym(g_csr_ht);
    int* csr_rh = (int*)sym(g_csr_rh);
    float* wsumP = (float*)sym(g_wsumP);
    float* w2sum = (float*)sym(g_w2sum);

    // ---- fork: s1 does weight prep + layer-1 GEMMs ----
    cudaEventRecord(ev0, 0);
    cudaStreamWaitEvent(s1, ev0, 0);

    prep_weights<<<(HID * OUTF + 255) / 256, 256, 0, s1>>>(
        wr1_wr, wr1_ci, wr1_rh, wr2_wr, wr2_ci, wr2_rh,
        b1_wr, b1_ci, b1_rh, b2_wr, b2_ci, b2_rh);

    const int gP = (NP + 127) / 128, gA = (NA + 127) / 128, gF = (NF + 127) / 128;
    {
        GemmBatch bp;
        bp.B[0] = wl1_rw; bp.C[0] = hs_rw;
        bp.B[1] = wl1_ci; bp.C[1] = hs_ci;
        bp.B[2] = wl1_ht; bp.C[2] = hs_ht;
        bp.B[3] = wsumP;  bp.C[3] = selfP;
        gemm_f16_f128<<<dim3(gP, 4), 256, 0, s1>>>(x_paper, bp, NP);
        GemmBatch ba;
        ba.B[0] = wl1_wr; ba.C[0] = hs_wr;
        ba.B[1] = wr1_rw; ba.C[1] = selfA;
        ba.B[2] = wl1_wr; ba.C[2] = hs_wr;
        ba.B[3] = wl1_wr; ba.C[3] = hs_wr;
        gemm_f16_f128<<<dim3(gA, 2), 256, 0, s1>>>(x_author, ba, NA);
        GemmBatch bf;
        bf.B[0] = wl1_rh; bf.C[0] = hs_rh;
        bf.B[1] = wr1_ht; bf.C[1] = selfF;
        bf.B[2] = wl1_rh; bf.C[2] = hs_rh;
        bf.B[3] = wl1_rh; bf.C[3] = hs_rh;
        gemm_f16_f128<<<dim3(gF, 2), 256, 0, s1>>>(x_field, bf, NF);
    }
    cudaEventRecord(ev1, s1);

    // ---- stream 0: CSR build ----
    cudaMemsetAsync(cnt, 0, sizeof(int) * CNT_TOT, 0);

    EJobs ep;
    ep.ei[0] = ei_wr; ep.E[0] = nE_wr;
    ep.ei[1] = ei_rw; ep.E[1] = nE_rw;
    ep.ei[2] = ei_ci; ep.E[2] = nE_ci;
    ep.ei[3] = ei_ht; ep.E[3] = nE_ht;
    ep.ei[4] = ei_rh; ep.E[4] = nE_rh;
    ep.bs[0] = 0;
    for (int i = 0; i < 5; ++i) ep.bs[i + 1] = ep.bs[i] + (ep.E[i] + 255) / 256;

    k_count_all<<<ep.bs[5], 256>>>(ep);
    k_blocksum_all<<<dim3((NP + 1023) / 1024, 5), 256>>>();
    k_scan_bsums_all<<<5, 256>>>();
    k_scan_write_all<<<dim3((NP + 1023) / 1024, 5), 256>>>();
    k_fill_all<<<ep.bs[5], 256>>>(ep);
    cudaEventRecord(ev2, 0);

    auto wg = [](int n) { return (n * 32 + 255) / 256; };

    // ---- stream 0 chain: paper layer-1 -> layer-2 ci pull ----
    cudaStreamWaitEvent(0, ev1, 0);      // needs hs_* from s1
    k_paper_warp<<<wg(NP), 256>>>();
    k_l2_warp<<<wg(NP), 256>>>(p1h, rp_ci, csr_ci, m2_ci, NP);

    // ---- s1 chain: author layer-1 -> layer-2 wr pull ----
    cudaStreamWaitEvent(s1, ev2, 0);     // needs CSR from stream 0
    k_af_warp<<<wg(NA), 256, 0, s1>>>(hs_rw, rp_rw, csr_rw, selfA, b1_rw, a1h, NA);
    k_l2_warp<<<wg(NP), 256, 0, s1>>>(a1h, rp_wr, csr_wr, m2_wr, NP);
    cudaEventRecord(ev3, s1);

    // ---- s2 chain: field layer-1 -> layer-2 rh pull ----
    cudaStreamWaitEvent(s2, ev1, 0);
    cudaStreamWaitEvent(s2, ev2, 0);
    k_af_warp<<<wg(NF), 256, 0, s2>>>(hs_ht, rp_ht, csr_ht, selfF, b1_ht, f1h, NF);
    k_l2_warp<<<wg(NP), 256, 0, s2>>>(f1h, rp_rh, csr_rh, m2_rh, NP);
    cudaEventRecord(ev4, s2);

    // ---- join + output GEMM ----
    cudaStreamWaitEvent(0, ev3, 0);
    cudaStreamWaitEvent(0, ev4, 0);
    dim3 g2(gP, (OUTF + 63) / 64);
    gemm_out_f16<<<g2, 256>>>(m2_wr, m2_ci, m2_rh, p1h,
                              wl2_wr, wl2_ci, wl2_rh, w2sum,
                              out, NP);
}